// round 6
// baseline (speedup 1.0000x reference)
#include <cuda_runtime.h>
#include <cuda_bf16.h>

#define BB   32
#define TT   96
#define HID  256
#define CE   400
#define VV   256
#define HH_  16
#define WW_  64
#define AA   256
#define HW   1024
#define NZ   8          // a-chunks
#define ACH  32         // a per chunk
#define GRID 512        // scan kernel grid (32 b x 2 strips x 8 zc)

// ---------------- device scratch ----------------
__device__ __align__(16) float g_x0[BB*TT*HID];
__device__ __align__(16) float g_x1[BB*TT*HID];
__device__ __align__(16) float g_wT1[3*256*512];
__device__ __align__(16) float g_wT2[3*256*512];
__device__ __align__(16) float g_wT3[3*256*512];
__device__ __align__(16) float g_WhT[HID*AA];
__device__ __align__(16) float g_fcWT[(HID+CE)*VV];
__device__ __align__(16) float2 g_Wc2[AA*26];      // dup-packed (w,w), 26th = pad 0
__device__ __align__(16) float g_EP[BB*AA*HW];     // (b, a, hw), includes b_enc
__device__ __align__(16) float g_QB[BB*TT*AA];     // q + b_h + b_cov
__device__ __align__(16) float g_cov[BB*HW];
__device__ __align__(16) float g_epart[NZ*BB*HW];  // partial e per a-chunk
__device__ __align__(16) float g_alpha[BB*TT*HW];  // all attention maps
__device__ __align__(16) float g_ctxall[BB*TT*CE];

// grid barrier state
__device__ unsigned g_bar_count = 0;
__device__ unsigned g_bar_gen   = 0;

__device__ __forceinline__ float sigmoid_fast(float x) {
    return __fdividef(1.f, 1.f + __expf(-x));
}

// ---- packed f32x2 helpers (sm_103a) ----
typedef unsigned long long u64;
__device__ __forceinline__ u64 pk2(float lo, float hi) {
    u64 d;
    asm("mov.b64 %0, {%1, %2};" : "=l"(d) : "r"(__float_as_uint(lo)), "r"(__float_as_uint(hi)));
    return d;
}
__device__ __forceinline__ void upk2(u64 v, float& lo, float& hi) {
    unsigned int a, b;
    asm("mov.b64 {%0, %1}, %2;" : "=r"(a), "=r"(b) : "l"(v));
    lo = __uint_as_float(a); hi = __uint_as_float(b);
}
__device__ __forceinline__ u64 ffma2(u64 a, u64 b, u64 c) {
    u64 d;
    asm("fma.rn.f32x2 %0, %1, %2, %3;" : "=l"(d) : "l"(a), "l"(b), "l"(c));
    return d;
}
__device__ __forceinline__ u64 fadd2(u64 a, u64 b) {
    u64 d;
    asm("add.rn.f32x2 %0, %1, %2;" : "=l"(d) : "l"(a), "l"(b));
    return d;
}
__device__ __forceinline__ float tanh_hw(float x) {
    float r; asm("tanh.approx.f32 %0, %1;" : "=f"(r) : "f"(x)); return r;
}

// generation grid barrier: all blocks co-resident (guaranteed by launch_bounds)
__device__ __forceinline__ void grid_barrier() {
    __threadfence();
    __syncthreads();
    if (threadIdx.x == 0) {
        unsigned gen = *((volatile unsigned*)&g_bar_gen);
        unsigned arrived = atomicAdd(&g_bar_count, 1u);
        if (arrived == GRID - 1) {
            g_bar_count = 0;
            __threadfence();
            *((volatile unsigned*)&g_bar_gen) = gen + 1;
        } else {
            while (*((volatile unsigned*)&g_bar_gen) == gen) __nanosleep(64);
        }
    }
    __syncthreads();
}

// ---------------- prep: embedding, weight transposes, zero cov ----------------
__global__ void __launch_bounds__(256) prep_kernel(const int* __restrict__ tgt,
                            const float* __restrict__ embed,
                            const float* __restrict__ w1,
                            const float* __restrict__ w2,
                            const float* __restrict__ w3,
                            const float* __restrict__ W_h,
                            const float* __restrict__ fc_W,
                            const float* __restrict__ W_cov) {
    int idx = blockIdx.x * 256 + threadIdx.x;
    if (idx < BB*TT*HID) {
        int bt = idx >> 8;
        g_x0[idx] = embed[tgt[bt]*HID + (idx & 255)];
    }
    if (idx < 512*256*3) {
        int o = idx / 768, rem = idx % 768, ic = rem / 3, k = rem % 3;
        int d = (k*256 + ic)*512 + o;
        g_wT1[d] = w1[idx];
        g_wT2[d] = w2[idx];
        g_wT3[d] = w3[idx];
    }
    if (idx < AA*HID) {
        int a = idx >> 8, h = idx & 255;
        g_WhT[h*AA + a] = W_h[idx];
    }
    if (idx < VV*(HID+CE)) {
        int v = idx / (HID+CE), j = idx % (HID+CE);
        g_fcWT[j*VV + v] = fc_W[idx];
    }
    if (idx < AA*26) {
        int a = idx / 26, k = idx % 26;
        float w = (k < 25) ? W_cov[a*25 + k] : 0.f;
        g_Wc2[idx] = make_float2(w, w);
    }
    if (idx < BB*HW) g_cov[idx] = 0.f;
}

// ---------------- causal GLU layer (32t x 64h tiles) ----------------
__global__ void __launch_bounds__(256) glu_kernel(int src_sel, int layer,
                                                  const float* __restrict__ bias) {
    const float* xin  = src_sel ? g_x1 : g_x0;
    float*       xout = src_sel ? g_x0 : g_x1;
    const float* wT = (layer == 0) ? g_wT1 : (layer == 1) ? g_wT2 : g_wT3;

    int b  = blockIdx.x / 3;
    int t0 = (blockIdx.x % 3) * 32;
    int h0 = blockIdx.y * 64;
    __shared__ float As[34][17];
    __shared__ float Wa[3][16][64];
    __shared__ float Wg[3][16][64];
    int tid = threadIdx.x;
    int tr = (tid & 15) * 2;
    int tc = (tid >> 4) * 4;
    float aa[2][4], gg[2][4];
#pragma unroll
    for (int r = 0; r < 2; r++)
#pragma unroll
        for (int c = 0; c < 4; c++) { aa[r][c] = 0.f; gg[r][c] = 0.f; }

    for (int ic0 = 0; ic0 < 256; ic0 += 16) {
        __syncthreads();
        for (int idx = tid; idx < 34*16; idx += 256) {
            int r = idx >> 4, c = idx & 15;
            int tg = t0 - 2 + r;
            As[r][c] = (tg >= 0) ? xin[(b*TT + tg)*HID + ic0 + c] : 0.f;
        }
        for (int idx = tid; idx < 3072; idx += 256) {
            int k = idx >> 10, rem = idx & 1023, i = rem >> 6, j = rem & 63;
            const float* base = wT + (k*256 + ic0 + i)*512 + h0 + j;
            Wa[k][i][j] = base[0];
            Wg[k][i][j] = base[256];
        }
        __syncthreads();
#pragma unroll
        for (int k = 0; k < 3; k++) {
#pragma unroll
            for (int i = 0; i < 16; i++) {
                float x0 = As[tr + k][i];
                float x1 = As[tr + 1 + k][i];
#pragma unroll
                for (int c = 0; c < 4; c++) {
                    float wa = Wa[k][i][tc + c];
                    float wg = Wg[k][i][tc + c];
                    aa[0][c] = fmaf(x0, wa, aa[0][c]);
                    aa[1][c] = fmaf(x1, wa, aa[1][c]);
                    gg[0][c] = fmaf(x0, wg, gg[0][c]);
                    gg[1][c] = fmaf(x1, wg, gg[1][c]);
                }
            }
        }
    }
#pragma unroll
    for (int r = 0; r < 2; r++)
#pragma unroll
        for (int c = 0; c < 4; c++) {
            int t = t0 + tr + r, h = h0 + tc + c;
            float av = aa[r][c] + bias[h];
            float gv = gg[r][c] + bias[256 + h];
            xout[(b*TT + t)*HID + h] = av * sigmoid_fast(gv);
        }
}

// ---------------- enc_proj (f32x2): EP[b,a,hw] = W_enc @ enc_feat + b_enc ----------------
__global__ void __launch_bounds__(256) encproj_kernel(const float* __restrict__ enc_feat,
                                                      const float* __restrict__ W_enc,
                                                      const float* __restrict__ b_enc) {
    int b = blockIdx.x, a0 = blockIdx.y*64, p0 = blockIdx.z*64;
    __shared__ float Ws[16][66];
    __shared__ __align__(16) float Fs[16][64];
    int tid = threadIdx.x;
    int ta = (tid & 15)*4, tp = (tid >> 4)*4;
    u64 acc2[4][2];
#pragma unroll
    for (int r = 0; r < 4; r++) { acc2[r][0] = 0ull; acc2[r][1] = 0ull; }

    for (int c0 = 0; c0 < CE; c0 += 16) {
        __syncthreads();
        for (int idx = tid; idx < 1024; idx += 256) {
            int j = idx & 15, i = idx >> 4;
            Ws[j][i] = W_enc[(a0 + i)*CE + c0 + j];
        }
        for (int idx = tid; idx < 1024; idx += 256) {
            int i = idx & 63, j = idx >> 6;
            Fs[j][i] = enc_feat[((size_t)b*CE + c0 + j)*HW + p0 + i];
        }
        __syncthreads();
#pragma unroll
        for (int j = 0; j < 16; j++) {
            const u64* fp = (const u64*)&Fs[j][tp];
            u64 f01 = fp[0], f23 = fp[1];
#pragma unroll
            for (int r = 0; r < 4; r++) {
                float av = Ws[j][ta + r];
                u64 ad = pk2(av, av);
                acc2[r][0] = ffma2(ad, f01, acc2[r][0]);
                acc2[r][1] = ffma2(ad, f23, acc2[r][1]);
            }
        }
    }
#pragma unroll
    for (int r = 0; r < 4; r++) {
        int a = a0 + ta + r;
        float be = b_enc[a];
        float v0, v1, v2, v3;
        upk2(acc2[r][0], v0, v1);
        upk2(acc2[r][1], v2, v3);
        *(float4*)&g_EP[((size_t)b*AA + a)*HW + p0 + tp] =
            make_float4(v0 + be, v1 + be, v2 + be, v3 + be);
    }
}

// ---------------- q precompute ----------------
__global__ void __launch_bounds__(256) qgemm_kernel(const float* __restrict__ b_h,
                                                    const float* __restrict__ b_cov) {
    int m0 = blockIdx.x * 64;
    int n0 = blockIdx.y * 64;
    __shared__ float Hs[16][66];
    __shared__ float Ws[16][64];
    int tid = threadIdx.x;
    int tm = (tid & 15)*4, tn = (tid >> 4)*4;
    float acc[4][4];
#pragma unroll
    for (int r = 0; r < 4; r++)
#pragma unroll
        for (int c = 0; c < 4; c++) acc[r][c] = 0.f;

    for (int k0 = 0; k0 < HID; k0 += 16) {
        __syncthreads();
        for (int idx = tid; idx < 1024; idx += 256) {
            int kk = idx & 15, m = idx >> 4;
            Hs[kk][m] = g_x1[(m0 + m)*HID + k0 + kk];
        }
        for (int idx = tid; idx < 1024; idx += 256) {
            int i = idx & 63, kk = idx >> 6;
            Ws[kk][i] = g_WhT[(k0 + kk)*AA + n0 + i];
        }
        __syncthreads();
#pragma unroll
        for (int kk = 0; kk < 16; kk++) {
            float hv[4], wv[4];
#pragma unroll
            for (int r = 0; r < 4; r++) hv[r] = Hs[kk][tm + r];
#pragma unroll
            for (int c = 0; c < 4; c++) wv[c] = Ws[kk][tn + c];
#pragma unroll
            for (int r = 0; r < 4; r++)
#pragma unroll
                for (int c = 0; c < 4; c++)
                    acc[r][c] = fmaf(hv[r], wv[c], acc[r][c]);
        }
    }
#pragma unroll
    for (int r = 0; r < 4; r++)
#pragma unroll
        for (int c = 0; c < 4; c++) {
            int n = n0 + tn + c;
            g_QB[(m0 + tm + r)*AA + n] = acc[r][c] + b_h[n] + b_cov[n];
        }
}

// ---------------- persistent fused scan: 96 steps, grid barriers ----------------
// 512 blocks x 128 threads: bid = zc*64 + b*2 + strip
__global__ void __launch_bounds__(128, 4) scan_kernel(const float* __restrict__ v_attn) {
    int bid   = blockIdx.x;
    int zc    = bid >> 6;         // 0..7
    int b     = (bid >> 1) & 31;  // 0..31
    int strip = bid & 1;          // 0..1
    int a0    = zc * ACH;
    __shared__ float sCov[12][68];
    __shared__ __align__(16) float2 sW[ACH*26];
    __shared__ float2 sQ2[ACH];
    __shared__ float2 sV2[ACH];
    __shared__ float redm[4];
    __shared__ float reds[4];
    int tid = threadIdx.x, lane = tid & 31, warp = tid >> 5;
    int r0 = strip * 8;
    const bool isP2 = (zc == 0 && strip == 0);

    for (int idx = tid; idx < ACH*26; idx += 128)
        sW[idx] = g_Wc2[a0*26 + idx];
    if (tid < ACH) {
        float v = v_attn[a0 + tid];
        sV2[tid] = make_float2(v, v);
    }

    int row = tid >> 4;
    int c0  = (tid & 15) * 4;
    int pix = (r0 + row)*WW_ + c0;
    const int STR = HW/4;     // ulonglong2 per a-row
    const ulonglong2* ep_base = (const ulonglong2*)(g_EP + ((size_t)b*AA + a0)*HW + pix);
    const ulonglong2* wb = (const ulonglong2*)sW;

    float4 covA = make_float4(0.f,0.f,0.f,0.f);
    float4 covB = make_float4(0.f,0.f,0.f,0.f);

    for (int t = 0; t < TT; t++) {
        // ---- per-step smem fill ----
        if (tid < ACH) {
            float q = g_QB[(b*TT + t)*AA + a0 + tid];
            sQ2[tid] = make_float2(q, q);
        }
        for (int idx = tid; idx < 12*68; idx += 128) {
            int rr = idx / 68, cc = idx % 68;
            int h = r0 - 2 + rr, w = cc - 2;
            sCov[rr][cc] = (h >= 0 && h < HH_ && (unsigned)w < WW_)
                           ? __ldcg(&g_cov[b*HW + h*WW_ + w]) : 0.f;
        }
        __syncthreads();

        // ---- energy: conv + tanh + sum over ACH a ----
        u64 pp[5][7];
#pragma unroll
        for (int dy = 0; dy < 5; dy++)
#pragma unroll
            for (int dx = 0; dx < 7; dx++)
                pp[dy][dx] = pk2(sCov[row + dy][c0 + dx], sCov[row + dy][c0 + dx + 1]);

        const ulonglong2* ep2 = ep_base;
        u64 e0 = 0ull, e1 = 0ull;
        ulonglong2 buf0 = ep2[0];
        ulonglong2 buf1 = ep2[STR];
        ep2 += 2*STR;

#pragma unroll 1
        for (int aa = 0; aa < ACH; aa++) {
            ulonglong2 cur = buf0;
            buf0 = buf1;
            if (aa < ACH - 2) { buf1 = *ep2; ep2 += STR; }

            const ulonglong2* w2 = wb + aa*13;
            u64 a00 = 0ull, a01 = 0ull, a10 = 0ull, a11 = 0ull;
#pragma unroll
            for (int j = 0; j < 13; j++) {
                ulonglong2 w = w2[j];
                {   const int k = 2*j;
                    if (k < 25) {
                        const int dy = k / 5, dx = k % 5;
                        a00 = ffma2(pp[dy][dx],     w.x, a00);
                        a10 = ffma2(pp[dy][dx + 2], w.x, a10);
                    }
                }
                {   const int k = 2*j + 1;
                    if (k < 25) {
                        const int dy = k / 5, dx = k % 5;
                        a01 = ffma2(pp[dy][dx],     w.y, a01);
                        a11 = ffma2(pp[dy][dx + 2], w.y, a11);
                    }
                }
            }
            u64 q2 = *(const u64*)&sQ2[aa];
            u64 g0 = fadd2(fadd2(a00, a01), fadd2(cur.x, q2));
            u64 g1 = fadd2(fadd2(a10, a11), fadd2(cur.y, q2));
            float s0, s1, s2, s3;
            upk2(g0, s0, s1); upk2(g1, s2, s3);
            float t0 = tanh_hw(s0), t1 = tanh_hw(s1);
            float t2 = tanh_hw(s2), t3 = tanh_hw(s3);
            u64 v2 = *(const u64*)&sV2[aa];
            e0 = ffma2(pk2(t0, t1), v2, e0);
            e1 = ffma2(pk2(t2, t3), v2, e1);
        }
        {
            float r0_, r1_, r2_, r3_;
            upk2(e0, r0_, r1_); upk2(e1, r2_, r3_);
            *(float4*)&g_epart[(zc*BB + b)*HW + pix] = make_float4(r0_, r1_, r2_, r3_);
        }

        grid_barrier();

        // ---- phase 2: 32 blocks do softmax + cov + alpha ----
        if (isP2) {
            float4 ev0 = make_float4(0.f,0.f,0.f,0.f);
            float4 ev1 = make_float4(0.f,0.f,0.f,0.f);
#pragma unroll
            for (int z = 0; z < NZ; z++) {
                const float4* p = (const float4*)(g_epart + ((size_t)z*BB + b)*HW) + tid*2;
                float4 q0 = __ldcg(p);
                float4 q1 = __ldcg(p + 1);
                ev0.x += q0.x; ev0.y += q0.y; ev0.z += q0.z; ev0.w += q0.w;
                ev1.x += q1.x; ev1.y += q1.y; ev1.z += q1.z; ev1.w += q1.w;
            }
            float m = fmaxf(fmaxf(fmaxf(ev0.x, ev0.y), fmaxf(ev0.z, ev0.w)),
                            fmaxf(fmaxf(ev1.x, ev1.y), fmaxf(ev1.z, ev1.w)));
#pragma unroll
            for (int o = 16; o; o >>= 1) m = fmaxf(m, __shfl_xor_sync(~0u, m, o));
            if (lane == 0) redm[warp] = m;
            __syncthreads();
            m = fmaxf(fmaxf(redm[0], redm[1]), fmaxf(redm[2], redm[3]));

            float4 x0, x1;
            x0.x = __expf(ev0.x - m); x0.y = __expf(ev0.y - m);
            x0.z = __expf(ev0.z - m); x0.w = __expf(ev0.w - m);
            x1.x = __expf(ev1.x - m); x1.y = __expf(ev1.y - m);
            x1.z = __expf(ev1.z - m); x1.w = __expf(ev1.w - m);
            float s = (x0.x + x0.y + x0.z + x0.w) + (x1.x + x1.y + x1.z + x1.w);
#pragma unroll
            for (int o = 16; o; o >>= 1) s += __shfl_xor_sync(~0u, s, o);
            if (lane == 0) reds[warp] = s;
            __syncthreads();
            s = (reds[0] + reds[1]) + (reds[2] + reds[3]);
            float inv = __fdividef(1.f, s);

            float4 al0, al1;
            al0.x = x0.x*inv; al0.y = x0.y*inv; al0.z = x0.z*inv; al0.w = x0.w*inv;
            al1.x = x1.x*inv; al1.y = x1.y*inv; al1.z = x1.z*inv; al1.w = x1.w*inv;

            float4* ap = (float4*)(g_alpha + ((size_t)b*TT + t)*HW) + tid*2;
            ap[0] = al0; ap[1] = al1;

            covA.x += al0.x; covA.y += al0.y; covA.z += al0.z; covA.w += al0.w;
            covB.x += al1.x; covB.y += al1.y; covB.z += al1.z; covB.w += al1.w;
            float4* cp = (float4*)(g_cov + b*HW) + tid*2;
            cp[0] = covA; cp[1] = covB;
        }

        grid_barrier();
    }
}

// ---------------- batched ctx GEMM (f32x2) ----------------
__global__ void __launch_bounds__(256) ctxgemm_kernel(const float* __restrict__ enc_feat) {
    int b  = blockIdx.x;
    int m0 = blockIdx.y * 64;   // t tile
    int n0 = blockIdx.z * 64;   // c tile
    __shared__ float As[16][66];
    __shared__ __align__(16) float Fs[16][64];
    int tid = threadIdx.x;
    int tm = (tid & 15)*4, tn = (tid >> 4)*4;
    u64 acc2[4][2];
#pragma unroll
    for (int r = 0; r < 4; r++) { acc2[r][0] = 0ull; acc2[r][1] = 0ull; }

    for (int k0 = 0; k0 < HW; k0 += 16) {
        __syncthreads();
        for (int idx = tid; idx < 1024; idx += 256) {
            int kk = idx & 15, mm = idx >> 4;
            int tt = m0 + mm;
            As[kk][mm] = (tt < TT) ? g_alpha[((size_t)b*TT + tt)*HW + k0 + kk] : 0.f;
        }
        for (int idx = tid; idx < 1024; idx += 256) {
            int i = idx & 63, kk = idx >> 6;
            int cc = n0 + i;
            Fs[kk][i] = (cc < CE) ? enc_feat[((size_t)b*CE + cc)*HW + k0 + kk] : 0.f;
        }
        __syncthreads();
#pragma unroll
        for (int kk = 0; kk < 16; kk++) {
            const u64* fp = (const u64*)&Fs[kk][tn];
            u64 f01 = fp[0], f23 = fp[1];
#pragma unroll
            for (int r = 0; r < 4; r++) {
                float av = As[kk][tm + r];
                u64 ad = pk2(av, av);
                acc2[r][0] = ffma2(ad, f01, acc2[r][0]);
                acc2[r][1] = ffma2(ad, f23, acc2[r][1]);
            }
        }
    }
#pragma unroll
    for (int r = 0; r < 4; r++) {
        int tt = m0 + tm + r;
        if (tt < TT) {
            float v0, v1, v2, v3;
            upk2(acc2[r][0], v0, v1);
            upk2(acc2[r][1], v2, v3);
            float vv[4] = {v0, v1, v2, v3};
#pragma unroll
            for (int c = 0; c < 4; c++) {
                int cc = n0 + tn + c;
                if (cc < CE) g_ctxall[((size_t)b*TT + tt)*CE + cc] = vv[c];
            }
        }
    }
}

// ---------------- final fc ----------------
__global__ void __launch_bounds__(256) fc_kernel(const float* __restrict__ fc_b,
                                                 float* __restrict__ out) {
    int m0 = blockIdx.x * 64;
    int n0 = blockIdx.y * 64;
    __shared__ float Is[16][66];
    __shared__ float Ws[16][64];
    int tid = threadIdx.x;
    int tm = (tid & 15)*4, tn = (tid >> 4)*4;
    float acc[4][4];
#pragma unroll
    for (int r = 0; r < 4; r++)
#pragma unroll
        for (int c = 0; c < 4; c++) acc[r][c] = 0.f;

    for (int k0 = 0; k0 < HID + CE; k0 += 16) {
        __syncthreads();
        const float* src; int stride, off;
        if (k0 < HID) { src = g_x1;     stride = HID; off = k0; }
        else          { src = g_ctxall; stride = CE;  off = k0 - HID; }
        for (int idx = tid; idx < 1024; idx += 256) {
            int kk = idx & 15, mm = idx >> 4;
            Is[kk][mm] = src[(m0 + mm)*stride + off + kk];
        }
        for (int idx = tid; idx < 1024; idx += 256) {
            int i = idx & 63, kk = idx >> 6;
            Ws[kk][i] = g_fcWT[(k0 + kk)*VV + n0 + i];
        }
        __syncthreads();
#pragma unroll
        for (int kk = 0; kk < 16; kk++) {
            float iv[4], wv[4];
#pragma unroll
            for (int r = 0; r < 4; r++) iv[r] = Is[kk][tm + r];
#pragma unroll
            for (int c = 0; c < 4; c++) wv[c] = Ws[kk][tn + c];
#pragma unroll
            for (int r = 0; r < 4; r++)
#pragma unroll
                for (int c = 0; c < 4; c++)
                    acc[r][c] = fmaf(iv[r], wv[c], acc[r][c]);
        }
    }
#pragma unroll
    for (int r = 0; r < 4; r++)
#pragma unroll
        for (int c = 0; c < 4; c++) {
            int n = n0 + tn + c;
            out[(m0 + tm + r)*VV + n] = acc[r][c] + fc_b[n];
        }
}

// ---------------- launch ----------------
extern "C" void kernel_launch(void* const* d_in, const int* in_sizes, int n_in,
                              void* d_out, int out_size) {
    const float* enc_feat = (const float*)d_in[0];
    const int*   tgt      = (const int*)  d_in[1];
    const float* embed    = (const float*)d_in[2];
    const float* w1       = (const float*)d_in[3];
    const float* b1       = (const float*)d_in[4];
    const float* w2       = (const float*)d_in[5];
    const float* b2       = (const float*)d_in[6];
    const float* w3       = (const float*)d_in[7];
    const float* b3       = (const float*)d_in[8];
    const float* W_enc    = (const float*)d_in[9];
    const float* b_enc    = (const float*)d_in[10];
    const float* W_h      = (const float*)d_in[11];
    const float* b_h      = (const float*)d_in[12];
    const float* W_cov    = (const float*)d_in[13];
    const float* b_cov    = (const float*)d_in[14];
    const float* v_attn   = (const float*)d_in[15];
    const float* fc_W     = (const float*)d_in[16];
    const float* fc_b     = (const float*)d_in[17];
    float* out = (float*)d_out;

    prep_kernel<<<3072, 256>>>(tgt, embed, w1, w2, w3, W_h, fc_W, W_cov);

    dim3 gglu(BB*3, 4);
    glu_kernel<<<gglu, 256>>>(0, 0, b1);   // g_x0 -> g_x1
    glu_kernel<<<gglu, 256>>>(1, 1, b2);   // g_x1 -> g_x0
    glu_kernel<<<gglu, 256>>>(0, 2, b3);   // g_x0 -> g_x1 (= hidd)

    encproj_kernel<<<dim3(BB, 4, 16), 256>>>(enc_feat, W_enc, b_enc);
    qgemm_kernel<<<dim3(48, 4), 256>>>(b_h, b_cov);

    scan_kernel<<<GRID, 128>>>(v_attn);

    ctxgemm_kernel<<<dim3(BB, 2, 7), 256>>>(enc_feat);
    fc_kernel<<<dim3(48, 4), 256>>>(fc_b, out);
}

// round 7
// speedup vs baseline: 1.1613x; 1.1613x over previous
#include <cuda_runtime.h>
#include <cuda_bf16.h>

#define BB   32
#define TT   96
#define HID  256
#define CE   400
#define VV   256
#define HH_  16
#define WW_  64
#define AA   256
#define HW   1024
#define NZ   8          // a-chunks
#define ACH  32         // a per chunk
#define GRID 512        // 32 b x 8 zc x 2 strips
#define NBLK_B 16       // blocks per batch

// ---------------- device scratch ----------------
__device__ __align__(16) float g_x0[BB*TT*HID];
__device__ __align__(16) float g_x1[BB*TT*HID];
__device__ __align__(16) float g_wT1[3*256*512];
__device__ __align__(16) float g_wT2[3*256*512];
__device__ __align__(16) float g_wT3[3*256*512];
__device__ __align__(16) float g_WhT[HID*AA];
__device__ __align__(16) float g_fcWT[(HID+CE)*VV];
__device__ __align__(16) float2 g_Wc2[AA*26];        // dup-packed (w,w)
__device__ __align__(16) uint2 g_EPh[BB*NZ*2*4096];  // bf16 EP, blocked [slab][aa*128+t]
__device__ __align__(16) float g_QB[BB*TT*AA];       // q + b_h + b_cov
__device__ __align__(16) float g_epart[2*NZ*BB*HW];  // double-buffered partial e
__device__ __align__(16) float g_alpha[BB*TT*HW];
__device__ __align__(16) float g_ctxall[BB*TT*CE];

// per-batch barrier state (128B padded)
__device__ unsigned g_barC[BB*32];
__device__ unsigned g_barG[BB*32];

__device__ __forceinline__ float sigmoid_fast(float x) {
    return __fdividef(1.f, 1.f + __expf(-x));
}

// ---- packed f32x2 helpers (sm_103a) ----
typedef unsigned long long u64;
__device__ __forceinline__ u64 pk2(float lo, float hi) {
    u64 d;
    asm("mov.b64 %0, {%1, %2};" : "=l"(d) : "r"(__float_as_uint(lo)), "r"(__float_as_uint(hi)));
    return d;
}
__device__ __forceinline__ void upk2(u64 v, float& lo, float& hi) {
    unsigned int a, b;
    asm("mov.b64 {%0, %1}, %2;" : "=r"(a), "=r"(b) : "l"(v));
    lo = __uint_as_float(a); hi = __uint_as_float(b);
}
__device__ __forceinline__ u64 ffma2(u64 a, u64 b, u64 c) {
    u64 d;
    asm("fma.rn.f32x2 %0, %1, %2, %3;" : "=l"(d) : "l"(a), "l"(b), "l"(c));
    return d;
}
__device__ __forceinline__ u64 fadd2(u64 a, u64 b) {
    u64 d;
    asm("add.rn.f32x2 %0, %1, %2;" : "=l"(d) : "l"(a), "l"(b));
    return d;
}
__device__ __forceinline__ float tanh_hw(float x) {
    float r; asm("tanh.approx.f32 %0, %1;" : "=f"(r) : "f"(x)); return r;
}
// bf16x2 word -> f32x2 (low half -> lane0)
__device__ __forceinline__ u64 bf2f2(unsigned u) {
    return pk2(__uint_as_float(u << 16), __uint_as_float(u & 0xFFFF0000u));
}
__device__ __forceinline__ unsigned pack_bf16x2(float x, float y) {
    return ((unsigned)__bfloat16_as_ushort(__float2bfloat16_rn(y)) << 16)
         |  (unsigned)__bfloat16_as_ushort(__float2bfloat16_rn(x));
}

// ---------------- prep ----------------
__global__ void __launch_bounds__(256) prep_kernel(const int* __restrict__ tgt,
                            const float* __restrict__ embed,
                            const float* __restrict__ w1,
                            const float* __restrict__ w2,
                            const float* __restrict__ w3,
                            const float* __restrict__ W_h,
                            const float* __restrict__ fc_W,
                            const float* __restrict__ W_cov) {
    int idx = blockIdx.x * 256 + threadIdx.x;
    if (idx < BB*TT*HID) {
        int bt = idx >> 8;
        g_x0[idx] = embed[tgt[bt]*HID + (idx & 255)];
    }
    if (idx < 512*256*3) {
        int o = idx / 768, rem = idx % 768, ic = rem / 3, k = rem % 3;
        int d = (k*256 + ic)*512 + o;
        g_wT1[d] = w1[idx];
        g_wT2[d] = w2[idx];
        g_wT3[d] = w3[idx];
    }
    if (idx < AA*HID) {
        int a = idx >> 8, h = idx & 255;
        g_WhT[h*AA + a] = W_h[idx];
    }
    if (idx < VV*(HID+CE)) {
        int v = idx / (HID+CE), j = idx % (HID+CE);
        g_fcWT[j*VV + v] = fc_W[idx];
    }
    if (idx < AA*26) {
        int a = idx / 26, k = idx % 26;
        float w = (k < 25) ? W_cov[a*25 + k] : 0.f;
        g_Wc2[idx] = make_float2(w, w);
    }
}

// ---------------- causal GLU layer (32t x 64h tiles) ----------------
__global__ void __launch_bounds__(256) glu_kernel(int src_sel, int layer,
                                                  const float* __restrict__ bias) {
    const float* xin  = src_sel ? g_x1 : g_x0;
    float*       xout = src_sel ? g_x0 : g_x1;
    const float* wT = (layer == 0) ? g_wT1 : (layer == 1) ? g_wT2 : g_wT3;

    int b  = blockIdx.x / 3;
    int t0 = (blockIdx.x % 3) * 32;
    int h0 = blockIdx.y * 64;
    __shared__ float As[34][17];
    __shared__ float Wa[3][16][64];
    __shared__ float Wg[3][16][64];
    int tid = threadIdx.x;
    int tr = (tid & 15) * 2;
    int tc = (tid >> 4) * 4;
    float aa[2][4], gg[2][4];
#pragma unroll
    for (int r = 0; r < 2; r++)
#pragma unroll
        for (int c = 0; c < 4; c++) { aa[r][c] = 0.f; gg[r][c] = 0.f; }

    for (int ic0 = 0; ic0 < 256; ic0 += 16) {
        __syncthreads();
        for (int idx = tid; idx < 34*16; idx += 256) {
            int r = idx >> 4, c = idx & 15;
            int tg = t0 - 2 + r;
            As[r][c] = (tg >= 0) ? xin[(b*TT + tg)*HID + ic0 + c] : 0.f;
        }
        for (int idx = tid; idx < 3072; idx += 256) {
            int k = idx >> 10, rem = idx & 1023, i = rem >> 6, j = rem & 63;
            const float* base = wT + (k*256 + ic0 + i)*512 + h0 + j;
            Wa[k][i][j] = base[0];
            Wg[k][i][j] = base[256];
        }
        __syncthreads();
#pragma unroll
        for (int k = 0; k < 3; k++) {
#pragma unroll
            for (int i = 0; i < 16; i++) {
                float x0 = As[tr + k][i];
                float x1 = As[tr + 1 + k][i];
#pragma unroll
                for (int c = 0; c < 4; c++) {
                    float wa = Wa[k][i][tc + c];
                    float wg = Wg[k][i][tc + c];
                    aa[0][c] = fmaf(x0, wa, aa[0][c]);
                    aa[1][c] = fmaf(x1, wa, aa[1][c]);
                    gg[0][c] = fmaf(x0, wg, gg[0][c]);
                    gg[1][c] = fmaf(x1, wg, gg[1][c]);
                }
            }
        }
    }
#pragma unroll
    for (int r = 0; r < 2; r++)
#pragma unroll
        for (int c = 0; c < 4; c++) {
            int t = t0 + tr + r, h = h0 + tc + c;
            float av = aa[r][c] + bias[h];
            float gv = gg[r][c] + bias[256 + h];
            xout[(b*TT + t)*HID + h] = av * sigmoid_fast(gv);
        }
}

// ---------------- enc_proj (f32x2) -> bf16 blocked layout ----------------
__global__ void __launch_bounds__(256) encproj_kernel(const float* __restrict__ enc_feat,
                                                      const float* __restrict__ W_enc,
                                                      const float* __restrict__ b_enc) {
    int b = blockIdx.x, a0 = blockIdx.y*64, p0 = blockIdx.z*64;
    __shared__ float Ws[16][66];
    __shared__ __align__(16) float Fs[16][64];
    int tid = threadIdx.x;
    int ta = (tid & 15)*4, tp = (tid >> 4)*4;
    u64 acc2[4][2];
#pragma unroll
    for (int r = 0; r < 4; r++) { acc2[r][0] = 0ull; acc2[r][1] = 0ull; }

    for (int c0 = 0; c0 < CE; c0 += 16) {
        __syncthreads();
        for (int idx = tid; idx < 1024; idx += 256) {
            int j = idx & 15, i = idx >> 4;
            Ws[j][i] = W_enc[(a0 + i)*CE + c0 + j];
        }
        for (int idx = tid; idx < 1024; idx += 256) {
            int i = idx & 63, j = idx >> 6;
            Fs[j][i] = enc_feat[((size_t)b*CE + c0 + j)*HW + p0 + i];
        }
        __syncthreads();
#pragma unroll
        for (int j = 0; j < 16; j++) {
            const u64* fp = (const u64*)&Fs[j][tp];
            u64 f01 = fp[0], f23 = fp[1];
#pragma unroll
            for (int r = 0; r < 4; r++) {
                float av = Ws[j][ta + r];
                u64 ad = pk2(av, av);
                acc2[r][0] = ffma2(ad, f01, acc2[r][0]);
                acc2[r][1] = ffma2(ad, f23, acc2[r][1]);
            }
        }
    }
    int p = p0 + tp;
    int slab_p = p >> 9;               // strip
    int within = p & 511;
    int row = within >> 6, cc = within & 63;
    int ts = row*16 + (cc >> 2);
#pragma unroll
    for (int r = 0; r < 4; r++) {
        int a = a0 + ta + r;
        float be = b_enc[a];
        float v0, v1, v2, v3;
        upk2(acc2[r][0], v0, v1);
        upk2(acc2[r][1], v2, v3);
        int slab = (b*NZ + (a >> 5))*2 + slab_p;
        uint2 u;
        u.x = pack_bf16x2(v0 + be, v1 + be);
        u.y = pack_bf16x2(v2 + be, v3 + be);
        g_EPh[slab*4096 + ((a & 31)*128 + ts)] = u;
    }
}

// ---------------- q precompute ----------------
__global__ void __launch_bounds__(256) qgemm_kernel(const float* __restrict__ b_h,
                                                    const float* __restrict__ b_cov) {
    int m0 = blockIdx.x * 64;
    int n0 = blockIdx.y * 64;
    __shared__ float Hs[16][66];
    __shared__ float Ws[16][64];
    int tid = threadIdx.x;
    int tm = (tid & 15)*4, tn = (tid >> 4)*4;
    float acc[4][4];
#pragma unroll
    for (int r = 0; r < 4; r++)
#pragma unroll
        for (int c = 0; c < 4; c++) acc[r][c] = 0.f;

    for (int k0 = 0; k0 < HID; k0 += 16) {
        __syncthreads();
        for (int idx = tid; idx < 1024; idx += 256) {
            int kk = idx & 15, m = idx >> 4;
            Hs[kk][m] = g_x1[(m0 + m)*HID + k0 + kk];
        }
        for (int idx = tid; idx < 1024; idx += 256) {
            int i = idx & 63, kk = idx >> 6;
            Ws[kk][i] = g_WhT[(k0 + kk)*AA + n0 + i];
        }
        __syncthreads();
#pragma unroll
        for (int kk = 0; kk < 16; kk++) {
            float hv[4], wv[4];
#pragma unroll
            for (int r = 0; r < 4; r++) hv[r] = Hs[kk][tm + r];
#pragma unroll
            for (int c = 0; c < 4; c++) wv[c] = Ws[kk][tn + c];
#pragma unroll
            for (int r = 0; r < 4; r++)
#pragma unroll
                for (int c = 0; c < 4; c++)
                    acc[r][c] = fmaf(hv[r], wv[c], acc[r][c]);
        }
    }
#pragma unroll
    for (int r = 0; r < 4; r++)
#pragma unroll
        for (int c = 0; c < 4; c++) {
            int n = n0 + tn + c;
            g_QB[(m0 + tm + r)*AA + n] = acc[r][c] + b_h[n] + b_cov[n];
        }
}

// ---------------- persistent scan: smem EP, per-batch barrier, smem cov ----------------
// bid = b*16 + zc*2 + strip  (batch-contiguous for residency robustness)
__global__ void __launch_bounds__(128, 4) scan_kernel(const float* __restrict__ v_attn) {
    int bid   = blockIdx.x;
    int b     = bid >> 4;
    int zc    = (bid >> 1) & 7;
    int strip = bid & 1;
    int a0    = zc * ACH;
    int r0    = strip * 8;

    __shared__ __align__(16) uint2  sEP[ACH*128];    // 32KB bf16 EP slab
    __shared__ float  sCov[12][68];                  // persistent cov halo patch
    __shared__ __align__(16) float2 sW[ACH*26];
    __shared__ float  sE[HW];                        // exp(e - m) full image
    __shared__ float2 sQ2[ACH];
    __shared__ float2 sV2[ACH];
    __shared__ float  redm[4], reds[4];

    int tid = threadIdx.x, lane = tid & 31, warp = tid >> 5;

    // one-time fills
    {
        const uint2* src = g_EPh + ((b*NZ + zc)*2 + strip)*4096;
        for (int i = tid; i < ACH*128; i += 128) sEP[i] = src[i];
    }
    for (int i = tid; i < ACH*26; i += 128) sW[i] = g_Wc2[a0*26 + i];
    if (tid < ACH) { float v = v_attn[a0 + tid]; sV2[tid] = make_float2(v, v); }
    for (int i = tid; i < 12*68; i += 128) ((float*)sCov)[i] = 0.f;

    int row = tid >> 4;
    int c0  = (tid & 15) * 4;
    int pix = (r0 + row)*WW_ + c0;
    const ulonglong2* wb = (const ulonglong2*)sW;
    const u64* q2p = (const u64*)sQ2;

    for (int t = 0; t < TT; t++) {
        int ping = t & 1;
        if (tid < ACH) {
            float q = g_QB[(b*TT + t)*AA + a0 + tid];
            sQ2[tid] = make_float2(q, q);
        }
        __syncthreads();

        // ---- energy ----
        u64 pp[5][7];
#pragma unroll
        for (int dy = 0; dy < 5; dy++)
#pragma unroll
            for (int dx = 0; dx < 7; dx++)
                pp[dy][dx] = pk2(sCov[row + dy][c0 + dx], sCov[row + dy][c0 + dx + 1]);

        u64 e0 = 0ull, e1 = 0ull;
#pragma unroll 1
        for (int aa = 0; aa < ACH; aa++) {
            uint2 epw = sEP[aa*128 + tid];
            const ulonglong2* w2 = wb + aa*13;
            u64 a00 = 0ull, a01 = 0ull, a10 = 0ull, a11 = 0ull;
#pragma unroll
            for (int j = 0; j < 13; j++) {
                ulonglong2 w = w2[j];
                {   const int k = 2*j;
                    if (k < 25) {
                        const int dy = k / 5, dx = k % 5;
                        a00 = ffma2(pp[dy][dx],     w.x, a00);
                        a10 = ffma2(pp[dy][dx + 2], w.x, a10);
                    }
                }
                {   const int k = 2*j + 1;
                    if (k < 25) {
                        const int dy = k / 5, dx = k % 5;
                        a01 = ffma2(pp[dy][dx],     w.y, a01);
                        a11 = ffma2(pp[dy][dx + 2], w.y, a11);
                    }
                }
            }
            u64 q2 = q2p[aa];
            u64 g0 = fadd2(fadd2(a00, a01), fadd2(bf2f2(epw.x), q2));
            u64 g1 = fadd2(fadd2(a10, a11), fadd2(bf2f2(epw.y), q2));
            float s0, s1, s2, s3;
            upk2(g0, s0, s1); upk2(g1, s2, s3);
            u64 v2 = *((const u64*)sV2 + aa);
            e0 = ffma2(pk2(tanh_hw(s0), tanh_hw(s1)), v2, e0);
            e1 = ffma2(pk2(tanh_hw(s2), tanh_hw(s3)), v2, e1);
        }
        {
            float r0_, r1_, r2_, r3_;
            upk2(e0, r0_, r1_); upk2(e1, r2_, r3_);
            *(float4*)&g_epart[(size_t)ping*(NZ*BB*HW) + (zc*BB + b)*HW + pix] =
                make_float4(r0_, r1_, r2_, r3_);
        }

        // ---- per-batch barrier (16 arrivals) ----
        __threadfence();
        __syncthreads();
        if (tid == 0) {
            volatile unsigned* gp = &g_barG[b*32];
            unsigned gen = *gp;
            unsigned arrived = atomicAdd(&g_barC[b*32], 1u);
            if (arrived == NBLK_B - 1) {
                g_barC[b*32] = 0;
                __threadfence();
                *gp = gen + 1;
            } else {
                int spins = 0;
                while (*gp == gen) { __nanosleep(64); if (++spins > (1 << 23)) break; }
            }
            __threadfence();
        }
        __syncthreads();

        // ---- phase2 (redundant per block): softmax + cov halo + alpha ----
        float e8[8];
        {
            float4 s0v = make_float4(0.f,0.f,0.f,0.f);
            float4 s1v = make_float4(0.f,0.f,0.f,0.f);
            const float* base = g_epart + (size_t)ping*(NZ*BB*HW) + b*HW + tid*8;
#pragma unroll
            for (int z = 0; z < NZ; z++) {
                const float4* p4 = (const float4*)(base + (size_t)z*BB*HW);
                float4 q0 = __ldcg(p4);
                float4 q1 = __ldcg(p4 + 1);
                s0v.x += q0.x; s0v.y += q0.y; s0v.z += q0.z; s0v.w += q0.w;
                s1v.x += q1.x; s1v.y += q1.y; s1v.z += q1.z; s1v.w += q1.w;
            }
            e8[0]=s0v.x; e8[1]=s0v.y; e8[2]=s0v.z; e8[3]=s0v.w;
            e8[4]=s1v.x; e8[5]=s1v.y; e8[6]=s1v.z; e8[7]=s1v.w;
        }
        float m = e8[0];
#pragma unroll
        for (int j = 1; j < 8; j++) m = fmaxf(m, e8[j]);
#pragma unroll
        for (int o = 16; o; o >>= 1) m = fmaxf(m, __shfl_xor_sync(~0u, m, o));
        if (lane == 0) redm[warp] = m;
        __syncthreads();
        m = fmaxf(fmaxf(redm[0], redm[1]), fmaxf(redm[2], redm[3]));

        float ex8[8], sl = 0.f;
#pragma unroll
        for (int j = 0; j < 8; j++) { ex8[j] = __expf(e8[j] - m); sl += ex8[j]; }
        ((float4*)sE)[tid*2]     = make_float4(ex8[0], ex8[1], ex8[2], ex8[3]);
        ((float4*)sE)[tid*2 + 1] = make_float4(ex8[4], ex8[5], ex8[6], ex8[7]);
#pragma unroll
        for (int o = 16; o; o >>= 1) sl += __shfl_xor_sync(~0u, sl, o);
        if (lane == 0) reds[warp] = sl;
        __syncthreads();
        float s = (reds[0] + reds[1]) + (reds[2] + reds[3]);
        float inv = __fdividef(1.f, s);

        // cov halo update (single writer per element)
        for (int h = tid; h < 12*64; h += 128) {
            int hr = h >> 6, cc = h & 63;
            int imrow = r0 - 2 + hr;
            if ((unsigned)imrow < HH_)
                sCov[hr][cc + 2] += sE[imrow*WW_ + cc] * inv;
        }
        // one block per batch stores full alpha image for ctx GEMM
        if (zc == 0 && strip == 0) {
            float4* ap = (float4*)(g_alpha + ((size_t)b*TT + t)*HW) + tid*2;
            ap[0] = make_float4(ex8[0]*inv, ex8[1]*inv, ex8[2]*inv, ex8[3]*inv);
            ap[1] = make_float4(ex8[4]*inv, ex8[5]*inv, ex8[6]*inv, ex8[7]*inv);
        }
        __syncthreads();
    }
}

// ---------------- batched ctx GEMM (f32x2) ----------------
__global__ void __launch_bounds__(256) ctxgemm_kernel(const float* __restrict__ enc_feat) {
    int b  = blockIdx.x;
    int m0 = blockIdx.y * 64;
    int n0 = blockIdx.z * 64;
    __shared__ float As[16][66];
    __shared__ __align__(16) float Fs[16][64];
    int tid = threadIdx.x;
    int tm = (tid & 15)*4, tn = (tid >> 4)*4;
    u64 acc2[4][2];
#pragma unroll
    for (int r = 0; r < 4; r++) { acc2[r][0] = 0ull; acc2[r][1] = 0ull; }

    for (int k0 = 0; k0 < HW; k0 += 16) {
        __syncthreads();
        for (int idx = tid; idx < 1024; idx += 256) {
            int kk = idx & 15, mm = idx >> 4;
            int tt = m0 + mm;
            As[kk][mm] = (tt < TT) ? g_alpha[((size_t)b*TT + tt)*HW + k0 + kk] : 0.f;
        }
        for (int idx = tid; idx < 1024; idx += 256) {
            int i = idx & 63, kk = idx >> 6;
            int cc = n0 + i;
            Fs[kk][i] = (cc < CE) ? enc_feat[((size_t)b*CE + cc)*HW + k0 + kk] : 0.f;
        }
        __syncthreads();
#pragma unroll
        for (int kk = 0; kk < 16; kk++) {
            const u64* fp = (const u64*)&Fs[kk][tn];
            u64 f01 = fp[0], f23 = fp[1];
#pragma unroll
            for (int r = 0; r < 4; r++) {
                float av = As[kk][tm + r];
                u64 ad = pk2(av, av);
                acc2[r][0] = ffma2(ad, f01, acc2[r][0]);
                acc2[r][1] = ffma2(ad, f23, acc2[r][1]);
            }
        }
    }
#pragma unroll
    for (int r = 0; r < 4; r++) {
        int tt = m0 + tm + r;
        if (tt < TT) {
            float v0, v1, v2, v3;
            upk2(acc2[r][0], v0, v1);
            upk2(acc2[r][1], v2, v3);
            float vv[4] = {v0, v1, v2, v3};
#pragma unroll
            for (int c = 0; c < 4; c++) {
                int cc = n0 + tn + c;
                if (cc < CE) g_ctxall[((size_t)b*TT + tt)*CE + cc] = vv[c];
            }
        }
    }
}

// ---------------- final fc ----------------
__global__ void __launch_bounds__(256) fc_kernel(const float* __restrict__ fc_b,
                                                 float* __restrict__ out) {
    int m0 = blockIdx.x * 64;
    int n0 = blockIdx.y * 64;
    __shared__ float Is[16][66];
    __shared__ float Ws[16][64];
    int tid = threadIdx.x;
    int tm = (tid & 15)*4, tn = (tid >> 4)*4;
    float acc[4][4];
#pragma unroll
    for (int r = 0; r < 4; r++)
#pragma unroll
        for (int c = 0; c < 4; c++) acc[r][c] = 0.f;

    for (int k0 = 0; k0 < HID + CE; k0 += 16) {
        __syncthreads();
        const float* src; int stride, off;
        if (k0 < HID) { src = g_x1;     stride = HID; off = k0; }
        else          { src = g_ctxall; stride = CE;  off = k0 - HID; }
        for (int idx = tid; idx < 1024; idx += 256) {
            int kk = idx & 15, mm = idx >> 4;
            Is[kk][mm] = src[(m0 + mm)*stride + off + kk];
        }
        for (int idx = tid; idx < 1024; idx += 256) {
            int i = idx & 63, kk = idx >> 6;
            Ws[kk][i] = g_fcWT[(k0 + kk)*VV + n0 + i];
        }
        __syncthreads();
#pragma unroll
        for (int kk = 0; kk < 16; kk++) {
            float iv[4], wv[4];
#pragma unroll
            for (int r = 0; r < 4; r++) iv[r] = Is[kk][tm + r];
#pragma unroll
            for (int c = 0; c < 4; c++) wv[c] = Ws[kk][tn + c];
#pragma unroll
            for (int r = 0; r < 4; r++)
#pragma unroll
                for (int c = 0; c < 4; c++)
                    acc[r][c] = fmaf(iv[r], wv[c], acc[r][c]);
        }
    }
#pragma unroll
    for (int r = 0; r < 4; r++)
#pragma unroll
        for (int c = 0; c < 4; c++) {
            int n = n0 + tn + c;
            out[(m0 + tm + r)*VV + n] = acc[r][c] + fc_b[n];
        }
}

// ---------------- launch ----------------
extern "C" void kernel_launch(void* const* d_in, const int* in_sizes, int n_in,
                              void* d_out, int out_size) {
    const float* enc_feat = (const float*)d_in[0];
    const int*   tgt      = (const int*)  d_in[1];
    const float* embed    = (const float*)d_in[2];
    const float* w1       = (const float*)d_in[3];
    const float* b1       = (const float*)d_in[4];
    const float* w2       = (const float*)d_in[5];
    const float* b2       = (const float*)d_in[6];
    const float* w3       = (const float*)d_in[7];
    const float* b3       = (const float*)d_in[8];
    const float* W_enc    = (const float*)d_in[9];
    const float* b_enc    = (const float*)d_in[10];
    const float* W_h      = (const float*)d_in[11];
    const float* b_h      = (const float*)d_in[12];
    const float* W_cov    = (const float*)d_in[13];
    const float* b_cov    = (const float*)d_in[14];
    const float* v_attn   = (const float*)d_in[15];
    const float* fc_W     = (const float*)d_in[16];
    const float* fc_b     = (const float*)d_in[17];
    float* out = (float*)d_out;

    prep_kernel<<<3072, 256>>>(tgt, embed, w1, w2, w3, W_h, fc_W, W_cov);

    dim3 gglu(BB*3, 4);
    glu_kernel<<<gglu, 256>>>(0, 0, b1);   // g_x0 -> g_x1
    glu_kernel<<<gglu, 256>>>(1, 1, b2);   // g_x1 -> g_x0
    glu_kernel<<<gglu, 256>>>(0, 2, b3);   // g_x0 -> g_x1 (= hidd)

    encproj_kernel<<<dim3(BB, 4, 16), 256>>>(enc_feat, W_enc, b_enc);
    qgemm_kernel<<<dim3(48, 4), 256>>>(b_h, b_cov);

    scan_kernel<<<GRID, 128>>>(v_attn);

    ctxgemm_kernel<<<dim3(BB, 2, 7), 256>>>(enc_feat);
    fc_kernel<<<dim3(48, 4), 256>>>(fc_b, out);
}

// round 8
// speedup vs baseline: 1.1953x; 1.0293x over previous
#include <cuda_runtime.h>
#include <cuda_bf16.h>

#define BB   32
#define TT   96
#define HID  256
#define CE   400
#define VV   256
#define HH_  16
#define WW_  64
#define AA   256
#define HW   1024
#define NZ   8          // a-chunks
#define ACH  32         // a per chunk
#define GRID 512        // 32 b x 8 zc x 2 strips
#define NBLK_B 16       // blocks per batch

// ---------------- device scratch ----------------
__device__ __align__(16) float g_x0[BB*TT*HID];
__device__ __align__(16) float g_x1[BB*TT*HID];
__device__ __align__(16) float g_wT1[3*256*512];
__device__ __align__(16) float g_wT2[3*256*512];
__device__ __align__(16) float g_wT3[3*256*512];
__device__ __align__(16) float g_WhT[HID*AA];
__device__ __align__(16) float g_fcWT[(HID+CE)*VV];
__device__ __align__(16) float2 g_Wc2[AA*26];        // dup-packed (w,w)
__device__ __align__(16) uint2 g_EPh[BB*NZ*2*4096];  // bf16 EP, blocked [slab][aa*128+t]
__device__ __align__(16) float g_QB[BB*TT*AA];       // q + b_h + b_cov
__device__ __align__(16) float g_epart[2*NZ*BB*HW];  // double-buffered partial e
__device__ __align__(16) float g_alpha[BB*TT*HW];
__device__ __align__(16) float g_ctxall[BB*TT*CE];

// per-batch barrier state (128B padded)
__device__ unsigned g_barC[BB*32];
__device__ unsigned g_barG[BB*32];

__device__ __forceinline__ float sigmoid_fast(float x) {
    return __fdividef(1.f, 1.f + __expf(-x));
}

// ---- packed f32x2 helpers (sm_103a) ----
typedef unsigned long long u64;
__device__ __forceinline__ u64 pk2(float lo, float hi) {
    u64 d;
    asm("mov.b64 %0, {%1, %2};" : "=l"(d) : "r"(__float_as_uint(lo)), "r"(__float_as_uint(hi)));
    return d;
}
__device__ __forceinline__ void upk2(u64 v, float& lo, float& hi) {
    unsigned int a, b;
    asm("mov.b64 {%0, %1}, %2;" : "=r"(a), "=r"(b) : "l"(v));
    lo = __uint_as_float(a); hi = __uint_as_float(b);
}
__device__ __forceinline__ u64 ffma2(u64 a, u64 b, u64 c) {
    u64 d;
    asm("fma.rn.f32x2 %0, %1, %2, %3;" : "=l"(d) : "l"(a), "l"(b), "l"(c));
    return d;
}
__device__ __forceinline__ u64 fadd2(u64 a, u64 b) {
    u64 d;
    asm("add.rn.f32x2 %0, %1, %2;" : "=l"(d) : "l"(a), "l"(b));
    return d;
}
// f32x2 (lo,hi) -> f16x2 (lo in low half)
__device__ __forceinline__ unsigned f2h2(u64 v) {
    float lo, hi; upk2(v, lo, hi);
    unsigned d;
    asm("cvt.rn.f16x2.f32 %0, %1, %2;" : "=r"(d) : "f"(hi), "f"(lo));
    return d;
}
__device__ __forceinline__ unsigned tanh2_hw(unsigned s) {
    unsigned d; asm("tanh.approx.f16x2 %0, %1;" : "=r"(d) : "r"(s)); return d;
}
__device__ __forceinline__ unsigned hfma2(unsigned a, unsigned b, unsigned c) {
    unsigned d;
    asm("fma.rn.f16x2 %0, %1, %2, %3;" : "=r"(d) : "r"(a), "r"(b), "r"(c));
    return d;
}
// f16x2 -> two f32
__device__ __forceinline__ void h2f2(unsigned h, float& lo, float& hi) {
    asm("{.reg .b16 l, hh; mov.b32 {l, hh}, %2; cvt.f32.f16 %0, l; cvt.f32.f16 %1, hh;}"
        : "=f"(lo), "=f"(hi) : "r"(h));
}
// bf16x2 word -> f32x2 (low half -> lane0)
__device__ __forceinline__ u64 bf2f2(unsigned u) {
    return pk2(__uint_as_float(u << 16), __uint_as_float(u & 0xFFFF0000u));
}
__device__ __forceinline__ unsigned pack_bf16x2(float x, float y) {
    return ((unsigned)__bfloat16_as_ushort(__float2bfloat16_rn(y)) << 16)
         |  (unsigned)__bfloat16_as_ushort(__float2bfloat16_rn(x));
}

// ---------------- prep ----------------
__global__ void __launch_bounds__(256) prep_kernel(const int* __restrict__ tgt,
                            const float* __restrict__ embed,
                            const float* __restrict__ w1,
                            const float* __restrict__ w2,
                            const float* __restrict__ w3,
                            const float* __restrict__ W_h,
                            const float* __restrict__ fc_W,
                            const float* __restrict__ W_cov) {
    int idx = blockIdx.x * 256 + threadIdx.x;
    if (idx < BB*TT*HID) {
        int bt = idx >> 8;
        g_x0[idx] = embed[tgt[bt]*HID + (idx & 255)];
    }
    if (idx < 512*256*3) {
        int o = idx / 768, rem = idx % 768, ic = rem / 3, k = rem % 3;
        int d = (k*256 + ic)*512 + o;
        g_wT1[d] = w1[idx];
        g_wT2[d] = w2[idx];
        g_wT3[d] = w3[idx];
    }
    if (idx < AA*HID) {
        int a = idx >> 8, h = idx & 255;
        g_WhT[h*AA + a] = W_h[idx];
    }
    if (idx < VV*(HID+CE)) {
        int v = idx / (HID+CE), j = idx % (HID+CE);
        g_fcWT[j*VV + v] = fc_W[idx];
    }
    if (idx < AA*26) {
        int a = idx / 26, k = idx % 26;
        float w = (k < 25) ? W_cov[a*25 + k] : 0.f;
        g_Wc2[idx] = make_float2(w, w);
    }
}

// ---------------- causal GLU layer (32t x 64h tiles) ----------------
__global__ void __launch_bounds__(256) glu_kernel(int src_sel, int layer,
                                                  const float* __restrict__ bias) {
    const float* xin  = src_sel ? g_x1 : g_x0;
    float*       xout = src_sel ? g_x0 : g_x1;
    const float* wT = (layer == 0) ? g_wT1 : (layer == 1) ? g_wT2 : g_wT3;

    int b  = blockIdx.x / 3;
    int t0 = (blockIdx.x % 3) * 32;
    int h0 = blockIdx.y * 64;
    __shared__ float As[34][17];
    __shared__ float Wa[3][16][64];
    __shared__ float Wg[3][16][64];
    int tid = threadIdx.x;
    int tr = (tid & 15) * 2;
    int tc = (tid >> 4) * 4;
    float aa[2][4], gg[2][4];
#pragma unroll
    for (int r = 0; r < 2; r++)
#pragma unroll
        for (int c = 0; c < 4; c++) { aa[r][c] = 0.f; gg[r][c] = 0.f; }

    for (int ic0 = 0; ic0 < 256; ic0 += 16) {
        __syncthreads();
        for (int idx = tid; idx < 34*16; idx += 256) {
            int r = idx >> 4, c = idx & 15;
            int tg = t0 - 2 + r;
            As[r][c] = (tg >= 0) ? xin[(b*TT + tg)*HID + ic0 + c] : 0.f;
        }
        for (int idx = tid; idx < 3072; idx += 256) {
            int k = idx >> 10, rem = idx & 1023, i = rem >> 6, j = rem & 63;
            const float* base = wT + (k*256 + ic0 + i)*512 + h0 + j;
            Wa[k][i][j] = base[0];
            Wg[k][i][j] = base[256];
        }
        __syncthreads();
#pragma unroll
        for (int k = 0; k < 3; k++) {
#pragma unroll
            for (int i = 0; i < 16; i++) {
                float x0 = As[tr + k][i];
                float x1 = As[tr + 1 + k][i];
#pragma unroll
                for (int c = 0; c < 4; c++) {
                    float wa = Wa[k][i][tc + c];
                    float wg = Wg[k][i][tc + c];
                    aa[0][c] = fmaf(x0, wa, aa[0][c]);
                    aa[1][c] = fmaf(x1, wa, aa[1][c]);
                    gg[0][c] = fmaf(x0, wg, gg[0][c]);
                    gg[1][c] = fmaf(x1, wg, gg[1][c]);
                }
            }
        }
    }
#pragma unroll
    for (int r = 0; r < 2; r++)
#pragma unroll
        for (int c = 0; c < 4; c++) {
            int t = t0 + tr + r, h = h0 + tc + c;
            float av = aa[r][c] + bias[h];
            float gv = gg[r][c] + bias[256 + h];
            xout[(b*TT + t)*HID + h] = av * sigmoid_fast(gv);
        }
}

// ---------------- enc_proj (f32x2) -> bf16 blocked layout ----------------
__global__ void __launch_bounds__(256) encproj_kernel(const float* __restrict__ enc_feat,
                                                      const float* __restrict__ W_enc,
                                                      const float* __restrict__ b_enc) {
    int b = blockIdx.x, a0 = blockIdx.y*64, p0 = blockIdx.z*64;
    __shared__ float Ws[16][66];
    __shared__ __align__(16) float Fs[16][64];
    int tid = threadIdx.x;
    int ta = (tid & 15)*4, tp = (tid >> 4)*4;
    u64 acc2[4][2];
#pragma unroll
    for (int r = 0; r < 4; r++) { acc2[r][0] = 0ull; acc2[r][1] = 0ull; }

    for (int c0 = 0; c0 < CE; c0 += 16) {
        __syncthreads();
        for (int idx = tid; idx < 1024; idx += 256) {
            int j = idx & 15, i = idx >> 4;
            Ws[j][i] = W_enc[(a0 + i)*CE + c0 + j];
        }
        for (int idx = tid; idx < 1024; idx += 256) {
            int i = idx & 63, j = idx >> 6;
            Fs[j][i] = enc_feat[((size_t)b*CE + c0 + j)*HW + p0 + i];
        }
        __syncthreads();
#pragma unroll
        for (int j = 0; j < 16; j++) {
            const u64* fp = (const u64*)&Fs[j][tp];
            u64 f01 = fp[0], f23 = fp[1];
#pragma unroll
            for (int r = 0; r < 4; r++) {
                float av = Ws[j][ta + r];
                u64 ad = pk2(av, av);
                acc2[r][0] = ffma2(ad, f01, acc2[r][0]);
                acc2[r][1] = ffma2(ad, f23, acc2[r][1]);
            }
        }
    }
    int p = p0 + tp;
    int slab_p = p >> 9;               // strip
    int within = p & 511;
    int row = within >> 6, cc = within & 63;
    int ts = row*16 + (cc >> 2);
#pragma unroll
    for (int r = 0; r < 4; r++) {
        int a = a0 + ta + r;
        float be = b_enc[a];
        float v0, v1, v2, v3;
        upk2(acc2[r][0], v0, v1);
        upk2(acc2[r][1], v2, v3);
        int slab = (b*NZ + (a >> 5))*2 + slab_p;
        uint2 u;
        u.x = pack_bf16x2(v0 + be, v1 + be);
        u.y = pack_bf16x2(v2 + be, v3 + be);
        g_EPh[slab*4096 + ((a & 31)*128 + ts)] = u;
    }
}

// ---------------- q precompute ----------------
__global__ void __launch_bounds__(256) qgemm_kernel(const float* __restrict__ b_h,
                                                    const float* __restrict__ b_cov) {
    int m0 = blockIdx.x * 64;
    int n0 = blockIdx.y * 64;
    __shared__ float Hs[16][66];
    __shared__ float Ws[16][64];
    int tid = threadIdx.x;
    int tm = (tid & 15)*4, tn = (tid >> 4)*4;
    float acc[4][4];
#pragma unroll
    for (int r = 0; r < 4; r++)
#pragma unroll
        for (int c = 0; c < 4; c++) acc[r][c] = 0.f;

    for (int k0 = 0; k0 < HID; k0 += 16) {
        __syncthreads();
        for (int idx = tid; idx < 1024; idx += 256) {
            int kk = idx & 15, m = idx >> 4;
            Hs[kk][m] = g_x1[(m0 + m)*HID + k0 + kk];
        }
        for (int idx = tid; idx < 1024; idx += 256) {
            int i = idx & 63, kk = idx >> 6;
            Ws[kk][i] = g_WhT[(k0 + kk)*AA + n0 + i];
        }
        __syncthreads();
#pragma unroll
        for (int kk = 0; kk < 16; kk++) {
            float hv[4], wv[4];
#pragma unroll
            for (int r = 0; r < 4; r++) hv[r] = Hs[kk][tm + r];
#pragma unroll
            for (int c = 0; c < 4; c++) wv[c] = Ws[kk][tn + c];
#pragma unroll
            for (int r = 0; r < 4; r++)
#pragma unroll
                for (int c = 0; c < 4; c++)
                    acc[r][c] = fmaf(hv[r], wv[c], acc[r][c]);
        }
    }
#pragma unroll
    for (int r = 0; r < 4; r++)
#pragma unroll
        for (int c = 0; c < 4; c++) {
            int n = n0 + tn + c;
            g_QB[(m0 + tm + r)*AA + n] = acc[r][c] + b_h[n] + b_cov[n];
        }
}

// ---------------- persistent scan: smem EP, f16x2 tanh, per-batch barrier ----------------
// bid = b*16 + zc*2 + strip
__global__ void __launch_bounds__(128, 4) scan_kernel(const float* __restrict__ v_attn) {
    int bid   = blockIdx.x;
    int b     = bid >> 4;
    int zc    = (bid >> 1) & 7;
    int strip = bid & 1;
    int a0    = zc * ACH;
    int r0    = strip * 8;

    __shared__ __align__(16) uint2  sEP[ACH*128];    // 32KB bf16 EP slab
    __shared__ float  sCov[12][68];                  // persistent cov halo patch
    __shared__ __align__(16) float2 sW[ACH*26];
    __shared__ float  sE[HW];                        // exp(e - m) full image
    __shared__ float2 sQ2[ACH];
    __shared__ unsigned sVh[ACH];                    // (v,v) f16x2
    __shared__ float  redm[4], reds[4];

    int tid = threadIdx.x, lane = tid & 31, warp = tid >> 5;

    // one-time fills
    {
        const uint2* src = g_EPh + ((b*NZ + zc)*2 + strip)*4096;
        for (int i = tid; i < ACH*128; i += 128) sEP[i] = src[i];
    }
    for (int i = tid; i < ACH*26; i += 128) sW[i] = g_Wc2[a0*26 + i];
    if (tid < ACH) {
        float v = v_attn[a0 + tid];
        unsigned d;
        asm("cvt.rn.f16x2.f32 %0, %1, %2;" : "=r"(d) : "f"(v), "f"(v));
        sVh[tid] = d;
    }
    for (int i = tid; i < 12*68; i += 128) ((float*)sCov)[i] = 0.f;

    int row = tid >> 4;
    int c0  = (tid & 15) * 4;
    int pix = (r0 + row)*WW_ + c0;
    const ulonglong2* wb = (const ulonglong2*)sW;
    const u64* q2p = (const u64*)sQ2;

    for (int t = 0; t < TT; t++) {
        int ping = t & 1;
        if (tid < ACH) {
            float q = g_QB[(b*TT + t)*AA + a0 + tid];
            sQ2[tid] = make_float2(q, q);
        }
        __syncthreads();

        // ---- energy ----
        u64 pp[5][7];
#pragma unroll
        for (int dy = 0; dy < 5; dy++)
#pragma unroll
            for (int dx = 0; dx < 7; dx++)
                pp[dy][dx] = pk2(sCov[row + dy][c0 + dx], sCov[row + dy][c0 + dx + 1]);

        u64 e0f = 0ull, e1f = 0ull;     // f32x2 master accumulators
#pragma unroll 1
        for (int g = 0; g < 4; g++) {
            unsigned e0h = 0u, e1h = 0u;    // f16x2 partial accumulators
#pragma unroll
            for (int u = 0; u < 8; u++) {
                int aa = g*8 + u;
                uint2 epw = sEP[aa*128 + tid];
                u64 q2 = q2p[aa];
                u64 a00 = fadd2(bf2f2(epw.x), q2), a01 = 0ull;
                u64 a10 = fadd2(bf2f2(epw.y), q2), a11 = 0ull;
                const ulonglong2* w2 = wb + aa*13;
#pragma unroll
                for (int j = 0; j < 13; j++) {
                    ulonglong2 w = w2[j];
                    {   const int k = 2*j;
                        if (k < 25) {
                            const int dy = k / 5, dx = k % 5;
                            a00 = ffma2(pp[dy][dx],     w.x, a00);
                            a10 = ffma2(pp[dy][dx + 2], w.x, a10);
                        }
                    }
                    {   const int k = 2*j + 1;
                        if (k < 25) {
                            const int dy = k / 5, dx = k % 5;
                            a01 = ffma2(pp[dy][dx],     w.y, a01);
                            a11 = ffma2(pp[dy][dx + 2], w.y, a11);
                        }
                    }
                }
                unsigned s0h = f2h2(fadd2(a00, a01));
                unsigned s1h = f2h2(fadd2(a10, a11));
                unsigned vh = sVh[aa];
                e0h = hfma2(tanh2_hw(s0h), vh, e0h);
                e1h = hfma2(tanh2_hw(s1h), vh, e1h);
            }
            float f0, f1, f2, f3;
            h2f2(e0h, f0, f1);
            h2f2(e1h, f2, f3);
            e0f = fadd2(e0f, pk2(f0, f1));
            e1f = fadd2(e1f, pk2(f2, f3));
        }
        {
            float r0_, r1_, r2_, r3_;
            upk2(e0f, r0_, r1_); upk2(e1f, r2_, r3_);
            *(float4*)&g_epart[(size_t)ping*(NZ*BB*HW) + (zc*BB + b)*HW + pix] =
                make_float4(r0_, r1_, r2_, r3_);
        }

        // ---- per-batch barrier (16 arrivals) ----
        __threadfence();
        __syncthreads();
        if (tid == 0) {
            volatile unsigned* gp = &g_barG[b*32];
            unsigned gen = *gp;
            unsigned arrived = atomicAdd(&g_barC[b*32], 1u);
            if (arrived == NBLK_B - 1) {
                g_barC[b*32] = 0;
                __threadfence();
                *gp = gen + 1;
            } else {
                int spins = 0;
                while (*gp == gen) { __nanosleep(64); if (++spins > (1 << 23)) break; }
            }
            __threadfence();
        }
        __syncthreads();

        // ---- phase2 (redundant per block): softmax + cov halo + alpha ----
        float e8[8];
        {
            float4 s0v = make_float4(0.f,0.f,0.f,0.f);
            float4 s1v = make_float4(0.f,0.f,0.f,0.f);
            const float* base = g_epart + (size_t)ping*(NZ*BB*HW) + b*HW + tid*8;
#pragma unroll
            for (int z = 0; z < NZ; z++) {
                const float4* p4 = (const float4*)(base + (size_t)z*BB*HW);
                float4 q0 = __ldcg(p4);
                float4 q1 = __ldcg(p4 + 1);
                s0v.x += q0.x; s0v.y += q0.y; s0v.z += q0.z; s0v.w += q0.w;
                s1v.x += q1.x; s1v.y += q1.y; s1v.z += q1.z; s1v.w += q1.w;
            }
            e8[0]=s0v.x; e8[1]=s0v.y; e8[2]=s0v.z; e8[3]=s0v.w;
            e8[4]=s1v.x; e8[5]=s1v.y; e8[6]=s1v.z; e8[7]=s1v.w;
        }
        float m = e8[0];
#pragma unroll
        for (int j = 1; j < 8; j++) m = fmaxf(m, e8[j]);
#pragma unroll
        for (int o = 16; o; o >>= 1) m = fmaxf(m, __shfl_xor_sync(~0u, m, o));
        if (lane == 0) redm[warp] = m;
        __syncthreads();
        m = fmaxf(fmaxf(redm[0], redm[1]), fmaxf(redm[2], redm[3]));

        float ex8[8], sl = 0.f;
#pragma unroll
        for (int j = 0; j < 8; j++) { ex8[j] = __expf(e8[j] - m); sl += ex8[j]; }
        ((float4*)sE)[tid*2]     = make_float4(ex8[0], ex8[1], ex8[2], ex8[3]);
        ((float4*)sE)[tid*2 + 1] = make_float4(ex8[4], ex8[5], ex8[6], ex8[7]);
#pragma unroll
        for (int o = 16; o; o >>= 1) sl += __shfl_xor_sync(~0u, sl, o);
        if (lane == 0) reds[warp] = sl;
        __syncthreads();
        float s = (reds[0] + reds[1]) + (reds[2] + reds[3]);
        float inv = __fdividef(1.f, s);

        // cov halo update (single writer per element)
        for (int h = tid; h < 12*64; h += 128) {
            int hr = h >> 6, cc = h & 63;
            int imrow = r0 - 2 + hr;
            if ((unsigned)imrow < HH_)
                sCov[hr][cc + 2] += sE[imrow*WW_ + cc] * inv;
        }
        // one block per batch stores full alpha image for ctx GEMM
        if (zc == 0 && strip == 0) {
            float4* ap = (float4*)(g_alpha + ((size_t)b*TT + t)*HW) + tid*2;
            ap[0] = make_float4(ex8[0]*inv, ex8[1]*inv, ex8[2]*inv, ex8[3]*inv);
            ap[1] = make_float4(ex8[4]*inv, ex8[5]*inv, ex8[6]*inv, ex8[7]*inv);
        }
        __syncthreads();
    }
}

// ---------------- batched ctx GEMM (f32x2) ----------------
__global__ void __launch_bounds__(256) ctxgemm_kernel(const float* __restrict__ enc_feat) {
    int b  = blockIdx.x;
    int m0 = blockIdx.y * 64;
    int n0 = blockIdx.z * 64;
    __shared__ float As[16][66];
    __shared__ __align__(16) float Fs[16][64];
    int tid = threadIdx.x;
    int tm = (tid & 15)*4, tn = (tid >> 4)*4;
    u64 acc2[4][2];
#pragma unroll
    for (int r = 0; r < 4; r++) { acc2[r][0] = 0ull; acc2[r][1] = 0ull; }

    for (int k0 = 0; k0 < HW; k0 += 16) {
        __syncthreads();
        for (int idx = tid; idx < 1024; idx += 256) {
            int kk = idx & 15, mm = idx >> 4;
            int tt = m0 + mm;
            As[kk][mm] = (tt < TT) ? g_alpha[((size_t)b*TT + tt)*HW + k0 + kk] : 0.f;
        }
        for (int idx = tid; idx < 1024; idx += 256) {
            int i = idx & 63, kk = idx >> 6;
            int cc = n0 + i;
            Fs[kk][i] = (cc < CE) ? enc_feat[((size_t)b*CE + cc)*HW + k0 + kk] : 0.f;
        }
        __syncthreads();
#pragma unroll
        for (int kk = 0; kk < 16; kk++) {
            const u64* fp = (const u64*)&Fs[kk][tn];
            u64 f01 = fp[0], f23 = fp[1];
#pragma unroll
            for (int r = 0; r < 4; r++) {
                float av = As[kk][tm + r];
                u64 ad = pk2(av, av);
                acc2[r][0] = ffma2(ad, f01, acc2[r][0]);
                acc2[r][1] = ffma2(ad, f23, acc2[r][1]);
            }
        }
    }
#pragma unroll
    for (int r = 0; r < 4; r++) {
        int tt = m0 + tm + r;
        if (tt < TT) {
            float v0, v1, v2, v3;
            upk2(acc2[r][0], v0, v1);
            upk2(acc2[r][1], v2, v3);
            float vv[4] = {v0, v1, v2, v3};
#pragma unroll
            for (int c = 0; c < 4; c++) {
                int cc = n0 + tn + c;
                if (cc < CE) g_ctxall[((size_t)b*TT + tt)*CE + cc] = vv[c];
            }
        }
    }
}

// ---------------- final fc ----------------
__global__ void __launch_bounds__(256) fc_kernel(const float* __restrict__ fc_b,
                                                 float* __restrict__ out) {
    int m0 = blockIdx.x * 64;
    int n0 = blockIdx.y * 64;
    __shared__ float Is[16][66];
    __shared__ float Ws[16][64];
    int tid = threadIdx.x;
    int tm = (tid & 15)*4, tn = (tid >> 4)*4;
    float acc[4][4];
#pragma unroll
    for (int r = 0; r < 4; r++)
#pragma unroll
        for (int c = 0; c < 4; c++) acc[r][c] = 0.f;

    for (int k0 = 0; k0 < HID + CE; k0 += 16) {
        __syncthreads();
        const float* src; int stride, off;
        if (k0 < HID) { src = g_x1;     stride = HID; off = k0; }
        else          { src = g_ctxall; stride = CE;  off = k0 - HID; }
        for (int idx = tid; idx < 1024; idx += 256) {
            int kk = idx & 15, mm = idx >> 4;
            Is[kk][mm] = src[(m0 + mm)*stride + off + kk];
        }
        for (int idx = tid; idx < 1024; idx += 256) {
            int i = idx & 63, kk = idx >> 6;
            Ws[kk][i] = g_fcWT[(k0 + kk)*VV + n0 + i];
        }
        __syncthreads();
#pragma unroll
        for (int kk = 0; kk < 16; kk++) {
            float iv[4], wv[4];
#pragma unroll
            for (int r = 0; r < 4; r++) iv[r] = Is[kk][tm + r];
#pragma unroll
            for (int c = 0; c < 4; c++) wv[c] = Ws[kk][tn + c];
#pragma unroll
            for (int r = 0; r < 4; r++)
#pragma unroll
                for (int c = 0; c < 4; c++)
                    acc[r][c] = fmaf(iv[r], wv[c], acc[r][c]);
        }
    }
#pragma unroll
    for (int r = 0; r < 4; r++)
#pragma unroll
        for (int c = 0; c < 4; c++) {
            int n = n0 + tn + c;
            out[(m0 + tm + r)*VV + n] = acc[r][c] + fc_b[n];
        }
}

// ---------------- launch ----------------
extern "C" void kernel_launch(void* const* d_in, const int* in_sizes, int n_in,
                              void* d_out, int out_size) {
    const float* enc_feat = (const float*)d_in[0];
    const int*   tgt      = (const int*)  d_in[1];
    const float* embed    = (const float*)d_in[2];
    const float* w1       = (const float*)d_in[3];
    const float* b1       = (const float*)d_in[4];
    const float* w2       = (const float*)d_in[5];
    const float* b2       = (const float*)d_in[6];
    const float* w3       = (const float*)d_in[7];
    const float* b3       = (const float*)d_in[8];
    const float* W_enc    = (const float*)d_in[9];
    const float* b_enc    = (const float*)d_in[10];
    const float* W_h      = (const float*)d_in[11];
    const float* b_h      = (const float*)d_in[12];
    const float* W_cov    = (const float*)d_in[13];
    const float* b_cov    = (const float*)d_in[14];
    const float* v_attn   = (const float*)d_in[15];
    const float* fc_W     = (const float*)d_in[16];
    const float* fc_b     = (const float*)d_in[17];
    float* out = (float*)d_out;

    prep_kernel<<<3072, 256>>>(tgt, embed, w1, w2, w3, W_h, fc_W, W_cov);

    dim3 gglu(BB*3, 4);
    glu_kernel<<<gglu, 256>>>(0, 0, b1);   // g_x0 -> g_x1
    glu_kernel<<<gglu, 256>>>(1, 1, b2);   // g_x1 -> g_x0
    glu_kernel<<<gglu, 256>>>(0, 2, b3);   // g_x0 -> g_x1 (= hidd)

    encproj_kernel<<<dim3(BB, 4, 16), 256>>>(enc_feat, W_enc, b_enc);
    qgemm_kernel<<<dim3(48, 4), 256>>>(b_h, b_cov);

    scan_kernel<<<GRID, 128>>>(v_attn);

    ctxgemm_kernel<<<dim3(BB, 2, 7), 256>>>(enc_feat);
    fc_kernel<<<dim3(48, 4), 256>>>(fc_b, out);
}

// round 9
// speedup vs baseline: 1.5043x; 1.2585x over previous
#include <cuda_runtime.h>
#include <cuda_bf16.h>

#define BB   32
#define TT   96
#define HID  256
#define CE   400
#define VV   256
#define HH_  16
#define WW_  64
#define AA   256
#define HW   1024
#define NZ   8          // a-chunks
#define ACH  32         // a per chunk
#define GRID 512        // 32 b x 8 zc x 2 strips
#define NBLK_B 16       // blocks per batch

// ---------------- device scratch ----------------
__device__ __align__(16) float g_x0[BB*TT*HID];
__device__ __align__(16) float g_x1[BB*TT*HID];
__device__ __align__(16) float g_wT1[3*256*512];
__device__ __align__(16) float g_wT2[3*256*512];
__device__ __align__(16) float g_wT3[3*256*512];
__device__ __align__(16) float g_WhT[HID*AA];
__device__ __align__(16) float g_fcWT[(HID+CE)*VV];
__device__ __align__(16) unsigned g_Wch[AA*28];      // f16x2 dup-packed (w,w), taps 25..27 = 0
__device__ __align__(16) uint2 g_EPh[BB*NZ*2*4096];  // f16 EP, blocked [slab][aa*128+t]
__device__ __align__(16) float g_QB[BB*TT*AA];       // q + b_h + b_cov
__device__ __align__(16) float g_epart[2*NZ*BB*HW];  // double-buffered partial e
__device__ __align__(16) float g_alpha[BB*TT*HW];
__device__ __align__(16) float g_ctxall[BB*TT*CE];

// per-batch barrier state (128B padded)
__device__ unsigned g_barC[BB*32];
__device__ unsigned g_barG[BB*32];

__device__ __forceinline__ float sigmoid_fast(float x) {
    return __fdividef(1.f, 1.f + __expf(-x));
}

// ---- packed helpers (sm_103a) ----
typedef unsigned long long u64;
__device__ __forceinline__ u64 pk2(float lo, float hi) {
    u64 d;
    asm("mov.b64 %0, {%1, %2};" : "=l"(d) : "r"(__float_as_uint(lo)), "r"(__float_as_uint(hi)));
    return d;
}
__device__ __forceinline__ void upk2(u64 v, float& lo, float& hi) {
    unsigned int a, b;
    asm("mov.b64 {%0, %1}, %2;" : "=r"(a), "=r"(b) : "l"(v));
    lo = __uint_as_float(a); hi = __uint_as_float(b);
}
__device__ __forceinline__ u64 ffma2(u64 a, u64 b, u64 c) {
    u64 d;
    asm("fma.rn.f32x2 %0, %1, %2, %3;" : "=l"(d) : "l"(a), "l"(b), "l"(c));
    return d;
}
__device__ __forceinline__ u64 fadd2(u64 a, u64 b) {
    u64 d;
    asm("add.rn.f32x2 %0, %1, %2;" : "=l"(d) : "l"(a), "l"(b));
    return d;
}
// pack two f32 -> f16x2 (lo in low half)
__device__ __forceinline__ unsigned pk_h2(float lo, float hi) {
    unsigned d;
    asm("cvt.rn.f16x2.f32 %0, %1, %2;" : "=r"(d) : "f"(hi), "f"(lo));
    return d;
}
__device__ __forceinline__ unsigned tanh2_hw(unsigned s) {
    unsigned d; asm("tanh.approx.f16x2 %0, %1;" : "=r"(d) : "r"(s)); return d;
}
__device__ __forceinline__ unsigned hfma2(unsigned a, unsigned b, unsigned c) {
    unsigned d;
    asm("fma.rn.f16x2 %0, %1, %2, %3;" : "=r"(d) : "r"(a), "r"(b), "r"(c));
    return d;
}
__device__ __forceinline__ unsigned hadd2(unsigned a, unsigned b) {
    unsigned d;
    asm("add.rn.f16x2 %0, %1, %2;" : "=r"(d) : "r"(a), "r"(b));
    return d;
}
// f16x2 -> two f32
__device__ __forceinline__ void h2f2(unsigned h, float& lo, float& hi) {
    asm("{.reg .b16 l, hh; mov.b32 {l, hh}, %2; cvt.f32.f16 %0, l; cvt.f32.f16 %1, hh;}"
        : "=f"(lo), "=f"(hi) : "r"(h));
}

// ---------------- prep ----------------
__global__ void __launch_bounds__(256) prep_kernel(const int* __restrict__ tgt,
                            const float* __restrict__ embed,
                            const float* __restrict__ w1,
                            const float* __restrict__ w2,
                            const float* __restrict__ w3,
                            const float* __restrict__ W_h,
                            const float* __restrict__ fc_W,
                            const float* __restrict__ W_cov) {
    int idx = blockIdx.x * 256 + threadIdx.x;
    if (idx < BB*TT*HID) {
        int bt = idx >> 8;
        g_x0[idx] = embed[tgt[bt]*HID + (idx & 255)];
    }
    if (idx < 512*256*3) {
        int o = idx / 768, rem = idx % 768, ic = rem / 3, k = rem % 3;
        int d = (k*256 + ic)*512 + o;
        g_wT1[d] = w1[idx];
        g_wT2[d] = w2[idx];
        g_wT3[d] = w3[idx];
    }
    if (idx < AA*HID) {
        int a = idx >> 8, h = idx & 255;
        g_WhT[h*AA + a] = W_h[idx];
    }
    if (idx < VV*(HID+CE)) {
        int v = idx / (HID+CE), j = idx % (HID+CE);
        g_fcWT[j*VV + v] = fc_W[idx];
    }
    if (idx < AA*28) {
        int a = idx / 28, k = idx % 28;
        float w = (k < 25) ? W_cov[a*25 + k] : 0.f;
        g_Wch[idx] = pk_h2(w, w);
    }
}

// ---------------- causal GLU layer (32t x 64h tiles) ----------------
__global__ void __launch_bounds__(256) glu_kernel(int src_sel, int layer,
                                                  const float* __restrict__ bias) {
    const float* xin  = src_sel ? g_x1 : g_x0;
    float*       xout = src_sel ? g_x0 : g_x1;
    const float* wT = (layer == 0) ? g_wT1 : (layer == 1) ? g_wT2 : g_wT3;

    int b  = blockIdx.x / 3;
    int t0 = (blockIdx.x % 3) * 32;
    int h0 = blockIdx.y * 64;
    __shared__ float As[34][17];
    __shared__ float Wa[3][16][64];
    __shared__ float Wg[3][16][64];
    int tid = threadIdx.x;
    int tr = (tid & 15) * 2;
    int tc = (tid >> 4) * 4;
    float aa[2][4], gg[2][4];
#pragma unroll
    for (int r = 0; r < 2; r++)
#pragma unroll
        for (int c = 0; c < 4; c++) { aa[r][c] = 0.f; gg[r][c] = 0.f; }

    for (int ic0 = 0; ic0 < 256; ic0 += 16) {
        __syncthreads();
        for (int idx = tid; idx < 34*16; idx += 256) {
            int r = idx >> 4, c = idx & 15;
            int tg = t0 - 2 + r;
            As[r][c] = (tg >= 0) ? xin[(b*TT + tg)*HID + ic0 + c] : 0.f;
        }
        for (int idx = tid; idx < 3072; idx += 256) {
            int k = idx >> 10, rem = idx & 1023, i = rem >> 6, j = rem & 63;
            const float* base = wT + (k*256 + ic0 + i)*512 + h0 + j;
            Wa[k][i][j] = base[0];
            Wg[k][i][j] = base[256];
        }
        __syncthreads();
#pragma unroll
        for (int k = 0; k < 3; k++) {
#pragma unroll
            for (int i = 0; i < 16; i++) {
                float x0 = As[tr + k][i];
                float x1 = As[tr + 1 + k][i];
#pragma unroll
                for (int c = 0; c < 4; c++) {
                    float wa = Wa[k][i][tc + c];
                    float wg = Wg[k][i][tc + c];
                    aa[0][c] = fmaf(x0, wa, aa[0][c]);
                    aa[1][c] = fmaf(x1, wa, aa[1][c]);
                    gg[0][c] = fmaf(x0, wg, gg[0][c]);
                    gg[1][c] = fmaf(x1, wg, gg[1][c]);
                }
            }
        }
    }
#pragma unroll
    for (int r = 0; r < 2; r++)
#pragma unroll
        for (int c = 0; c < 4; c++) {
            int t = t0 + tr + r, h = h0 + tc + c;
            float av = aa[r][c] + bias[h];
            float gv = gg[r][c] + bias[256 + h];
            xout[(b*TT + t)*HID + h] = av * sigmoid_fast(gv);
        }
}

// ---------------- enc_proj (f32x2 accum) -> f16 blocked layout ----------------
__global__ void __launch_bounds__(256) encproj_kernel(const float* __restrict__ enc_feat,
                                                      const float* __restrict__ W_enc,
                                                      const float* __restrict__ b_enc) {
    int b = blockIdx.x, a0 = blockIdx.y*64, p0 = blockIdx.z*64;
    __shared__ float Ws[16][66];
    __shared__ __align__(16) float Fs[16][64];
    int tid = threadIdx.x;
    int ta = (tid & 15)*4, tp = (tid >> 4)*4;
    u64 acc2[4][2];
#pragma unroll
    for (int r = 0; r < 4; r++) { acc2[r][0] = 0ull; acc2[r][1] = 0ull; }

    for (int c0 = 0; c0 < CE; c0 += 16) {
        __syncthreads();
        for (int idx = tid; idx < 1024; idx += 256) {
            int j = idx & 15, i = idx >> 4;
            Ws[j][i] = W_enc[(a0 + i)*CE + c0 + j];
        }
        for (int idx = tid; idx < 1024; idx += 256) {
            int i = idx & 63, j = idx >> 6;
            Fs[j][i] = enc_feat[((size_t)b*CE + c0 + j)*HW + p0 + i];
        }
        __syncthreads();
#pragma unroll
        for (int j = 0; j < 16; j++) {
            const u64* fp = (const u64*)&Fs[j][tp];
            u64 f01 = fp[0], f23 = fp[1];
#pragma unroll
            for (int r = 0; r < 4; r++) {
                float av = Ws[j][ta + r];
                u64 ad = pk2(av, av);
                acc2[r][0] = ffma2(ad, f01, acc2[r][0]);
                acc2[r][1] = ffma2(ad, f23, acc2[r][1]);
            }
        }
    }
    int p = p0 + tp;
    int slab_p = p >> 9;               // strip
    int within = p & 511;
    int row = within >> 6, cc = within & 63;
    int ts = row*16 + (cc >> 2);
#pragma unroll
    for (int r = 0; r < 4; r++) {
        int a = a0 + ta + r;
        float be = b_enc[a];
        float v0, v1, v2, v3;
        upk2(acc2[r][0], v0, v1);
        upk2(acc2[r][1], v2, v3);
        int slab = (b*NZ + (a >> 5))*2 + slab_p;
        uint2 u;
        u.x = pk_h2(v0 + be, v1 + be);
        u.y = pk_h2(v2 + be, v3 + be);
        g_EPh[slab*4096 + ((a & 31)*128 + ts)] = u;
    }
}

// ---------------- q precompute ----------------
__global__ void __launch_bounds__(256) qgemm_kernel(const float* __restrict__ b_h,
                                                    const float* __restrict__ b_cov) {
    int m0 = blockIdx.x * 64;
    int n0 = blockIdx.y * 64;
    __shared__ float Hs[16][66];
    __shared__ float Ws[16][64];
    int tid = threadIdx.x;
    int tm = (tid & 15)*4, tn = (tid >> 4)*4;
    float acc[4][4];
#pragma unroll
    for (int r = 0; r < 4; r++)
#pragma unroll
        for (int c = 0; c < 4; c++) acc[r][c] = 0.f;

    for (int k0 = 0; k0 < HID; k0 += 16) {
        __syncthreads();
        for (int idx = tid; idx < 1024; idx += 256) {
            int kk = idx & 15, m = idx >> 4;
            Hs[kk][m] = g_x1[(m0 + m)*HID + k0 + kk];
        }
        for (int idx = tid; idx < 1024; idx += 256) {
            int i = idx & 63, kk = idx >> 6;
            Ws[kk][i] = g_WhT[(k0 + kk)*AA + n0 + i];
        }
        __syncthreads();
#pragma unroll
        for (int kk = 0; kk < 16; kk++) {
            float hv[4], wv[4];
#pragma unroll
            for (int r = 0; r < 4; r++) hv[r] = Hs[kk][tm + r];
#pragma unroll
            for (int c = 0; c < 4; c++) wv[c] = Ws[kk][tn + c];
#pragma unroll
            for (int r = 0; r < 4; r++)
#pragma unroll
                for (int c = 0; c < 4; c++)
                    acc[r][c] = fmaf(hv[r], wv[c], acc[r][c]);
        }
    }
#pragma unroll
    for (int r = 0; r < 4; r++)
#pragma unroll
        for (int c = 0; c < 4; c++) {
            int n = n0 + tn + c;
            g_QB[(m0 + tm + r)*AA + n] = acc[r][c] + b_h[n] + b_cov[n];
        }
}

// ---------------- persistent scan: f16x2 conv+tanh, smem EP, per-batch barrier ----------------
// bid = b*16 + zc*2 + strip
__global__ void __launch_bounds__(128, 4) scan_kernel(const float* __restrict__ v_attn) {
    int bid   = blockIdx.x;
    int b     = bid >> 4;
    int zc    = (bid >> 1) & 7;
    int strip = bid & 1;
    int a0    = zc * ACH;
    int r0    = strip * 8;

    __shared__ __align__(16) uint2    sEP[ACH*128];    // 32KB f16 EP slab
    __shared__ float    sCov[12][68];                  // persistent cov halo patch
    __shared__ __align__(16) unsigned sWh[ACH*28];     // f16x2 dup weights
    __shared__ float    sE[HW];                        // exp(e - m) full image
    __shared__ unsigned sQh[ACH];                      // (q,q) f16x2
    __shared__ unsigned sVh[ACH];                      // (v,v) f16x2
    __shared__ float    redm[4], reds[4];

    int tid = threadIdx.x, lane = tid & 31, warp = tid >> 5;

    // one-time fills
    {
        const uint2* src = g_EPh + ((b*NZ + zc)*2 + strip)*4096;
        for (int i = tid; i < ACH*128; i += 128) sEP[i] = src[i];
    }
    for (int i = tid; i < ACH*28; i += 128) sWh[i] = g_Wch[a0*28 + i];
    if (tid < ACH) {
        float v = v_attn[a0 + tid];
        sVh[tid] = pk_h2(v, v);
    }
    for (int i = tid; i < 12*68; i += 128) ((float*)sCov)[i] = 0.f;

    int row = tid >> 4;
    int c0  = (tid & 15) * 4;
    int pix = (r0 + row)*WW_ + c0;

    for (int t = 0; t < TT; t++) {
        int ping = t & 1;
        if (tid < ACH) {
            float q = g_QB[(b*TT + t)*AA + a0 + tid];
            sQh[tid] = pk_h2(q, q);
        }
        __syncthreads();

        // ---- pack cov patch as f16x2: pph[dy][dx] = (cov[c0+dx], cov[c0+dx+1]) ----
        unsigned pph[5][7];
#pragma unroll
        for (int dy = 0; dy < 5; dy++) {
            float4 ra = *(const float4*)&sCov[row + dy][c0];
            float4 rb = *(const float4*)&sCov[row + dy][c0 + 4];
            pph[dy][0] = pk_h2(ra.x, ra.y);
            pph[dy][1] = pk_h2(ra.y, ra.z);
            pph[dy][2] = pk_h2(ra.z, ra.w);
            pph[dy][3] = pk_h2(ra.w, rb.x);
            pph[dy][4] = pk_h2(rb.x, rb.y);
            pph[dy][5] = pk_h2(rb.y, rb.z);
            pph[dy][6] = pk_h2(rb.z, rb.w);
        }

        u64 e0f = 0ull, e1f = 0ull;     // f32x2 master accumulators
#pragma unroll 1
        for (int g = 0; g < 4; g++) {
            unsigned e0h = 0u, e1h = 0u;
#pragma unroll
            for (int u = 0; u < 8; u++) {
                int aa = g*8 + u;
                uint2 epw = sEP[aa*128 + tid];
                unsigned qh = sQh[aa];
                unsigned a00 = epw.x, a01 = qh;     // accumulators seeded with EP and q
                unsigned a10 = epw.y, a11 = qh;
                const uint4* w4 = (const uint4*)sWh + aa*7;
#pragma unroll
                for (int j = 0; j < 7; j++) {
                    uint4 w = w4[j];
                    {   const int k = 4*j;
                        if (k < 25) { const int dy = k/5, dx = k%5;
                            a00 = hfma2(pph[dy][dx],     w.x, a00);
                            a10 = hfma2(pph[dy][dx + 2], w.x, a10); } }
                    {   const int k = 4*j + 1;
                        if (k < 25) { const int dy = k/5, dx = k%5;
                            a01 = hfma2(pph[dy][dx],     w.y, a01);
                            a11 = hfma2(pph[dy][dx + 2], w.y, a11); } }
                    {   const int k = 4*j + 2;
                        if (k < 25) { const int dy = k/5, dx = k%5;
                            a00 = hfma2(pph[dy][dx],     w.z, a00);
                            a10 = hfma2(pph[dy][dx + 2], w.z, a10); } }
                    {   const int k = 4*j + 3;
                        if (k < 25) { const int dy = k/5, dx = k%5;
                            a01 = hfma2(pph[dy][dx],     w.w, a01);
                            a11 = hfma2(pph[dy][dx + 2], w.w, a11); } }
                }
                unsigned s0 = hadd2(a00, a01);
                unsigned s1 = hadd2(a10, a11);
                unsigned vh = sVh[aa];
                e0h = hfma2(tanh2_hw(s0), vh, e0h);
                e1h = hfma2(tanh2_hw(s1), vh, e1h);
            }
            float f0, f1, f2, f3;
            h2f2(e0h, f0, f1);
            h2f2(e1h, f2, f3);
            e0f = fadd2(e0f, pk2(f0, f1));
            e1f = fadd2(e1f, pk2(f2, f3));
        }
        {
            float r0_, r1_, r2_, r3_;
            upk2(e0f, r0_, r1_); upk2(e1f, r2_, r3_);
            *(float4*)&g_epart[(size_t)ping*(NZ*BB*HW) + (zc*BB + b)*HW + pix] =
                make_float4(r0_, r1_, r2_, r3_);
        }

        // ---- per-batch barrier (16 arrivals) ----
        __threadfence();
        __syncthreads();
        if (tid == 0) {
            volatile unsigned* gp = &g_barG[b*32];
            unsigned gen = *gp;
            unsigned arrived = atomicAdd(&g_barC[b*32], 1u);
            if (arrived == NBLK_B - 1) {
                g_barC[b*32] = 0;
                __threadfence();
                *gp = gen + 1;
            } else {
                int spins = 0;
                while (*gp == gen) { __nanosleep(64); if (++spins > (1 << 23)) break; }
            }
            __threadfence();
        }
        __syncthreads();

        // ---- phase2 (redundant per block): softmax + cov halo + alpha ----
        float e8[8];
        {
            float4 s0v = make_float4(0.f,0.f,0.f,0.f);
            float4 s1v = make_float4(0.f,0.f,0.f,0.f);
            const float* base = g_epart + (size_t)ping*(NZ*BB*HW) + b*HW + tid*8;
#pragma unroll
            for (int z = 0; z < NZ; z++) {
                const float4* p4 = (const float4*)(base + (size_t)z*BB*HW);
                float4 q0 = __ldcg(p4);
                float4 q1 = __ldcg(p4 + 1);
                s0v.x += q0.x; s0v.y += q0.y; s0v.z += q0.z; s0v.w += q0.w;
                s1v.x += q1.x; s1v.y += q1.y; s1v.z += q1.z; s1v.w += q1.w;
            }
            e8[0]=s0v.x; e8[1]=s0v.y; e8[2]=s0v.z; e8[3]=s0v.w;
            e8[4]=s1v.x; e8[5]=s1v.y; e8[6]=s1v.z; e8[7]=s1v.w;
        }
        float m = e8[0];
#pragma unroll
        for (int j = 1; j < 8; j++) m = fmaxf(m, e8[j]);
#pragma unroll
        for (int o = 16; o; o >>= 1) m = fmaxf(m, __shfl_xor_sync(~0u, m, o));
        if (lane == 0) redm[warp] = m;
        __syncthreads();
        m = fmaxf(fmaxf(redm[0], redm[1]), fmaxf(redm[2], redm[3]));

        float ex8[8], sl = 0.f;
#pragma unroll
        for (int j = 0; j < 8; j++) { ex8[j] = __expf(e8[j] - m); sl += ex8[j]; }
        ((float4*)sE)[tid*2]     = make_float4(ex8[0], ex8[1], ex8[2], ex8[3]);
        ((float4*)sE)[tid*2 + 1] = make_float4(ex8[4], ex8[5], ex8[6], ex8[7]);
#pragma unroll
        for (int o = 16; o; o >>= 1) sl += __shfl_xor_sync(~0u, sl, o);
        if (lane == 0) reds[warp] = sl;
        __syncthreads();
        float s = (reds[0] + reds[1]) + (reds[2] + reds[3]);
        float inv = __fdividef(1.f, s);

        // cov halo update (single writer per element)
        for (int h = tid; h < 12*64; h += 128) {
            int hr = h >> 6, cc = h & 63;
            int imrow = r0 - 2 + hr;
            if ((unsigned)imrow < HH_)
                sCov[hr][cc + 2] += sE[imrow*WW_ + cc] * inv;
        }
        // one block per batch stores full alpha image for ctx GEMM
        if (zc == 0 && strip == 0) {
            float4* ap = (float4*)(g_alpha + ((size_t)b*TT + t)*HW) + tid*2;
            ap[0] = make_float4(ex8[0]*inv, ex8[1]*inv, ex8[2]*inv, ex8[3]*inv);
            ap[1] = make_float4(ex8[4]*inv, ex8[5]*inv, ex8[6]*inv, ex8[7]*inv);
        }
        __syncthreads();
    }
}

// ---------------- batched ctx GEMM (f32x2) ----------------
__global__ void __launch_bounds__(256) ctxgemm_kernel(const float* __restrict__ enc_feat) {
    int b  = blockIdx.x;
    int m0 = blockIdx.y * 64;
    int n0 = blockIdx.z * 64;
    __shared__ float As[16][66];
    __shared__ __align__(16) float Fs[16][64];
    int tid = threadIdx.x;
    int tm = (tid & 15)*4, tn = (tid >> 4)*4;
    u64 acc2[4][2];
#pragma unroll
    for (int r = 0; r < 4; r++) { acc2[r][0] = 0ull; acc2[r][1] = 0ull; }

    for (int k0 = 0; k0 < HW; k0 += 16) {
        __syncthreads();
        for (int idx = tid; idx < 1024; idx += 256) {
            int kk = idx & 15, mm = idx >> 4;
            int tt = m0 + mm;
            As[kk][mm] = (tt < TT) ? g_alpha[((size_t)b*TT + tt)*HW + k0 + kk] : 0.f;
        }
        for (int idx = tid; idx < 1024; idx += 256) {
            int i = idx & 63, kk = idx >> 6;
            int cc = n0 + i;
            Fs[kk][i] = (cc < CE) ? enc_feat[((size_t)b*CE + cc)*HW + k0 + kk] : 0.f;
        }
        __syncthreads();
#pragma unroll
        for (int kk = 0; kk < 16; kk++) {
            const u64* fp = (const u64*)&Fs[kk][tn];
            u64 f01 = fp[0], f23 = fp[1];
#pragma unroll
            for (int r = 0; r < 4; r++) {
                float av = As[kk][tm + r];
                u64 ad = pk2(av, av);
                acc2[r][0] = ffma2(ad, f01, acc2[r][0]);
                acc2[r][1] = ffma2(ad, f23, acc2[r][1]);
            }
        }
    }
#pragma unroll
    for (int r = 0; r < 4; r++) {
        int tt = m0 + tm + r;
        if (tt < TT) {
            float v0, v1, v2, v3;
            upk2(acc2[r][0], v0, v1);
            upk2(acc2[r][1], v2, v3);
            float vv[4] = {v0, v1, v2, v3};
#pragma unroll
            for (int c = 0; c < 4; c++) {
                int cc = n0 + tn + c;
                if (cc < CE) g_ctxall[((size_t)b*TT + tt)*CE + cc] = vv[c];
            }
        }
    }
}

// ---------------- final fc ----------------
__global__ void __launch_bounds__(256) fc_kernel(const float* __restrict__ fc_b,
                                                 float* __restrict__ out) {
    int m0 = blockIdx.x * 64;
    int n0 = blockIdx.y * 64;
    __shared__ float Is[16][66];
    __shared__ float Ws[16][64];
    int tid = threadIdx.x;
    int tm = (tid & 15)*4, tn = (tid >> 4)*4;
    float acc[4][4];
#pragma unroll
    for (int r = 0; r < 4; r++)
#pragma unroll
        for (int c = 0; c < 4; c++) acc[r][c] = 0.f;

    for (int k0 = 0; k0 < HID + CE; k0 += 16) {
        __syncthreads();
        const float* src; int stride, off;
        if (k0 < HID) { src = g_x1;     stride = HID; off = k0; }
        else          { src = g_ctxall; stride = CE;  off = k0 - HID; }
        for (int idx = tid; idx < 1024; idx += 256) {
            int kk = idx & 15, mm = idx >> 4;
            Is[kk][mm] = src[(m0 + mm)*stride + off + kk];
        }
        for (int idx = tid; idx < 1024; idx += 256) {
            int i = idx & 63, kk = idx >> 6;
            Ws[kk][i] = g_fcWT[(k0 + kk)*VV + n0 + i];
        }
        __syncthreads();
#pragma unroll
        for (int kk = 0; kk < 16; kk++) {
            float iv[4], wv[4];
#pragma unroll
            for (int r = 0; r < 4; r++) iv[r] = Is[kk][tm + r];
#pragma unroll
            for (int c = 0; c < 4; c++) wv[c] = Ws[kk][tn + c];
#pragma unroll
            for (int r = 0; r < 4; r++)
#pragma unroll
                for (int c = 0; c < 4; c++)
                    acc[r][c] = fmaf(iv[r], wv[c], acc[r][c]);
        }
    }
#pragma unroll
    for (int r = 0; r < 4; r++)
#pragma unroll
        for (int c = 0; c < 4; c++) {
            int n = n0 + tn + c;
            out[(m0 + tm + r)*VV + n] = acc[r][c] + fc_b[n];
        }
}

// ---------------- launch ----------------
extern "C" void kernel_launch(void* const* d_in, const int* in_sizes, int n_in,
                              void* d_out, int out_size) {
    const float* enc_feat = (const float*)d_in[0];
    const int*   tgt      = (const int*)  d_in[1];
    const float* embed    = (const float*)d_in[2];
    const float* w1       = (const float*)d_in[3];
    const float* b1       = (const float*)d_in[4];
    const float* w2       = (const float*)d_in[5];
    const float* b2       = (const float*)d_in[6];
    const float* w3       = (const float*)d_in[7];
    const float* b3       = (const float*)d_in[8];
    const float* W_enc    = (const float*)d_in[9];
    const float* b_enc    = (const float*)d_in[10];
    const float* W_h      = (const float*)d_in[11];
    const float* b_h      = (const float*)d_in[12];
    const float* W_cov    = (const float*)d_in[13];
    const float* b_cov    = (const float*)d_in[14];
    const float* v_attn   = (const float*)d_in[15];
    const float* fc_W     = (const float*)d_in[16];
    const float* fc_b     = (const float*)d_in[17];
    float* out = (float*)d_out;

    prep_kernel<<<3072, 256>>>(tgt, embed, w1, w2, w3, W_h, fc_W, W_cov);

    dim3 gglu(BB*3, 4);
    glu_kernel<<<gglu, 256>>>(0, 0, b1);   // g_x0 -> g_x1
    glu_kernel<<<gglu, 256>>>(1, 1, b2);   // g_x1 -> g_x0
    glu_kernel<<<gglu, 256>>>(0, 2, b3);   // g_x0 -> g_x1 (= hidd)

    encproj_kernel<<<dim3(BB, 4, 16), 256>>>(enc_feat, W_enc, b_enc);
    qgemm_kernel<<<dim3(48, 4), 256>>>(b_h, b_cov);

    scan_kernel<<<GRID, 128>>>(v_attn);

    ctxgemm_kernel<<<dim3(BB, 2, 7), 256>>>(enc_feat);
    fc_kernel<<<dim3(48, 4), 256>>>(fc_b, out);
}

// round 10
// speedup vs baseline: 1.7254x; 1.1470x over previous
#include <cuda_runtime.h>
#include <cuda_bf16.h>
#include <cuda_fp16.h>

#define BB   32
#define TT   96
#define HID  256
#define CE   400
#define VV   256
#define HH_  16
#define WW_  64
#define AA   256
#define HW   1024
#define NZ   8          // a-chunks
#define ACH  32         // a per chunk
#define GRID 512        // 32 b x 8 zc x 2 strips
#define NBLK_B 16       // blocks per batch
#define EPSTR 260       // padded row stride (words) for sEPh

// ---------------- device scratch ----------------
__device__ __align__(16) float g_x0[BB*TT*HID];
__device__ __align__(16) float g_x1[BB*TT*HID];
__device__ __align__(16) float g_wT1[3*256*512];
__device__ __align__(16) float g_wT2[3*256*512];
__device__ __align__(16) float g_wT3[3*256*512];
__device__ __align__(16) float g_WhT[HID*AA];
__device__ __align__(16) float g_fcWT[(HID+CE)*VV];
__device__ __align__(16) __half g_Wh[AA*32];          // plain f16 W_cov, taps 25..31 = 0
__device__ __align__(16) unsigned g_EPh[BB*NZ*2*8192]; // f16x2 EP, [slab][(a&31)*256 + px/2]
__device__ __align__(16) float g_QB[BB*TT*AA];        // q + b_h + b_cov
__device__ __align__(16) float g_epart[2*NZ*BB*HW];   // double-buffered partial e
__device__ __align__(16) float g_alpha[BB*TT*HW];
__device__ __align__(16) float g_ctxall[BB*TT*CE];

// per-batch barrier state (128B padded)
__device__ unsigned g_barC[BB*32];
__device__ unsigned g_barG[BB*32];

__device__ __forceinline__ float sigmoid_fast(float x) {
    return __fdividef(1.f, 1.f + __expf(-x));
}

// ---- packed helpers (sm_103a) ----
typedef unsigned long long u64;
__device__ __forceinline__ u64 pk2(float lo, float hi) {
    u64 d;
    asm("mov.b64 %0, {%1, %2};" : "=l"(d) : "r"(__float_as_uint(lo)), "r"(__float_as_uint(hi)));
    return d;
}
__device__ __forceinline__ void upk2(u64 v, float& lo, float& hi) {
    unsigned int a, b;
    asm("mov.b64 {%0, %1}, %2;" : "=r"(a), "=r"(b) : "l"(v));
    lo = __uint_as_float(a); hi = __uint_as_float(b);
}
__device__ __forceinline__ u64 ffma2(u64 a, u64 b, u64 c) {
    u64 d;
    asm("fma.rn.f32x2 %0, %1, %2, %3;" : "=l"(d) : "l"(a), "l"(b), "l"(c));
    return d;
}
__device__ __forceinline__ unsigned pk_h2(float lo, float hi) {
    unsigned d;
    asm("cvt.rn.f16x2.f32 %0, %1, %2;" : "=r"(d) : "f"(hi), "f"(lo));
    return d;
}
__device__ __forceinline__ unsigned tanh2_hw(unsigned s) {
    unsigned d; asm("tanh.approx.f16x2 %0, %1;" : "=r"(d) : "r"(s)); return d;
}
__device__ __forceinline__ unsigned hfma2(unsigned a, unsigned b, unsigned c) {
    unsigned d;
    asm("fma.rn.f16x2 %0, %1, %2, %3;" : "=r"(d) : "r"(a), "r"(b), "r"(c));
    return d;
}
__device__ __forceinline__ unsigned hadd2(unsigned a, unsigned b) {
    unsigned d;
    asm("add.rn.f16x2 %0, %1, %2;" : "=r"(d) : "r"(a), "r"(b));
    return d;
}
__device__ __forceinline__ void h2f2(unsigned h, float& lo, float& hi) {
    asm("{.reg .b16 l, hh; mov.b32 {l, hh}, %2; cvt.f32.f16 %0, l; cvt.f32.f16 %1, hh;}"
        : "=f"(lo), "=f"(hi) : "r"(h));
}
__device__ __forceinline__ void mma16816(float& c0, float& c1, float& c2, float& c3,
                                         unsigned a0, unsigned a1, unsigned a2, unsigned a3,
                                         unsigned b0, unsigned b1) {
    asm("mma.sync.aligned.m16n8k16.row.col.f32.f16.f16.f32 "
        "{%0,%1,%2,%3}, {%4,%5,%6,%7}, {%8,%9}, {%0,%1,%2,%3};"
        : "+f"(c0), "+f"(c1), "+f"(c2), "+f"(c3)
        : "r"(a0), "r"(a1), "r"(a2), "r"(a3), "r"(b0), "r"(b1));
}

// ---------------- prep ----------------
__global__ void __launch_bounds__(256) prep_kernel(const int* __restrict__ tgt,
                            const float* __restrict__ embed,
                            const float* __restrict__ w1,
                            const float* __restrict__ w2,
                            const float* __restrict__ w3,
                            const float* __restrict__ W_h,
                            const float* __restrict__ fc_W,
                            const float* __restrict__ W_cov) {
    int idx = blockIdx.x * 256 + threadIdx.x;
    if (idx < BB*TT*HID) {
        int bt = idx >> 8;
        g_x0[idx] = embed[tgt[bt]*HID + (idx & 255)];
    }
    if (idx < 512*256*3) {
        int o = idx / 768, rem = idx % 768, ic = rem / 3, k = rem % 3;
        int d = (k*256 + ic)*512 + o;
        g_wT1[d] = w1[idx];
        g_wT2[d] = w2[idx];
        g_wT3[d] = w3[idx];
    }
    if (idx < AA*HID) {
        int a = idx >> 8, h = idx & 255;
        g_WhT[h*AA + a] = W_h[idx];
    }
    if (idx < VV*(HID+CE)) {
        int v = idx / (HID+CE), j = idx % (HID+CE);
        g_fcWT[j*VV + v] = fc_W[idx];
    }
    if (idx < AA*32) {
        int a = idx >> 5, k = idx & 31;
        g_Wh[idx] = __float2half((k < 25) ? W_cov[a*25 + k] : 0.f);
    }
}

// ---------------- causal GLU layer (32t x 64h tiles) ----------------
__global__ void __launch_bounds__(256) glu_kernel(int src_sel, int layer,
                                                  const float* __restrict__ bias) {
    const float* xin  = src_sel ? g_x1 : g_x0;
    float*       xout = src_sel ? g_x0 : g_x1;
    const float* wT = (layer == 0) ? g_wT1 : (layer == 1) ? g_wT2 : g_wT3;

    int b  = blockIdx.x / 3;
    int t0 = (blockIdx.x % 3) * 32;
    int h0 = blockIdx.y * 64;
    __shared__ float As[34][17];
    __shared__ float Wa[3][16][64];
    __shared__ float Wg[3][16][64];
    int tid = threadIdx.x;
    int tr = (tid & 15) * 2;
    int tc = (tid >> 4) * 4;
    float aa[2][4], gg[2][4];
#pragma unroll
    for (int r = 0; r < 2; r++)
#pragma unroll
        for (int c = 0; c < 4; c++) { aa[r][c] = 0.f; gg[r][c] = 0.f; }

    for (int ic0 = 0; ic0 < 256; ic0 += 16) {
        __syncthreads();
        for (int idx = tid; idx < 34*16; idx += 256) {
            int r = idx >> 4, c = idx & 15;
            int tg = t0 - 2 + r;
            As[r][c] = (tg >= 0) ? xin[(b*TT + tg)*HID + ic0 + c] : 0.f;
        }
        for (int idx = tid; idx < 3072; idx += 256) {
            int k = idx >> 10, rem = idx & 1023, i = rem >> 6, j = rem & 63;
            const float* base = wT + (k*256 + ic0 + i)*512 + h0 + j;
            Wa[k][i][j] = base[0];
            Wg[k][i][j] = base[256];
        }
        __syncthreads();
#pragma unroll
        for (int k = 0; k < 3; k++) {
#pragma unroll
            for (int i = 0; i < 16; i++) {
                float x0 = As[tr + k][i];
                float x1 = As[tr + 1 + k][i];
#pragma unroll
                for (int c = 0; c < 4; c++) {
                    float wa = Wa[k][i][tc + c];
                    float wg = Wg[k][i][tc + c];
                    aa[0][c] = fmaf(x0, wa, aa[0][c]);
                    aa[1][c] = fmaf(x1, wa, aa[1][c]);
                    gg[0][c] = fmaf(x0, wg, gg[0][c]);
                    gg[1][c] = fmaf(x1, wg, gg[1][c]);
                }
            }
        }
    }
#pragma unroll
    for (int r = 0; r < 2; r++)
#pragma unroll
        for (int c = 0; c < 4; c++) {
            int t = t0 + tr + r, h = h0 + tc + c;
            float av = aa[r][c] + bias[h];
            float gv = gg[r][c] + bias[256 + h];
            xout[(b*TT + t)*HID + h] = av * sigmoid_fast(gv);
        }
}

// ---------------- enc_proj (f32x2 accum) -> f16 [a][px] layout ----------------
__global__ void __launch_bounds__(256) encproj_kernel(const float* __restrict__ enc_feat,
                                                      const float* __restrict__ W_enc,
                                                      const float* __restrict__ b_enc) {
    int b = blockIdx.x, a0 = blockIdx.y*64, p0 = blockIdx.z*64;
    __shared__ float Ws[16][66];
    __shared__ __align__(16) float Fs[16][64];
    int tid = threadIdx.x;
    int ta = (tid & 15)*4, tp = (tid >> 4)*4;
    u64 acc2[4][2];
#pragma unroll
    for (int r = 0; r < 4; r++) { acc2[r][0] = 0ull; acc2[r][1] = 0ull; }

    for (int c0 = 0; c0 < CE; c0 += 16) {
        __syncthreads();
        for (int idx = tid; idx < 1024; idx += 256) {
            int j = idx & 15, i = idx >> 4;
            Ws[j][i] = W_enc[(a0 + i)*CE + c0 + j];
        }
        for (int idx = tid; idx < 1024; idx += 256) {
            int i = idx & 63, j = idx >> 6;
            Fs[j][i] = enc_feat[((size_t)b*CE + c0 + j)*HW + p0 + i];
        }
        __syncthreads();
#pragma unroll
        for (int j = 0; j < 16; j++) {
            const u64* fp = (const u64*)&Fs[j][tp];
            u64 f01 = fp[0], f23 = fp[1];
#pragma unroll
            for (int r = 0; r < 4; r++) {
                float av = Ws[j][ta + r];
                u64 ad = pk2(av, av);
                acc2[r][0] = ffma2(ad, f01, acc2[r][0]);
                acc2[r][1] = ffma2(ad, f23, acc2[r][1]);
            }
        }
    }
    int p = p0 + tp;
    int slab_p = p >> 9;               // strip
    int pw = p & 511;
#pragma unroll
    for (int r = 0; r < 4; r++) {
        int a = a0 + ta + r;
        float be = b_enc[a];
        float v0, v1, v2, v3;
        upk2(acc2[r][0], v0, v1);
        upk2(acc2[r][1], v2, v3);
        int slab = (b*NZ + (a >> 5))*2 + slab_p;
        int w0 = slab*8192 + (a & 31)*256 + (pw >> 1);
        uint2 u;
        u.x = pk_h2(v0 + be, v1 + be);
        u.y = pk_h2(v2 + be, v3 + be);
        *(uint2*)&g_EPh[w0] = u;
    }
}

// ---------------- q precompute ----------------
__global__ void __launch_bounds__(256) qgemm_kernel(const float* __restrict__ b_h,
                                                    const float* __restrict__ b_cov) {
    int m0 = blockIdx.x * 64;
    int n0 = blockIdx.y * 64;
    __shared__ float Hs[16][66];
    __shared__ float Ws[16][64];
    int tid = threadIdx.x;
    int tm = (tid & 15)*4, tn = (tid >> 4)*4;
    float acc[4][4];
#pragma unroll
    for (int r = 0; r < 4; r++)
#pragma unroll
        for (int c = 0; c < 4; c++) acc[r][c] = 0.f;

    for (int k0 = 0; k0 < HID; k0 += 16) {
        __syncthreads();
        for (int idx = tid; idx < 1024; idx += 256) {
            int kk = idx & 15, m = idx >> 4;
            Hs[kk][m] = g_x1[(m0 + m)*HID + k0 + kk];
        }
        for (int idx = tid; idx < 1024; idx += 256) {
            int i = idx & 63, kk = idx >> 6;
            Ws[kk][i] = g_WhT[(k0 + kk)*AA + n0 + i];
        }
        __syncthreads();
#pragma unroll
        for (int kk = 0; kk < 16; kk++) {
            float hv[4], wv[4];
#pragma unroll
            for (int r = 0; r < 4; r++) hv[r] = Hs[kk][tm + r];
#pragma unroll
            for (int c = 0; c < 4; c++) wv[c] = Ws[kk][tn + c];
#pragma unroll
            for (int r = 0; r < 4; r++)
#pragma unroll
                for (int c = 0; c < 4; c++)
                    acc[r][c] = fmaf(hv[r], wv[c], acc[r][c]);
        }
    }
#pragma unroll
    for (int r = 0; r < 4; r++)
#pragma unroll
        for (int c = 0; c < 4; c++) {
            int n = n0 + tn + c;
            g_QB[(m0 + tm + r)*AA + n] = acc[r][c] + b_h[n] + b_cov[n];
        }
}

// ---------------- persistent scan: HMMA conv, f16x2 tanh, per-batch barrier ----------------
// bid = b*16 + zc*2 + strip
__global__ void __launch_bounds__(128, 4) scan_kernel(const float* __restrict__ v_attn) {
    int bid   = blockIdx.x;
    int b     = bid >> 4;
    int zc    = (bid >> 1) & 7;
    int strip = bid & 1;
    int a0    = zc * ACH;
    int r0    = strip * 8;

    __shared__ __align__(16) unsigned sEPh[32*EPSTR];  // f16x2 EP, padded rows (33.3KB)
    __shared__ float    sCov[12][68];                  // persistent cov halo patch
    __shared__ float    sE[HW];                        // exp(e - m) full image
    __shared__ unsigned sQh[ACH];                      // (q,q) f16x2
    __shared__ float    redm[4], reds[4];

    int tid = threadIdx.x, lane = tid & 31, warp = tid >> 5;
    int ln4 = lane & 3, lnr = lane >> 2;
    int wpx = warp * 128;

    // one-time fills: EP slab (remap 256->EPSTR row stride)
    {
        const uint4* src = (const uint4*)&g_EPh[((b*NZ + zc)*2 + strip)*8192];
        for (int i = tid; i < 2048; i += 128) {
            int a = i >> 6, w = (i & 63) * 4;
            *(uint4*)&sEPh[a*EPSTR + w] = src[i];
        }
    }
    for (int i = tid; i < 12*68; i += 128) ((float*)sCov)[i] = 0.f;

    // A-fragments (W_cov) in registers, constant over t
    unsigned af[2][2][4];
#pragma unroll
    for (int mt = 0; mt < 2; mt++)
#pragma unroll
        for (int kt = 0; kt < 2; kt++) {
            int rL = a0 + mt*16 + lnr, rH = rL + 8;
            int kc = kt*16 + ln4*2;
            af[mt][kt][0] = *(const unsigned*)&g_Wh[rL*32 + kc];
            af[mt][kt][1] = *(const unsigned*)&g_Wh[rH*32 + kc];
            af[mt][kt][2] = *(const unsigned*)&g_Wh[rL*32 + kc + 8];
            af[mt][kt][3] = *(const unsigned*)&g_Wh[rH*32 + kc + 8];
        }
    // v in registers (rows lnr + m*8)
    unsigned vreg[4];
#pragma unroll
    for (int m = 0; m < 4; m++) {
        float v = v_attn[a0 + lnr + m*8];
        vreg[m] = pk_h2(v, v);
    }
    // per-lane B-gather offsets (tap k fixed per lane position)
    int goff[8]; bool gval[8];
#pragma unroll
    for (int kt = 0; kt < 2; kt++)
#pragma unroll
        for (int pos = 0; pos < 4; pos++) {
            int j = kt*4 + pos;
            int k = kt*16 + ln4*2 + (pos & 1) + ((pos & 2) ? 8 : 0);
            gval[j] = (k < 25);
            goff[j] = ((k/5)*68 + (k%5));
        }

    for (int t = 0; t < TT; t++) {
        int ping = t & 1;
        if (tid < ACH) {
            float q = g_QB[(b*TT + t)*AA + a0 + tid];
            sQh[tid] = pk_h2(q, q);
        }
        __syncthreads();

        unsigned qreg[4];
#pragma unroll
        for (int m = 0; m < 4; m++) qreg[m] = sQh[lnr + m*8];

        // ---- energy: 16 n-tiles of 8 px ----
#pragma unroll 2
        for (int nt = 0; nt < 16; nt++) {
            int n0 = wpx + nt*8;
            int px = n0 + lnr;
            int py = px >> 6, pxx = px & 63;
            const float* cb = &sCov[py][pxx];
            float gv[8];
#pragma unroll
            for (int j = 0; j < 8; j++)
                gv[j] = gval[j] ? cb[goff[j]] : 0.f;
            unsigned b00 = pk_h2(gv[0], gv[1]), b01 = pk_h2(gv[2], gv[3]);
            unsigned b10 = pk_h2(gv[4], gv[5]), b11 = pk_h2(gv[6], gv[7]);
            int epc = (n0 >> 1) + ln4;

            unsigned eacc = 0u;
#pragma unroll
            for (int mt = 0; mt < 2; mt++) {
                float c0 = 0.f, c1 = 0.f, c2 = 0.f, c3 = 0.f;
                mma16816(c0, c1, c2, c3,
                         af[mt][0][0], af[mt][0][1], af[mt][0][2], af[mt][0][3], b00, b01);
                mma16816(c0, c1, c2, c3,
                         af[mt][1][0], af[mt][1][1], af[mt][1][2], af[mt][1][3], b10, b11);
                int rowL = mt*16 + lnr, rowH = rowL + 8;
                unsigned sL = pk_h2(c0, c1);
                sL = hadd2(sL, sEPh[rowL*EPSTR + epc]);
                sL = hadd2(sL, qreg[mt*2]);
                eacc = hfma2(tanh2_hw(sL), vreg[mt*2], eacc);
                unsigned sH = pk_h2(c2, c3);
                sH = hadd2(sH, sEPh[rowH*EPSTR + epc]);
                sH = hadd2(sH, qreg[mt*2 + 1]);
                eacc = hfma2(tanh2_hw(sH), vreg[mt*2 + 1], eacc);
            }
            eacc = hadd2(eacc, __shfl_xor_sync(~0u, eacc, 4));
            eacc = hadd2(eacc, __shfl_xor_sync(~0u, eacc, 8));
            eacc = hadd2(eacc, __shfl_xor_sync(~0u, eacc, 16));
            if (lane < 4) {
                float lo, hi;
                h2f2(eacc, lo, hi);
                int gp = strip*512 + n0 + lane*2;
                *(float2*)&g_epart[(size_t)ping*(NZ*BB*HW) + (zc*BB + b)*HW + gp] =
                    make_float2(lo, hi);
            }
        }

        // ---- per-batch barrier (16 arrivals) ----
        __threadfence();
        __syncthreads();
        if (tid == 0) {
            volatile unsigned* gp = &g_barG[b*32];
            unsigned gen = *gp;
            unsigned arrived = atomicAdd(&g_barC[b*32], 1u);
            if (arrived == NBLK_B - 1) {
                g_barC[b*32] = 0;
                __threadfence();
                *gp = gen + 1;
            } else {
                int spins = 0;
                while (*gp == gen) { __nanosleep(64); if (++spins > (1 << 23)) break; }
            }
            __threadfence();
        }
        __syncthreads();

        // ---- phase2 (redundant per block): softmax + cov halo + alpha ----
        float e8[8];
        {
            float4 s0v = make_float4(0.f,0.f,0.f,0.f);
            float4 s1v = make_float4(0.f,0.f,0.f,0.f);
            const float* base = g_epart + (size_t)ping*(NZ*BB*HW) + b*HW + tid*8;
#pragma unroll
            for (int z = 0; z < NZ; z++) {
                const float4* p4 = (const float4*)(base + (size_t)z*BB*HW);
                float4 q0 = __ldcg(p4);
                float4 q1 = __ldcg(p4 + 1);
                s0v.x += q0.x; s0v.y += q0.y; s0v.z += q0.z; s0v.w += q0.w;
                s1v.x += q1.x; s1v.y += q1.y; s1v.z += q1.z; s1v.w += q1.w;
            }
            e8[0]=s0v.x; e8[1]=s0v.y; e8[2]=s0v.z; e8[3]=s0v.w;
            e8[4]=s1v.x; e8[5]=s1v.y; e8[6]=s1v.z; e8[7]=s1v.w;
        }
        float m = e8[0];
#pragma unroll
        for (int j = 1; j < 8; j++) m = fmaxf(m, e8[j]);
#pragma unroll
        for (int o = 16; o; o >>= 1) m = fmaxf(m, __shfl_xor_sync(~0u, m, o));
        if (lane == 0) redm[warp] = m;
        __syncthreads();
        m = fmaxf(fmaxf(redm[0], redm[1]), fmaxf(redm[2], redm[3]));

        float ex8[8], sl = 0.f;
#pragma unroll
        for (int j = 0; j < 8; j++) { ex8[j] = __expf(e8[j] - m); sl += ex8[j]; }
        ((float4*)sE)[tid*2]     = make_float4(ex8[0], ex8[1], ex8[2], ex8[3]);
        ((float4*)sE)[tid*2 + 1] = make_float4(ex8[4], ex8[5], ex8[6], ex8[7]);
#pragma unroll
        for (int o = 16; o; o >>= 1) sl += __shfl_xor_sync(~0u, sl, o);
        if (lane == 0) reds[warp] = sl;
        __syncthreads();
        float s = (reds[0] + reds[1]) + (reds[2] + reds[3]);
        float inv = __fdividef(1.f, s);

        // cov halo update (single writer per element)
        for (int h = tid; h < 12*64; h += 128) {
            int hr = h >> 6, cc = h & 63;
            int imrow = r0 - 2 + hr;
            if ((unsigned)imrow < HH_)
                sCov[hr][cc + 2] += sE[imrow*WW_ + cc] * inv;
        }
        // one block per batch stores full alpha image for ctx GEMM
        if (zc == 0 && strip == 0) {
            float4* ap = (float4*)(g_alpha + ((size_t)b*TT + t)*HW) + tid*2;
            ap[0] = make_float4(ex8[0]*inv, ex8[1]*inv, ex8[2]*inv, ex8[3]*inv);
            ap[1] = make_float4(ex8[4]*inv, ex8[5]*inv, ex8[6]*inv, ex8[7]*inv);
        }
        __syncthreads();
    }
}

// ---------------- batched ctx GEMM (f32x2) ----------------
__global__ void __launch_bounds__(256) ctxgemm_kernel(const float* __restrict__ enc_feat) {
    int b  = blockIdx.x;
    int m0 = blockIdx.y * 64;
    int n0 = blockIdx.z * 64;
    __shared__ float As[16][66];
    __shared__ __align__(16) float Fs[16][64];
    int tid = threadIdx.x;
    int tm = (tid & 15)*4, tn = (tid >> 4)*4;
    u64 acc2[4][2];
#pragma unroll
    for (int r = 0; r < 4; r++) { acc2[r][0] = 0ull; acc2[r][1] = 0ull; }

    for (int k0 = 0; k0 < HW; k0 += 16) {
        __syncthreads();
        for (int idx = tid; idx < 1024; idx += 256) {
            int kk = idx & 15, mm = idx >> 4;
            int tt = m0 + mm;
            As[kk][mm] = (tt < TT) ? g_alpha[((size_t)b*TT + tt)*HW + k0 + kk] : 0.f;
        }
        for (int idx = tid; idx < 1024; idx += 256) {
            int i = idx & 63, kk = idx >> 6;
            int cc = n0 + i;
            Fs[kk][i] = (cc < CE) ? enc_feat[((size_t)b*CE + cc)*HW + k0 + kk] : 0.f;
        }
        __syncthreads();
#pragma unroll
        for (int kk = 0; kk < 16; kk++) {
            const u64* fp = (const u64*)&Fs[kk][tn];
            u64 f01 = fp[0], f23 = fp[1];
#pragma unroll
            for (int r = 0; r < 4; r++) {
                float av = As[kk][tm + r];
                u64 ad = pk2(av, av);
                acc2[r][0] = ffma2(ad, f01, acc2[r][0]);
                acc2[r][1] = ffma2(ad, f23, acc2[r][1]);
            }
        }
    }
#pragma unroll
    for (int r = 0; r < 4; r++) {
        int tt = m0 + tm + r;
        if (tt < TT) {
            float v0, v1, v2, v3;
            upk2(acc2[r][0], v0, v1);
            upk2(acc2[r][1], v2, v3);
            float vv[4] = {v0, v1, v2, v3};
#pragma unroll
            for (int c = 0; c < 4; c++) {
                int cc = n0 + tn + c;
                if (cc < CE) g_ctxall[((size_t)b*TT + tt)*CE + cc] = vv[c];
            }
        }
    }
}

// ---------------- final fc ----------------
__global__ void __launch_bounds__(256) fc_kernel(const float* __restrict__ fc_b,
                                                 float* __restrict__ out) {
    int m0 = blockIdx.x * 64;
    int n0 = blockIdx.y * 64;
    __shared__ float Is[16][66];
    __shared__ float Ws[16][64];
    int tid = threadIdx.x;
    int tm = (tid & 15)*4, tn = (tid >> 4)*4;
    float acc[4][4];
#pragma unroll
    for (int r = 0; r < 4; r++)
#pragma unroll
        for (int c = 0; c < 4; c++) acc[r][c] = 0.f;

    for (int k0 = 0; k0 < HID + CE; k0 += 16) {
        __syncthreads();
        const float* src; int stride, off;
        if (k0 < HID) { src = g_x1;     stride = HID; off = k0; }
        else          { src = g_ctxall; stride = CE;  off = k0 - HID; }
        for (int idx = tid; idx < 1024; idx += 256) {
            int kk = idx & 15, mm = idx >> 4;
            Is[kk][mm] = src[(m0 + mm)*stride + off + kk];
        }
        for (int idx = tid; idx < 1024; idx += 256) {
            int i = idx & 63, kk = idx >> 6;
            Ws[kk][i] = g_fcWT[(k0 + kk)*VV + n0 + i];
        }
        __syncthreads();
#pragma unroll
        for (int kk = 0; kk < 16; kk++) {
            float iv[4], wv[4];
#pragma unroll
            for (int r = 0; r < 4; r++) iv[r] = Is[kk][tm + r];
#pragma unroll
            for (int c = 0; c < 4; c++) wv[c] = Ws[kk][tn + c];
#pragma unroll
            for (int r = 0; r < 4; r++)
#pragma unroll
                for (int c = 0; c < 4; c++)
                    acc[r][c] = fmaf(iv[r], wv[c], acc[r][c]);
        }
    }
#pragma unroll
    for (int r = 0; r < 4; r++)
#pragma unroll
        for (int c = 0; c < 4; c++) {
            int n = n0 + tn + c;
            out[(m0 + tm + r)*VV + n] = acc[r][c] + fc_b[n];
        }
}

// ---------------- launch ----------------
extern "C" void kernel_launch(void* const* d_in, const int* in_sizes, int n_in,
                              void* d_out, int out_size) {
    const float* enc_feat = (const float*)d_in[0];
    const int*   tgt      = (const int*)  d_in[1];
    const float* embed    = (const float*)d_in[2];
    const float* w1       = (const float*)d_in[3];
    const float* b1       = (const float*)d_in[4];
    const float* w2       = (const float*)d_in[5];
    const float* b2       = (const float*)d_in[6];
    const float* w3       = (const float*)d_in[7];
    const float* b3       = (const float*)d_in[8];
    const float* W_enc    = (const float*)d_in[9];
    const float* b_enc    = (const float*)d_in[10];
    const float* W_h      = (const float*)d_in[11];
    const float* b_h      = (const float*)d_in[12];
    const float* W_cov    = (const float*)d_in[13];
    const float* b_cov    = (const float*)d_in[14];
    const float* v_attn   = (const float*)d_in[15];
    const float* fc_W     = (const float*)d_in[16];
    const float* fc_b     = (const float*)d_in[17];
    float* out = (float*)d_out;

    prep_kernel<<<3072, 256>>>(tgt, embed, w1, w2, w3, W_h, fc_W, W_cov);

    dim3 gglu(BB*3, 4);
    glu_kernel<<<gglu, 256>>>(0, 0, b1);   // g_x0 -> g_x1
    glu_kernel<<<gglu, 256>>>(1, 1, b2);   // g_x1 -> g_x0
    glu_kernel<<<gglu, 256>>>(0, 2, b3);   // g_x0 -> g_x1 (= hidd)

    encproj_kernel<<<dim3(BB, 4, 16), 256>>>(enc_feat, W_enc, b_enc);
    qgemm_kernel<<<dim3(48, 4), 256>>>(b_h, b_cov);

    scan_kernel<<<GRID, 128>>>(v_attn);

    ctxgemm_kernel<<<dim3(BB, 2, 7), 256>>>(enc_feat);
    fc_kernel<<<dim3(48, 4), 256>>>(fc_b, out);
}

// round 11
// speedup vs baseline: 1.9457x; 1.1277x over previous
#include <cuda_runtime.h>
#include <cuda_bf16.h>
#include <cuda_fp16.h>

#define BB   32
#define TT   96
#define HID  256
#define CE   400
#define VV   256
#define HH_  16
#define WW_  64
#define AA   256
#define HW   1024
#define NZ   8          // a-chunks
#define ACH  32         // a per chunk
#define GRID 512        // 32 b x 8 zc x 2 strips
#define NBLK_B 16       // blocks per batch
#define EPSTR 260       // padded row stride (words) for sEPh

// ---------------- device scratch ----------------
__device__ __align__(16) float g_x0[BB*TT*HID];
__device__ __align__(16) float g_x1[BB*TT*HID];
__device__ __align__(16) float g_wT1[3*256*512];
__device__ __align__(16) float g_wT2[3*256*512];
__device__ __align__(16) float g_wT3[3*256*512];
__device__ __align__(16) float g_WhT[HID*AA];
__device__ __align__(16) float g_fcWT[(HID+CE)*VV];
__device__ __align__(16) __half g_Wh[AA*32];          // plain f16 W_cov, taps 25..31 = 0
__device__ __align__(16) unsigned g_EPh[BB*NZ*2*8192]; // f16x2 EP, [slab][(a&31)*256 + px/2]
__device__ __align__(16) float g_QB[BB*TT*AA];        // q + b_h + b_cov
__device__ __align__(16) float g_epart[2*NZ*BB*HW];   // double-buffered partial e
__device__ __align__(16) float g_alpha[BB*TT*HW];
__device__ __align__(16) float g_ctxall[BB*TT*CE];

// per-batch barrier state (128B padded)
__device__ unsigned g_barC[BB*32];
__device__ unsigned g_barG[BB*32];

__device__ __forceinline__ float sigmoid_fast(float x) {
    return __fdividef(1.f, 1.f + __expf(-x));
}

// ---- packed helpers (sm_103a) ----
typedef unsigned long long u64;
__device__ __forceinline__ u64 pk2(float lo, float hi) {
    u64 d;
    asm("mov.b64 %0, {%1, %2};" : "=l"(d) : "r"(__float_as_uint(lo)), "r"(__float_as_uint(hi)));
    return d;
}
__device__ __forceinline__ void upk2(u64 v, float& lo, float& hi) {
    unsigned int a, b;
    asm("mov.b64 {%0, %1}, %2;" : "=r"(a), "=r"(b) : "l"(v));
    lo = __uint_as_float(a); hi = __uint_as_float(b);
}
__device__ __forceinline__ u64 ffma2(u64 a, u64 b, u64 c) {
    u64 d;
    asm("fma.rn.f32x2 %0, %1, %2, %3;" : "=l"(d) : "l"(a), "l"(b), "l"(c));
    return d;
}
__device__ __forceinline__ unsigned pk_h2(float lo, float hi) {
    unsigned d;
    asm("cvt.rn.f16x2.f32 %0, %1, %2;" : "=r"(d) : "f"(hi), "f"(lo));
    return d;
}
__device__ __forceinline__ unsigned tanh2_hw(unsigned s) {
    unsigned d; asm("tanh.approx.f16x2 %0, %1;" : "=r"(d) : "r"(s)); return d;
}
__device__ __forceinline__ unsigned hfma2(unsigned a, unsigned b, unsigned c) {
    unsigned d;
    asm("fma.rn.f16x2 %0, %1, %2, %3;" : "=r"(d) : "r"(a), "r"(b), "r"(c));
    return d;
}
__device__ __forceinline__ unsigned hadd2(unsigned a, unsigned b) {
    unsigned d;
    asm("add.rn.f16x2 %0, %1, %2;" : "=r"(d) : "r"(a), "r"(b));
    return d;
}
__device__ __forceinline__ void h2f2(unsigned h, float& lo, float& hi) {
    asm("{.reg .b16 l, hh; mov.b32 {l, hh}, %2; cvt.f32.f16 %0, l; cvt.f32.f16 %1, hh;}"
        : "=f"(lo), "=f"(hi) : "r"(h));
}
__device__ __forceinline__ void mma16816(float& c0, float& c1, float& c2, float& c3,
                                         unsigned a0, unsigned a1, unsigned a2, unsigned a3,
                                         unsigned b0, unsigned b1) {
    asm("mma.sync.aligned.m16n8k16.row.col.f32.f16.f16.f32 "
        "{%0,%1,%2,%3}, {%4,%5,%6,%7}, {%8,%9}, {%0,%1,%2,%3};"
        : "+f"(c0), "+f"(c1), "+f"(c2), "+f"(c3)
        : "r"(a0), "r"(a1), "r"(a2), "r"(a3), "r"(b0), "r"(b1));
}

// ---------------- prep ----------------
__global__ void __launch_bounds__(256) prep_kernel(const int* __restrict__ tgt,
                            const float* __restrict__ embed,
                            const float* __restrict__ w1,
                            const float* __restrict__ w2,
                            const float* __restrict__ w3,
                            const float* __restrict__ W_h,
                            const float* __restrict__ fc_W,
                            const float* __restrict__ W_cov) {
    int idx = blockIdx.x * 256 + threadIdx.x;
    if (idx < BB*TT*HID) {
        int bt = idx >> 8;
        g_x0[idx] = embed[tgt[bt]*HID + (idx & 255)];
    }
    if (idx < 512*256*3) {
        int o = idx / 768, rem = idx % 768, ic = rem / 3, k = rem % 3;
        int d = (k*256 + ic)*512 + o;
        g_wT1[d] = w1[idx];
        g_wT2[d] = w2[idx];
        g_wT3[d] = w3[idx];
    }
    if (idx < AA*HID) {
        int a = idx >> 8, h = idx & 255;
        g_WhT[h*AA + a] = W_h[idx];
    }
    if (idx < VV*(HID+CE)) {
        int v = idx / (HID+CE), j = idx % (HID+CE);
        g_fcWT[j*VV + v] = fc_W[idx];
    }
    if (idx < AA*32) {
        int a = idx >> 5, k = idx & 31;
        g_Wh[idx] = __float2half((k < 25) ? W_cov[a*25 + k] : 0.f);
    }
}

// ---------------- causal GLU layer (32t x 64h tiles) ----------------
__global__ void __launch_bounds__(256) glu_kernel(int src_sel, int layer,
                                                  const float* __restrict__ bias) {
    const float* xin  = src_sel ? g_x1 : g_x0;
    float*       xout = src_sel ? g_x0 : g_x1;
    const float* wT = (layer == 0) ? g_wT1 : (layer == 1) ? g_wT2 : g_wT3;

    int b  = blockIdx.x / 3;
    int t0 = (blockIdx.x % 3) * 32;
    int h0 = blockIdx.y * 64;
    __shared__ float As[34][17];
    __shared__ float Wa[3][16][64];
    __shared__ float Wg[3][16][64];
    int tid = threadIdx.x;
    int tr = (tid & 15) * 2;
    int tc = (tid >> 4) * 4;
    float aa[2][4], gg[2][4];
#pragma unroll
    for (int r = 0; r < 2; r++)
#pragma unroll
        for (int c = 0; c < 4; c++) { aa[r][c] = 0.f; gg[r][c] = 0.f; }

    for (int ic0 = 0; ic0 < 256; ic0 += 16) {
        __syncthreads();
        for (int idx = tid; idx < 34*16; idx += 256) {
            int r = idx >> 4, c = idx & 15;
            int tg = t0 - 2 + r;
            As[r][c] = (tg >= 0) ? xin[(b*TT + tg)*HID + ic0 + c] : 0.f;
        }
        for (int idx = tid; idx < 3072; idx += 256) {
            int k = idx >> 10, rem = idx & 1023, i = rem >> 6, j = rem & 63;
            const float* base = wT + (k*256 + ic0 + i)*512 + h0 + j;
            Wa[k][i][j] = base[0];
            Wg[k][i][j] = base[256];
        }
        __syncthreads();
#pragma unroll
        for (int k = 0; k < 3; k++) {
#pragma unroll
            for (int i = 0; i < 16; i++) {
                float x0 = As[tr + k][i];
                float x1 = As[tr + 1 + k][i];
#pragma unroll
                for (int c = 0; c < 4; c++) {
                    float wa = Wa[k][i][tc + c];
                    float wg = Wg[k][i][tc + c];
                    aa[0][c] = fmaf(x0, wa, aa[0][c]);
                    aa[1][c] = fmaf(x1, wa, aa[1][c]);
                    gg[0][c] = fmaf(x0, wg, gg[0][c]);
                    gg[1][c] = fmaf(x1, wg, gg[1][c]);
                }
            }
        }
    }
#pragma unroll
    for (int r = 0; r < 2; r++)
#pragma unroll
        for (int c = 0; c < 4; c++) {
            int t = t0 + tr + r, h = h0 + tc + c;
            float av = aa[r][c] + bias[h];
            float gv = gg[r][c] + bias[256 + h];
            xout[(b*TT + t)*HID + h] = av * sigmoid_fast(gv);
        }
}

// ---------------- enc_proj: HMMA  EP[a,px] = W_enc @ enc_feat + b_enc -> f16 ----------------
// block: (b, a-tile of 64, px-tile of 64). 8 warps: warp -> (m = w>>1, n-half = (w&1)*4 tiles)
__global__ void __launch_bounds__(256) encproj_kernel(const float* __restrict__ enc_feat,
                                                      const float* __restrict__ W_enc,
                                                      const float* __restrict__ b_enc) {
    int b = blockIdx.x, a0 = blockIdx.y*64, p0 = blockIdx.z*64;
    __shared__ unsigned sWh[64][9];   // [a][kpair] f16x2 (k, k+1), padded
    __shared__ unsigned sFt[64][9];   // [px][kpair] f16x2 (k, k+1), padded
    int tid = threadIdx.x, lane = tid & 31, warp = tid >> 5;
    int ln4 = lane & 3, lnr = lane >> 2;
    int m  = warp >> 1;          // 0..3
    int nb = (warp & 1) * 4;     // n-tile base (each tile = 8 px)

    float acc[4][4];
#pragma unroll
    for (int nt = 0; nt < 4; nt++)
#pragma unroll
        for (int i = 0; i < 4; i++) acc[nt][i] = 0.f;

    for (int ks = 0; ks < 25; ks++) {
        int c0 = ks*16;
        __syncthreads();
        // fill W tile: 512 words (64a x 8 kpairs)
#pragma unroll
        for (int rep = 0; rep < 2; rep++) {
            int w = tid + rep*256;
            int a = w >> 3, kp = w & 7;
            float2 wv = *(const float2*)&W_enc[(a0 + a)*CE + c0 + kp*2];
            sWh[a][kp] = pk_h2(wv.x, wv.y);
        }
        // fill F tile (k-transposed): 512 words (64px x 8 kpairs)
#pragma unroll
        for (int rep = 0; rep < 2; rep++) {
            int w = tid + rep*256;
            int px = w & 63, kp = w >> 6;
            float f0 = enc_feat[((size_t)b*CE + c0 + kp*2    )*HW + p0 + px];
            float f1 = enc_feat[((size_t)b*CE + c0 + kp*2 + 1)*HW + p0 + px];
            sFt[px][kp] = pk_h2(f0, f1);
        }
        __syncthreads();

        int rL = m*16 + lnr, rH = rL + 8;
        unsigned af0 = sWh[rL][ln4],     af1 = sWh[rH][ln4];
        unsigned af2 = sWh[rL][ln4 + 4], af3 = sWh[rH][ln4 + 4];
#pragma unroll
        for (int nt = 0; nt < 4; nt++) {
            int pxr = (nb + nt)*8 + lnr;
            unsigned b0 = sFt[pxr][ln4], b1 = sFt[pxr][ln4 + 4];
            mma16816(acc[nt][0], acc[nt][1], acc[nt][2], acc[nt][3],
                     af0, af1, af2, af3, b0, b1);
        }
    }

    // epilogue: rows aL/aH, cols pxc = p0 + (nb+nt)*8 + ln4*2 (+1)
    int aL = a0 + m*16 + lnr, aH = aL + 8;
    float beL = b_enc[aL], beH = b_enc[aH];
    int slab_p = p0 >> 9;
#pragma unroll
    for (int nt = 0; nt < 4; nt++) {
        int pxc = p0 + (nb + nt)*8 + ln4*2;
        int wofs = ((pxc & 511) >> 1);
        {
            int slab = (b*NZ + (aL >> 5))*2 + slab_p;
            g_EPh[slab*8192 + (aL & 31)*256 + wofs] = pk_h2(acc[nt][0] + beL, acc[nt][1] + beL);
        }
        {
            int slab = (b*NZ + (aH >> 5))*2 + slab_p;
            g_EPh[slab*8192 + (aH & 31)*256 + wofs] = pk_h2(acc[nt][2] + beH, acc[nt][3] + beH);
        }
    }
}

// ---------------- q precompute ----------------
__global__ void __launch_bounds__(256) qgemm_kernel(const float* __restrict__ b_h,
                                                    const float* __restrict__ b_cov) {
    int m0 = blockIdx.x * 64;
    int n0 = blockIdx.y * 64;
    __shared__ float Hs[16][66];
    __shared__ float Ws[16][64];
    int tid = threadIdx.x;
    int tm = (tid & 15)*4, tn = (tid >> 4)*4;
    float acc[4][4];
#pragma unroll
    for (int r = 0; r < 4; r++)
#pragma unroll
        for (int c = 0; c < 4; c++) acc[r][c] = 0.f;

    for (int k0 = 0; k0 < HID; k0 += 16) {
        __syncthreads();
        for (int idx = tid; idx < 1024; idx += 256) {
            int kk = idx & 15, m = idx >> 4;
            Hs[kk][m] = g_x1[(m0 + m)*HID + k0 + kk];
        }
        for (int idx = tid; idx < 1024; idx += 256) {
            int i = idx & 63, kk = idx >> 6;
            Ws[kk][i] = g_WhT[(k0 + kk)*AA + n0 + i];
        }
        __syncthreads();
#pragma unroll
        for (int kk = 0; kk < 16; kk++) {
            float hv[4], wv[4];
#pragma unroll
            for (int r = 0; r < 4; r++) hv[r] = Hs[kk][tm + r];
#pragma unroll
            for (int c = 0; c < 4; c++) wv[c] = Ws[kk][tn + c];
#pragma unroll
            for (int r = 0; r < 4; r++)
#pragma unroll
                for (int c = 0; c < 4; c++)
                    acc[r][c] = fmaf(hv[r], wv[c], acc[r][c]);
        }
    }
#pragma unroll
    for (int r = 0; r < 4; r++)
#pragma unroll
        for (int c = 0; c < 4; c++) {
            int n = n0 + tn + c;
            g_QB[(m0 + tm + r)*AA + n] = acc[r][c] + b_h[n] + b_cov[n];
        }
}

// ---------------- persistent scan: HMMA conv, f16x2 tanh, per-batch barrier ----------------
// bid = b*16 + zc*2 + strip
__global__ void __launch_bounds__(128, 4) scan_kernel(const float* __restrict__ v_attn) {
    int bid   = blockIdx.x;
    int b     = bid >> 4;
    int zc    = (bid >> 1) & 7;
    int strip = bid & 1;
    int a0    = zc * ACH;
    int r0    = strip * 8;

    __shared__ __align__(16) unsigned sEPh[32*EPSTR];  // f16x2 EP, padded rows
    __shared__ float    sCov[12][68];                  // persistent cov halo patch
    __shared__ float    sE[HW];                        // exp(e) full image
    __shared__ unsigned sQh[ACH];                      // (q,q) f16x2
    __shared__ float    reds[4];

    int tid = threadIdx.x, lane = tid & 31, warp = tid >> 5;
    int ln4 = lane & 3, lnr = lane >> 2;
    int wpx = warp * 128;

    // one-time fills: EP slab (remap 256->EPSTR row stride)
    {
        const uint4* src = (const uint4*)&g_EPh[((b*NZ + zc)*2 + strip)*8192];
        for (int i = tid; i < 2048; i += 128) {
            int a = i >> 6, w = (i & 63) * 4;
            *(uint4*)&sEPh[a*EPSTR + w] = src[i];
        }
    }
    for (int i = tid; i < 12*68; i += 128) ((float*)sCov)[i] = 0.f;

    // A-fragments (W_cov) in registers, constant over t
    unsigned af[2][2][4];
#pragma unroll
    for (int mt = 0; mt < 2; mt++)
#pragma unroll
        for (int kt = 0; kt < 2; kt++) {
            int rL = a0 + mt*16 + lnr, rH = rL + 8;
            int kc = kt*16 + ln4*2;
            af[mt][kt][0] = *(const unsigned*)&g_Wh[rL*32 + kc];
            af[mt][kt][1] = *(const unsigned*)&g_Wh[rH*32 + kc];
            af[mt][kt][2] = *(const unsigned*)&g_Wh[rL*32 + kc + 8];
            af[mt][kt][3] = *(const unsigned*)&g_Wh[rH*32 + kc + 8];
        }
    // v in registers (rows lnr + m*8)
    unsigned vreg[4];
#pragma unroll
    for (int m = 0; m < 4; m++) {
        float v = v_attn[a0 + lnr + m*8];
        vreg[m] = pk_h2(v, v);
    }
    // per-lane B-gather offsets (tap k fixed per lane position)
    int goff[8]; bool gval[8];
#pragma unroll
    for (int kt = 0; kt < 2; kt++)
#pragma unroll
        for (int pos = 0; pos < 4; pos++) {
            int j = kt*4 + pos;
            int k = kt*16 + ln4*2 + (pos & 1) + ((pos & 2) ? 8 : 0);
            gval[j] = (k < 25);
            goff[j] = ((k/5)*68 + (k%5));
        }

    for (int t = 0; t < TT; t++) {
        int ping = t & 1;
        if (tid < ACH) {
            float q = g_QB[(b*TT + t)*AA + a0 + tid];
            sQh[tid] = pk_h2(q, q);
        }
        __syncthreads();

        unsigned qreg[4];
#pragma unroll
        for (int m = 0; m < 4; m++) qreg[m] = sQh[lnr + m*8];

        // ---- energy: 16 n-tiles of 8 px ----
#pragma unroll 2
        for (int nt = 0; nt < 16; nt++) {
            int n0 = wpx + nt*8;
            int px = n0 + lnr;
            int py = px >> 6, pxx = px & 63;
            const float* cb = &sCov[py][pxx];
            float gv[8];
#pragma unroll
            for (int j = 0; j < 8; j++)
                gv[j] = gval[j] ? cb[goff[j]] : 0.f;
            unsigned b00 = pk_h2(gv[0], gv[1]), b01 = pk_h2(gv[2], gv[3]);
            unsigned b10 = pk_h2(gv[4], gv[5]), b11 = pk_h2(gv[6], gv[7]);
            int epc = (n0 >> 1) + ln4;

            unsigned eacc = 0u;
#pragma unroll
            for (int mt = 0; mt < 2; mt++) {
                float c0 = 0.f, c1 = 0.f, c2 = 0.f, c3 = 0.f;
                mma16816(c0, c1, c2, c3,
                         af[mt][0][0], af[mt][0][1], af[mt][0][2], af[mt][0][3], b00, b01);
                mma16816(c0, c1, c2, c3,
                         af[mt][1][0], af[mt][1][1], af[mt][1][2], af[mt][1][3], b10, b11);
                int rowL = mt*16 + lnr, rowH = rowL + 8;
                unsigned sL = pk_h2(c0, c1);
                sL = hadd2(sL, sEPh[rowL*EPSTR + epc]);
                sL = hadd2(sL, qreg[mt*2]);
                eacc = hfma2(tanh2_hw(sL), vreg[mt*2], eacc);
                unsigned sH = pk_h2(c2, c3);
                sH = hadd2(sH, sEPh[rowH*EPSTR + epc]);
                sH = hadd2(sH, qreg[mt*2 + 1]);
                eacc = hfma2(tanh2_hw(sH), vreg[mt*2 + 1], eacc);
            }
            eacc = hadd2(eacc, __shfl_xor_sync(~0u, eacc, 4));
            eacc = hadd2(eacc, __shfl_xor_sync(~0u, eacc, 8));
            eacc = hadd2(eacc, __shfl_xor_sync(~0u, eacc, 16));
            if (lane < 4) {
                float lo, hi;
                h2f2(eacc, lo, hi);
                int gp = strip*512 + n0 + lane*2;
                *(float2*)&g_epart[(size_t)ping*(NZ*BB*HW) + (zc*BB + b)*HW + gp] =
                    make_float2(lo, hi);
            }
        }

        // ---- per-batch barrier (16 arrivals) ----
        __threadfence();
        __syncthreads();
        if (tid == 0) {
            volatile unsigned* gp = &g_barG[b*32];
            unsigned gen = *gp;
            unsigned arrived = atomicAdd(&g_barC[b*32], 1u);
            if (arrived == NBLK_B - 1) {
                g_barC[b*32] = 0;
                __threadfence();
                *gp = gen + 1;
            } else {
                int spins = 0;
                while (*gp == gen) { __nanosleep(64); if (++spins > (1 << 23)) break; }
            }
            __threadfence();
        }
        __syncthreads();

        // ---- phase2 (redundant per block): softmax (no max pass; |e|<=4) + cov + alpha ----
        float e8[8];
        {
            float4 s0v = make_float4(0.f,0.f,0.f,0.f);
            float4 s1v = make_float4(0.f,0.f,0.f,0.f);
            const float* base = g_epart + (size_t)ping*(NZ*BB*HW) + b*HW + tid*8;
#pragma unroll
            for (int z = 0; z < NZ; z++) {
                const float4* p4 = (const float4*)(base + (size_t)z*BB*HW);
                float4 q0 = __ldcg(p4);
                float4 q1 = __ldcg(p4 + 1);
                s0v.x += q0.x; s0v.y += q0.y; s0v.z += q0.z; s0v.w += q0.w;
                s1v.x += q1.x; s1v.y += q1.y; s1v.z += q1.z; s1v.w += q1.w;
            }
            e8[0]=s0v.x; e8[1]=s0v.y; e8[2]=s0v.z; e8[3]=s0v.w;
            e8[4]=s1v.x; e8[5]=s1v.y; e8[6]=s1v.z; e8[7]=s1v.w;
        }
        float ex8[8], sl = 0.f;
#pragma unroll
        for (int j = 0; j < 8; j++) { ex8[j] = __expf(e8[j]); sl += ex8[j]; }
        ((float4*)sE)[tid*2]     = make_float4(ex8[0], ex8[1], ex8[2], ex8[3]);
        ((float4*)sE)[tid*2 + 1] = make_float4(ex8[4], ex8[5], ex8[6], ex8[7]);
#pragma unroll
        for (int o = 16; o; o >>= 1) sl += __shfl_xor_sync(~0u, sl, o);
        if (lane == 0) reds[warp] = sl;
        __syncthreads();
        float s = (reds[0] + reds[1]) + (reds[2] + reds[3]);
        float inv = __fdividef(1.f, s);

        // cov halo update (single writer per element)
        for (int h = tid; h < 12*64; h += 128) {
            int hr = h >> 6, cc = h & 63;
            int imrow = r0 - 2 + hr;
            if ((unsigned)imrow < HH_)
                sCov[hr][cc + 2] += sE[imrow*WW_ + cc] * inv;
        }
        // one block per batch stores full alpha image for ctx GEMM
        if (zc == 0 && strip == 0) {
            float4* ap = (float4*)(g_alpha + ((size_t)b*TT + t)*HW) + tid*2;
            ap[0] = make_float4(ex8[0]*inv, ex8[1]*inv, ex8[2]*inv, ex8[3]*inv);
            ap[1] = make_float4(ex8[4]*inv, ex8[5]*inv, ex8[6]*inv, ex8[7]*inv);
        }
        __syncthreads();
    }
}

// ---------------- batched ctx GEMM (f32x2) ----------------
__global__ void __launch_bounds__(256) ctxgemm_kernel(const float* __restrict__ enc_feat) {
    int b  = blockIdx.x;
    int m0 = blockIdx.y * 64;
    int n0 = blockIdx.z * 64;
    __shared__ float As[16][66];
    __shared__ __align__(16) float Fs[16][64];
    int tid = threadIdx.x;
    int tm = (tid & 15)*4, tn = (tid >> 4)*4;
    u64 acc2[4][2];
#pragma unroll
    for (int r = 0; r < 4; r++) { acc2[r][0] = 0ull; acc2[r][1] = 0ull; }

    for (int k0 = 0; k0 < HW; k0 += 16) {
        __syncthreads();
        for (int idx = tid; idx < 1024; idx += 256) {
            int kk = idx & 15, mm = idx >> 4;
            int tt = m0 + mm;
            As[kk][mm] = (tt < TT) ? g_alpha[((size_t)b*TT + tt)*HW + k0 + kk] : 0.f;
        }
        for (int idx = tid; idx < 1024; idx += 256) {
            int i = idx & 63, kk = idx >> 6;
            int cc = n0 + i;
            Fs[kk][i] = (cc < CE) ? enc_feat[((size_t)b*CE + cc)*HW + k0 + kk] : 0.f;
        }
        __syncthreads();
#pragma unroll
        for (int kk = 0; kk < 16; kk++) {
            const u64* fp = (const u64*)&Fs[kk][tn];
            u64 f01 = fp[0], f23 = fp[1];
#pragma unroll
            for (int r = 0; r < 4; r++) {
                float av = As[kk][tm + r];
                u64 ad = pk2(av, av);
                acc2[r][0] = ffma2(ad, f01, acc2[r][0]);
                acc2[r][1] = ffma2(ad, f23, acc2[r][1]);
            }
        }
    }
#pragma unroll
    for (int r = 0; r < 4; r++) {
        int tt = m0 + tm + r;
        if (tt < TT) {
            float v0, v1, v2, v3;
            upk2(acc2[r][0], v0, v1);
            upk2(acc2[r][1], v2, v3);
            float vv[4] = {v0, v1, v2, v3};
#pragma unroll
            for (int c = 0; c < 4; c++) {
                int cc = n0 + tn + c;
                if (cc < CE) g_ctxall[((size_t)b*TT + tt)*CE + cc] = vv[c];
            }
        }
    }
}

// ---------------- final fc ----------------
__global__ void __launch_bounds__(256) fc_kernel(const float* __restrict__ fc_b,
                                                 float* __restrict__ out) {
    int m0 = blockIdx.x * 64;
    int n0 = blockIdx.y * 64;
    __shared__ float Is[16][66];
    __shared__ float Ws[16][64];
    int tid = threadIdx.x;
    int tm = (tid & 15)*4, tn = (tid >> 4)*4;
    float acc[4][4];
#pragma unroll
    for (int r = 0; r < 4; r++)
#pragma unroll
        for (int c = 0; c < 4; c++) acc[r][c] = 0.f;

    for (int k0 = 0; k0 < HID + CE; k0 += 16) {
        __syncthreads();
        const float* src; int stride, off;
        if (k0 < HID) { src = g_x1;     stride = HID; off = k0; }
        else          { src = g_ctxall; stride = CE;  off = k0 - HID; }
        for (int idx = tid; idx < 1024; idx += 256) {
            int kk = idx & 15, mm = idx >> 4;
            Is[kk][mm] = src[(m0 + mm)*stride + off + kk];
        }
        for (int idx = tid; idx < 1024; idx += 256) {
            int i = idx & 63, kk = idx >> 6;
            Ws[kk][i] = g_fcWT[(k0 + kk)*VV + n0 + i];
        }
        __syncthreads();
#pragma unroll
        for (int kk = 0; kk < 16; kk++) {
            float iv[4], wv[4];
#pragma unroll
            for (int r = 0; r < 4; r++) iv[r] = Is[kk][tm + r];
#pragma unroll
            for (int c = 0; c < 4; c++) wv[c] = Ws[kk][tn + c];
#pragma unroll
            for (int r = 0; r < 4; r++)
#pragma unroll
                for (int c = 0; c < 4; c++)
                    acc[r][c] = fmaf(iv[r], wv[c], acc[r][c]);
        }
    }
#pragma unroll
    for (int r = 0; r < 4; r++)
#pragma unroll
        for (int c = 0; c < 4; c++) {
            int n = n0 + tn + c;
            out[(m0 + tm + r)*VV + n] = acc[r][c] + fc_b[n];
        }
}

// ---------------- launch ----------------
extern "C" void kernel_launch(void* const* d_in, const int* in_sizes, int n_in,
                              void* d_out, int out_size) {
    const float* enc_feat = (const float*)d_in[0];
    const int*   tgt      = (const int*)  d_in[1];
    const float* embed    = (const float*)d_in[2];
    const float* w1       = (const float*)d_in[3];
    const float* b1       = (const float*)d_in[4];
    const float* w2       = (const float*)d_in[5];
    const float* b2       = (const float*)d_in[6];
    const float* w3       = (const float*)d_in[7];
    const float* b3       = (const float*)d_in[8];
    const float* W_enc    = (const float*)d_in[9];
    const float* b_enc    = (const float*)d_in[10];
    const float* W_h      = (const float*)d_in[11];
    const float* b_h      = (const float*)d_in[12];
    const float* W_cov    = (const float*)d_in[13];
    const float* b_cov    = (const float*)d_in[14];
    const float* v_attn   = (const float*)d_in[15];
    const float* fc_W     = (const float*)d_in[16];
    const float* fc_b     = (const float*)d_in[17];
    float* out = (float*)d_out;

    prep_kernel<<<3072, 256>>>(tgt, embed, w1, w2, w3, W_h, fc_W, W_cov);

    dim3 gglu(BB*3, 4);
    glu_kernel<<<gglu, 256>>>(0, 0, b1);   // g_x0 -> g_x1
    glu_kernel<<<gglu, 256>>>(1, 1, b2);   // g_x1 -> g_x0
    glu_kernel<<<gglu, 256>>>(0, 2, b3);   // g_x0 -> g_x1 (= hidd)

    encproj_kernel<<<dim3(BB, 4, 16), 256>>>(enc_feat, W_enc, b_enc);
    qgemm_kernel<<<dim3(48, 4), 256>>>(b_h, b_cov);

    scan_kernel<<<GRID, 128>>>(v_attn);

    ctxgemm_kernel<<<dim3(BB, 2, 7), 256>>>(enc_feat);
    fc_kernel<<<dim3(48, 4), 256>>>(fc_b, out);
}

// round 12
// speedup vs baseline: 2.0878x; 1.0730x over previous
#include <cuda_runtime.h>
#include <cuda_bf16.h>
#include <cuda_fp16.h>

#define BB   32
#define TT   96
#define HID  256
#define CE   400
#define VV   256
#define HH_  16
#define WW_  64
#define AA   256
#define HW   1024
#define NZ   8          // a-chunks
#define ACH  32         // a per chunk
#define GRID 512        // 32 b x 8 zc x 2 strips
#define NBLK_B 16       // blocks per batch
#define EPSTR 260       // padded row stride (words) for sEPh

// ---------------- device scratch ----------------
__device__ __align__(16) float g_x0[BB*TT*HID];
__device__ __align__(16) float g_x1[BB*TT*HID];
__device__ __align__(16) __half g_wgh[3*512*768];     // f16 glu weights, [layer][o][k*256+ic]
__device__ __align__(16) float g_WhT[HID*AA];
__device__ __align__(16) float g_fcWT[(HID+CE)*VV];
__device__ __align__(16) __half g_Wh[AA*32];          // plain f16 W_cov, taps 25..31 = 0
__device__ __align__(16) unsigned g_EPh[BB*NZ*2*8192]; // f16x2 EP, [slab][(a&31)*256 + px/2]
__device__ __align__(16) float g_QB[BB*TT*AA];        // q + b_h + b_cov
__device__ __align__(16) float g_epart[2*NZ*BB*HW];   // double-buffered partial e
__device__ __align__(16) float g_alpha[BB*TT*HW];
__device__ __align__(16) float g_ctxall[BB*TT*CE];

// per-batch barrier state (128B padded)
__device__ unsigned g_barC[BB*32];
__device__ unsigned g_barG[BB*32];

__device__ __forceinline__ float sigmoid_fast(float x) {
    return __fdividef(1.f, 1.f + __expf(-x));
}

// ---- packed helpers (sm_103a) ----
typedef unsigned long long u64;
__device__ __forceinline__ u64 pk2(float lo, float hi) {
    u64 d;
    asm("mov.b64 %0, {%1, %2};" : "=l"(d) : "r"(__float_as_uint(lo)), "r"(__float_as_uint(hi)));
    return d;
}
__device__ __forceinline__ void upk2(u64 v, float& lo, float& hi) {
    unsigned int a, b;
    asm("mov.b64 {%0, %1}, %2;" : "=r"(a), "=r"(b) : "l"(v));
    lo = __uint_as_float(a); hi = __uint_as_float(b);
}
__device__ __forceinline__ u64 ffma2(u64 a, u64 b, u64 c) {
    u64 d;
    asm("fma.rn.f32x2 %0, %1, %2, %3;" : "=l"(d) : "l"(a), "l"(b), "l"(c));
    return d;
}
__device__ __forceinline__ unsigned pk_h2(float lo, float hi) {
    unsigned d;
    asm("cvt.rn.f16x2.f32 %0, %1, %2;" : "=r"(d) : "f"(hi), "f"(lo));
    return d;
}
__device__ __forceinline__ unsigned tanh2_hw(unsigned s) {
    unsigned d; asm("tanh.approx.f16x2 %0, %1;" : "=r"(d) : "r"(s)); return d;
}
__device__ __forceinline__ unsigned hfma2(unsigned a, unsigned b, unsigned c) {
    unsigned d;
    asm("fma.rn.f16x2 %0, %1, %2, %3;" : "=r"(d) : "r"(a), "r"(b), "r"(c));
    return d;
}
__device__ __forceinline__ unsigned hadd2(unsigned a, unsigned b) {
    unsigned d;
    asm("add.rn.f16x2 %0, %1, %2;" : "=r"(d) : "r"(a), "r"(b));
    return d;
}
__device__ __forceinline__ void h2f2(unsigned h, float& lo, float& hi) {
    asm("{.reg .b16 l, hh; mov.b32 {l, hh}, %2; cvt.f32.f16 %0, l; cvt.f32.f16 %1, hh;}"
        : "=f"(lo), "=f"(hi) : "r"(h));
}
__device__ __forceinline__ void mma16816(float& c0, float& c1, float& c2, float& c3,
                                         unsigned a0, unsigned a1, unsigned a2, unsigned a3,
                                         unsigned b0, unsigned b1) {
    asm("mma.sync.aligned.m16n8k16.row.col.f32.f16.f16.f32 "
        "{%0,%1,%2,%3}, {%4,%5,%6,%7}, {%8,%9}, {%0,%1,%2,%3};"
        : "+f"(c0), "+f"(c1), "+f"(c2), "+f"(c3)
        : "r"(a0), "r"(a1), "r"(a2), "r"(a3), "r"(b0), "r"(b1));
}

// ---------------- prep ----------------
__global__ void __launch_bounds__(256) prep_kernel(const int* __restrict__ tgt,
                            const float* __restrict__ embed,
                            const float* __restrict__ w1,
                            const float* __restrict__ w2,
                            const float* __restrict__ w3,
                            const float* __restrict__ W_h,
                            const float* __restrict__ fc_W,
                            const float* __restrict__ W_cov) {
    int idx = blockIdx.x * 256 + threadIdx.x;
    if (idx < BB*TT*HID) {
        int bt = idx >> 8;
        g_x0[idx] = embed[tgt[bt]*HID + (idx & 255)];
    }
    if (idx < 3*512*768) {
        int layer = idx / (512*768);
        int rem = idx % (512*768);
        int o = rem / 768, kk = rem % 768;
        int k = kk >> 8, ic = kk & 255;
        const float* w = (layer == 0) ? w1 : (layer == 1) ? w2 : w3;
        g_wgh[idx] = __float2half(w[o*768 + ic*3 + k]);
    }
    if (idx < AA*HID) {
        int a = idx >> 8, h = idx & 255;
        g_WhT[h*AA + a] = W_h[idx];
    }
    if (idx < VV*(HID+CE)) {
        int v = idx / (HID+CE), j = idx % (HID+CE);
        g_fcWT[j*VV + v] = fc_W[idx];
    }
    if (idx < AA*32) {
        int a = idx >> 5, k = idx & 31;
        g_Wh[idx] = __float2half((k < 25) ? W_cov[a*25 + k] : 0.f);
    }
}

// ---------------- causal GLU layer via HMMA ----------------
// block: (b, o-tile: 32 a-channels + 32 gates, t-half of 48). 8 warps.
__global__ void __launch_bounds__(256) glu_kernel(int src_sel, int layer,
                                                  const float* __restrict__ bias) {
    const float* xin  = src_sel ? g_x1 : g_x0;
    float*       xout = src_sel ? g_x0 : g_x1;
    const unsigned* wW = (const unsigned*)g_wgh + layer*(512*768/2);

    int b  = blockIdx.x;
    int o0 = blockIdx.y * 32;
    int t0 = blockIdx.z * 48;
    __shared__ unsigned sW[64][9];     // [local row][kpair]
    __shared__ unsigned sX[48][9];     // [t-local][kpair]
    __shared__ float    sY[64][51];    // pre-GLU y
    int tid = threadIdx.x, lane = tid & 31, warp = tid >> 5;
    int ln4 = lane & 3, lnr = lane >> 2;
    int mt = warp >> 1;               // 0..3 (rows mt*16..+15; 0,1 = a; 2,3 = gate)
    int nbase = (warp & 1) * 3;       // 3 n-tiles of 8 t per warp

    float acc[3][4];
#pragma unroll
    for (int nt = 0; nt < 3; nt++)
#pragma unroll
        for (int i = 0; i < 4; i++) acc[nt][i] = 0.f;

    for (int ks = 0; ks < 48; ks++) {
        int k = ks >> 4, ic0 = (ks & 15) * 16;
        __syncthreads();
        // W tile: 512 words; local row r<32 -> a channel o0+r, r>=32 -> gate 256+o0+(r-32)
#pragma unroll
        for (int rep = 0; rep < 2; rep++) {
            int w = tid + rep*256;
            int row = w >> 3, jp = w & 7;
            int wr = (row < 32) ? (o0 + row) : (256 + o0 + row - 32);
            sW[row][jp] = wW[wr*384 + ks*8 + jp];
        }
        // X tile (im2col, tap k fixed within step): 384 words
        for (int idx = tid; idx < 384; idx += 256) {
            int tl = idx >> 3, jp = idx & 7;
            int tg = t0 + tl - 2 + k;
            unsigned v = 0u;
            if (tg >= 0) {
                float2 f = *(const float2*)&xin[(b*TT + tg)*HID + ic0 + jp*2];
                v = pk_h2(f.x, f.y);
            }
            sX[tl][jp] = v;
        }
        __syncthreads();

        int rL = mt*16 + lnr, rH = rL + 8;
        unsigned a0 = sW[rL][ln4],     a1 = sW[rH][ln4];
        unsigned a2 = sW[rL][ln4 + 4], a3 = sW[rH][ln4 + 4];
#pragma unroll
        for (int nt = 0; nt < 3; nt++) {
            int tr = (nbase + nt)*8 + lnr;
            unsigned b0 = sX[tr][ln4], b1 = sX[tr][ln4 + 4];
            mma16816(acc[nt][0], acc[nt][1], acc[nt][2], acc[nt][3],
                     a0, a1, a2, a3, b0, b1);
        }
    }

    // stage pre-GLU y
    {
        int rL = mt*16 + lnr, rH = rL + 8;
#pragma unroll
        for (int nt = 0; nt < 3; nt++) {
            int tc = (nbase + nt)*8 + ln4*2;
            sY[rL][tc]     = acc[nt][0];
            sY[rL][tc + 1] = acc[nt][1];
            sY[rH][tc]     = acc[nt][2];
            sY[rH][tc + 1] = acc[nt][3];
        }
    }
    __syncthreads();
    // combine a * sigmoid(g), coalesced channel-major store
    for (int idx = tid; idx < 32*48; idx += 256) {
        int r = idx & 31, tl = idx >> 5;
        float av = sY[r][tl]      + bias[o0 + r];
        float gv = sY[r + 32][tl] + bias[256 + o0 + r];
        xout[(b*TT + t0 + tl)*HID + o0 + r] = av * sigmoid_fast(gv);
    }
}

// ---------------- enc_proj: HMMA  EP[a,px] = W_enc @ enc_feat + b_enc -> f16 ----------------
__global__ void __launch_bounds__(256) encproj_kernel(const float* __restrict__ enc_feat,
                                                      const float* __restrict__ W_enc,
                                                      const float* __restrict__ b_enc) {
    int b = blockIdx.x, a0 = blockIdx.y*64, p0 = blockIdx.z*64;
    __shared__ unsigned sWh[64][9];   // [a][kpair] f16x2 (k, k+1), padded
    __shared__ unsigned sFt[64][9];   // [px][kpair] f16x2 (k, k+1), padded
    int tid = threadIdx.x, lane = tid & 31, warp = tid >> 5;
    int ln4 = lane & 3, lnr = lane >> 2;
    int m  = warp >> 1;          // 0..3
    int nb = (warp & 1) * 4;     // n-tile base (each tile = 8 px)

    float acc[4][4];
#pragma unroll
    for (int nt = 0; nt < 4; nt++)
#pragma unroll
        for (int i = 0; i < 4; i++) acc[nt][i] = 0.f;

    for (int ks = 0; ks < 25; ks++) {
        int c0 = ks*16;
        __syncthreads();
#pragma unroll
        for (int rep = 0; rep < 2; rep++) {
            int w = tid + rep*256;
            int a = w >> 3, kp = w & 7;
            float2 wv = *(const float2*)&W_enc[(a0 + a)*CE + c0 + kp*2];
            sWh[a][kp] = pk_h2(wv.x, wv.y);
        }
#pragma unroll
        for (int rep = 0; rep < 2; rep++) {
            int w = tid + rep*256;
            int px = w & 63, kp = w >> 6;
            float f0 = enc_feat[((size_t)b*CE + c0 + kp*2    )*HW + p0 + px];
            float f1 = enc_feat[((size_t)b*CE + c0 + kp*2 + 1)*HW + p0 + px];
            sFt[px][kp] = pk_h2(f0, f1);
        }
        __syncthreads();

        int rL = m*16 + lnr, rH = rL + 8;
        unsigned af0 = sWh[rL][ln4],     af1 = sWh[rH][ln4];
        unsigned af2 = sWh[rL][ln4 + 4], af3 = sWh[rH][ln4 + 4];
#pragma unroll
        for (int nt = 0; nt < 4; nt++) {
            int pxr = (nb + nt)*8 + lnr;
            unsigned b0 = sFt[pxr][ln4], b1 = sFt[pxr][ln4 + 4];
            mma16816(acc[nt][0], acc[nt][1], acc[nt][2], acc[nt][3],
                     af0, af1, af2, af3, b0, b1);
        }
    }

    int aL = a0 + m*16 + lnr, aH = aL + 8;
    float beL = b_enc[aL], beH = b_enc[aH];
    int slab_p = p0 >> 9;
#pragma unroll
    for (int nt = 0; nt < 4; nt++) {
        int pxc = p0 + (nb + nt)*8 + ln4*2;
        int wofs = ((pxc & 511) >> 1);
        {
            int slab = (b*NZ + (aL >> 5))*2 + slab_p;
            g_EPh[slab*8192 + (aL & 31)*256 + wofs] = pk_h2(acc[nt][0] + beL, acc[nt][1] + beL);
        }
        {
            int slab = (b*NZ + (aH >> 5))*2 + slab_p;
            g_EPh[slab*8192 + (aH & 31)*256 + wofs] = pk_h2(acc[nt][2] + beH, acc[nt][3] + beH);
        }
    }
}

// ---------------- q precompute ----------------
__global__ void __launch_bounds__(256) qgemm_kernel(const float* __restrict__ b_h,
                                                    const float* __restrict__ b_cov) {
    int m0 = blockIdx.x * 64;
    int n0 = blockIdx.y * 64;
    __shared__ float Hs[16][66];
    __shared__ float Ws[16][64];
    int tid = threadIdx.x;
    int tm = (tid & 15)*4, tn = (tid >> 4)*4;
    float acc[4][4];
#pragma unroll
    for (int r = 0; r < 4; r++)
#pragma unroll
        for (int c = 0; c < 4; c++) acc[r][c] = 0.f;

    for (int k0 = 0; k0 < HID; k0 += 16) {
        __syncthreads();
        for (int idx = tid; idx < 1024; idx += 256) {
            int kk = idx & 15, m = idx >> 4;
            Hs[kk][m] = g_x1[(m0 + m)*HID + k0 + kk];
        }
        for (int idx = tid; idx < 1024; idx += 256) {
            int i = idx & 63, kk = idx >> 6;
            Ws[kk][i] = g_WhT[(k0 + kk)*AA + n0 + i];
        }
        __syncthreads();
#pragma unroll
        for (int kk = 0; kk < 16; kk++) {
            float hv[4], wv[4];
#pragma unroll
            for (int r = 0; r < 4; r++) hv[r] = Hs[kk][tm + r];
#pragma unroll
            for (int c = 0; c < 4; c++) wv[c] = Ws[kk][tn + c];
#pragma unroll
            for (int r = 0; r < 4; r++)
#pragma unroll
                for (int c = 0; c < 4; c++)
                    acc[r][c] = fmaf(hv[r], wv[c], acc[r][c]);
        }
    }
#pragma unroll
    for (int r = 0; r < 4; r++)
#pragma unroll
        for (int c = 0; c < 4; c++) {
            int n = n0 + tn + c;
            g_QB[(m0 + tm + r)*AA + n] = acc[r][c] + b_h[n] + b_cov[n];
        }
}

// ---------------- persistent scan: HMMA conv, f16x2 tanh, per-batch barrier ----------------
// bid = b*16 + zc*2 + strip
__global__ void __launch_bounds__(128, 4) scan_kernel(const float* __restrict__ v_attn) {
    int bid   = blockIdx.x;
    int b     = bid >> 4;
    int zc    = (bid >> 1) & 7;
    int strip = bid & 1;
    int a0    = zc * ACH;
    int r0    = strip * 8;

    __shared__ __align__(16) unsigned sEPh[32*EPSTR];  // f16x2 EP, padded rows
    __shared__ float    sCov[12][68];                  // persistent cov halo patch
    __shared__ float    sE[HW];                        // exp(e) full image
    __shared__ unsigned sQh[ACH];                      // (q,q) f16x2
    __shared__ float    reds[4];

    int tid = threadIdx.x, lane = tid & 31, warp = tid >> 5;
    int ln4 = lane & 3, lnr = lane >> 2;
    int wpx = warp * 128;

    // one-time fills: EP slab (remap 256->EPSTR row stride)
    {
        const uint4* src = (const uint4*)&g_EPh[((b*NZ + zc)*2 + strip)*8192];
        for (int i = tid; i < 2048; i += 128) {
            int a = i >> 6, w = (i & 63) * 4;
            *(uint4*)&sEPh[a*EPSTR + w] = src[i];
        }
    }
    for (int i = tid; i < 12*68; i += 128) ((float*)sCov)[i] = 0.f;

    // A-fragments (W_cov) in registers, constant over t
    unsigned af[2][2][4];
#pragma unroll
    for (int mt = 0; mt < 2; mt++)
#pragma unroll
        for (int kt = 0; kt < 2; kt++) {
            int rL = a0 + mt*16 + lnr, rH = rL + 8;
            int kc = kt*16 + ln4*2;
            af[mt][kt][0] = *(const unsigned*)&g_Wh[rL*32 + kc];
            af[mt][kt][1] = *(const unsigned*)&g_Wh[rH*32 + kc];
            af[mt][kt][2] = *(const unsigned*)&g_Wh[rL*32 + kc + 8];
            af[mt][kt][3] = *(const unsigned*)&g_Wh[rH*32 + kc + 8];
        }
    unsigned vreg[4];
#pragma unroll
    for (int m = 0; m < 4; m++) {
        float v = v_attn[a0 + lnr + m*8];
        vreg[m] = pk_h2(v, v);
    }
    int goff[8]; bool gval[8];
#pragma unroll
    for (int kt = 0; kt < 2; kt++)
#pragma unroll
        for (int pos = 0; pos < 4; pos++) {
            int j = kt*4 + pos;
            int k = kt*16 + ln4*2 + (pos & 1) + ((pos & 2) ? 8 : 0);
            gval[j] = (k < 25);
            goff[j] = ((k/5)*68 + (k%5));
        }

    for (int t = 0; t < TT; t++) {
        int ping = t & 1;
        if (tid < ACH) {
            float q = g_QB[(b*TT + t)*AA + a0 + tid];
            sQh[tid] = pk_h2(q, q);
        }
        __syncthreads();

        unsigned qreg[4];
#pragma unroll
        for (int m = 0; m < 4; m++) qreg[m] = sQh[lnr + m*8];

        // ---- energy: 16 n-tiles of 8 px ----
#pragma unroll 2
        for (int nt = 0; nt < 16; nt++) {
            int n0 = wpx + nt*8;
            int px = n0 + lnr;
            int py = px >> 6, pxx = px & 63;
            const float* cb = &sCov[py][pxx];
            float gv[8];
#pragma unroll
            for (int j = 0; j < 8; j++)
                gv[j] = gval[j] ? cb[goff[j]] : 0.f;
            unsigned b00 = pk_h2(gv[0], gv[1]), b01 = pk_h2(gv[2], gv[3]);
            unsigned b10 = pk_h2(gv[4], gv[5]), b11 = pk_h2(gv[6], gv[7]);
            int epc = (n0 >> 1) + ln4;

            unsigned eacc = 0u;
#pragma unroll
            for (int mt = 0; mt < 2; mt++) {
                float c0 = 0.f, c1 = 0.f, c2 = 0.f, c3 = 0.f;
                mma16816(c0, c1, c2, c3,
                         af[mt][0][0], af[mt][0][1], af[mt][0][2], af[mt][0][3], b00, b01);
                mma16816(c0, c1, c2, c3,
                         af[mt][1][0], af[mt][1][1], af[mt][1][2], af[mt][1][3], b10, b11);
                int rowL = mt*16 + lnr, rowH = rowL + 8;
                unsigned sL = pk_h2(c0, c1);
                sL = hadd2(sL, sEPh[rowL*EPSTR + epc]);
                sL = hadd2(sL, qreg[mt*2]);
                eacc = hfma2(tanh2_hw(sL), vreg[mt*2], eacc);
                unsigned sH = pk_h2(c2, c3);
                sH = hadd2(sH, sEPh[rowH*EPSTR + epc]);
                sH = hadd2(sH, qreg[mt*2 + 1]);
                eacc = hfma2(tanh2_hw(sH), vreg[mt*2 + 1], eacc);
            }
            eacc = hadd2(eacc, __shfl_xor_sync(~0u, eacc, 4));
            eacc = hadd2(eacc, __shfl_xor_sync(~0u, eacc, 8));
            eacc = hadd2(eacc, __shfl_xor_sync(~0u, eacc, 16));
            if (lane < 4) {
                float lo, hi;
                h2f2(eacc, lo, hi);
                int gp = strip*512 + n0 + lane*2;
                *(float2*)&g_epart[(size_t)ping*(NZ*BB*HW) + (zc*BB + b)*HW + gp] =
                    make_float2(lo, hi);
            }
        }

        // ---- per-batch barrier (16 arrivals) ----
        __threadfence();
        __syncthreads();
        if (tid == 0) {
            volatile unsigned* gp = &g_barG[b*32];
            unsigned gen = *gp;
            unsigned arrived = atomicAdd(&g_barC[b*32], 1u);
            if (arrived == NBLK_B - 1) {
                g_barC[b*32] = 0;
                __threadfence();
                *gp = gen + 1;
            } else {
                int spins = 0;
                while (*gp == gen) { __nanosleep(64); if (++spins > (1 << 23)) break; }
            }
            __threadfence();
        }
        __syncthreads();

        // ---- phase2: softmax (no max pass; |e|<=4) + cov + alpha ----
        float e8[8];
        {
            float4 s0v = make_float4(0.f,0.f,0.f,0.f);
            float4 s1v = make_float4(0.f,0.f,0.f,0.f);
            const float* base = g_epart + (size_t)ping*(NZ*BB*HW) + b*HW + tid*8;
#pragma unroll
            for (int z = 0; z < NZ; z++) {
                const float4* p4 = (const float4*)(base + (size_t)z*BB*HW);
                float4 q0 = __ldcg(p4);
                float4 q1 = __ldcg(p4 + 1);
                s0v.x += q0.x; s0v.y += q0.y; s0v.z += q0.z; s0v.w += q0.w;
                s1v.x += q1.x; s1v.y += q1.y; s1v.z += q1.z; s1v.w += q1.w;
            }
            e8[0]=s0v.x; e8[1]=s0v.y; e8[2]=s0v.z; e8[3]=s0v.w;
            e8[4]=s1v.x; e8[5]=s1v.y; e8[6]=s1v.z; e8[7]=s1v.w;
        }
        float ex8[8], sl = 0.f;
#pragma unroll
        for (int j = 0; j < 8; j++) { ex8[j] = __expf(e8[j]); sl += ex8[j]; }
        ((float4*)sE)[tid*2]     = make_float4(ex8[0], ex8[1], ex8[2], ex8[3]);
        ((float4*)sE)[tid*2 + 1] = make_float4(ex8[4], ex8[5], ex8[6], ex8[7]);
#pragma unroll
        for (int o = 16; o; o >>= 1) sl += __shfl_xor_sync(~0u, sl, o);
        if (lane == 0) reds[warp] = sl;
        __syncthreads();
        float s = (reds[0] + reds[1]) + (reds[2] + reds[3]);
        float inv = __fdividef(1.f, s);

        for (int h = tid; h < 12*64; h += 128) {
            int hr = h >> 6, cc = h & 63;
            int imrow = r0 - 2 + hr;
            if ((unsigned)imrow < HH_)
                sCov[hr][cc + 2] += sE[imrow*WW_ + cc] * inv;
        }
        if (zc == 0 && strip == 0) {
            float4* ap = (float4*)(g_alpha + ((size_t)b*TT + t)*HW) + tid*2;
            ap[0] = make_float4(ex8[0]*inv, ex8[1]*inv, ex8[2]*inv, ex8[3]*inv);
            ap[1] = make_float4(ex8[4]*inv, ex8[5]*inv, ex8[6]*inv, ex8[7]*inv);
        }
        __syncthreads();
    }
}

// ---------------- batched ctx GEMM (f32x2) ----------------
__global__ void __launch_bounds__(256) ctxgemm_kernel(const float* __restrict__ enc_feat) {
    int b  = blockIdx.x;
    int m0 = blockIdx.y * 64;
    int n0 = blockIdx.z * 64;
    __shared__ float As[16][66];
    __shared__ __align__(16) float Fs[16][64];
    int tid = threadIdx.x;
    int tm = (tid & 15)*4, tn = (tid >> 4)*4;
    u64 acc2[4][2];
#pragma unroll
    for (int r = 0; r < 4; r++) { acc2[r][0] = 0ull; acc2[r][1] = 0ull; }

    for (int k0 = 0; k0 < HW; k0 += 16) {
        __syncthreads();
        for (int idx = tid; idx < 1024; idx += 256) {
            int kk = idx & 15, mm = idx >> 4;
            int tt = m0 + mm;
            As[kk][mm] = (tt < TT) ? g_alpha[((size_t)b*TT + tt)*HW + k0 + kk] : 0.f;
        }
        for (int idx = tid; idx < 1024; idx += 256) {
            int i = idx & 63, kk = idx >> 6;
            int cc = n0 + i;
            Fs[kk][i] = (cc < CE) ? enc_feat[((size_t)b*CE + cc)*HW + k0 + kk] : 0.f;
        }
        __syncthreads();
#pragma unroll
        for (int kk = 0; kk < 16; kk++) {
            const u64* fp = (const u64*)&Fs[kk][tn];
            u64 f01 = fp[0], f23 = fp[1];
#pragma unroll
            for (int r = 0; r < 4; r++) {
                float av = As[kk][tm + r];
                u64 ad = pk2(av, av);
                acc2[r][0] = ffma2(ad, f01, acc2[r][0]);
                acc2[r][1] = ffma2(ad, f23, acc2[r][1]);
            }
        }
    }
#pragma unroll
    for (int r = 0; r < 4; r++) {
        int tt = m0 + tm + r;
        if (tt < TT) {
            float v0, v1, v2, v3;
            upk2(acc2[r][0], v0, v1);
            upk2(acc2[r][1], v2, v3);
            float vv[4] = {v0, v1, v2, v3};
#pragma unroll
            for (int c = 0; c < 4; c++) {
                int cc = n0 + tn + c;
                if (cc < CE) g_ctxall[((size_t)b*TT + tt)*CE + cc] = vv[c];
            }
        }
    }
}

// ---------------- final fc ----------------
__global__ void __launch_bounds__(256) fc_kernel(const float* __restrict__ fc_b,
                                                 float* __restrict__ out) {
    int m0 = blockIdx.x * 64;
    int n0 = blockIdx.y * 64;
    __shared__ float Is[16][66];
    __shared__ float Ws[16][64];
    int tid = threadIdx.x;
    int tm = (tid & 15)*4, tn = (tid >> 4)*4;
    float acc[4][4];
#pragma unroll
    for (int r = 0; r < 4; r++)
#pragma unroll
        for (int c = 0; c < 4; c++) acc[r][c] = 0.f;

    for (int k0 = 0; k0 < HID + CE; k0 += 16) {
        __syncthreads();
        const float* src; int stride, off;
        if (k0 < HID) { src = g_x1;     stride = HID; off = k0; }
        else          { src = g_ctxall; stride = CE;  off = k0 - HID; }
        for (int idx = tid; idx < 1024; idx += 256) {
            int kk = idx & 15, mm = idx >> 4;
            Is[kk][mm] = src[(m0 + mm)*stride + off + kk];
        }
        for (int idx = tid; idx < 1024; idx += 256) {
            int i = idx & 63, kk = idx >> 6;
            Ws[kk][i] = g_fcWT[(k0 + kk)*VV + n0 + i];
        }
        __syncthreads();
#pragma unroll
        for (int kk = 0; kk < 16; kk++) {
            float iv[4], wv[4];
#pragma unroll
            for (int r = 0; r < 4; r++) iv[r] = Is[kk][tm + r];
#pragma unroll
            for (int c = 0; c < 4; c++) wv[c] = Ws[kk][tn + c];
#pragma unroll
            for (int r = 0; r < 4; r++)
#pragma unroll
                for (int c = 0; c < 4; c++)
                    acc[r][c] = fmaf(iv[r], wv[c], acc[r][c]);
        }
    }
#pragma unroll
    for (int r = 0; r < 4; r++)
#pragma unroll
        for (int c = 0; c < 4; c++) {
            int n = n0 + tn + c;
            out[(m0 + tm + r)*VV + n] = acc[r][c] + fc_b[n];
        }
}

// ---------------- launch ----------------
extern "C" void kernel_launch(void* const* d_in, const int* in_sizes, int n_in,
                              void* d_out, int out_size) {
    const float* enc_feat = (const float*)d_in[0];
    const int*   tgt      = (const int*)  d_in[1];
    const float* embed    = (const float*)d_in[2];
    const float* w1       = (const float*)d_in[3];
    const float* b1       = (const float*)d_in[4];
    const float* w2       = (const float*)d_in[5];
    const float* b2       = (const float*)d_in[6];
    const float* w3       = (const float*)d_in[7];
    const float* b3       = (const float*)d_in[8];
    const float* W_enc    = (const float*)d_in[9];
    const float* b_enc    = (const float*)d_in[10];
    const float* W_h      = (const float*)d_in[11];
    const float* b_h      = (const float*)d_in[12];
    const float* W_cov    = (const float*)d_in[13];
    const float* b_cov    = (const float*)d_in[14];
    const float* v_attn   = (const float*)d_in[15];
    const float* fc_W     = (const float*)d_in[16];
    const float* fc_b     = (const float*)d_in[17];
    float* out = (float*)d_out;

    prep_kernel<<<4608, 256>>>(tgt, embed, w1, w2, w3, W_h, fc_W, W_cov);

    dim3 gglu(BB, 8, 2);
    glu_kernel<<<gglu, 256>>>(0, 0, b1);   // g_x0 -> g_x1
    glu_kernel<<<gglu, 256>>>(1, 1, b2);   // g_x1 -> g_x0
    glu_kernel<<<gglu, 256>>>(0, 2, b3);   // g_x0 -> g_x1 (= hidd)

    encproj_kernel<<<dim3(BB, 4, 16), 256>>>(enc_feat, W_enc, b_enc);
    qgemm_kernel<<<dim3(48, 4), 256>>>(b_h, b_cov);

    scan_kernel<<<GRID, 128>>>(v_attn);

    ctxgemm_kernel<<<dim3(BB, 2, 7), 256>>>(enc_feat);
    fc_kernel<<<dim3(48, 4), 256>>>(fc_b, out);
}

// round 13
// speedup vs baseline: 2.6560x; 1.2722x over previous
#include <cuda_runtime.h>
#include <cuda_bf16.h>
#include <cuda_fp16.h>

#define BB   32
#define TT   96
#define HID  256
#define CE   400
#define VV   256
#define HH_  16
#define WW_  64
#define AA   256
#define HW   1024
#define NZ   8          // a-chunks
#define ACH  32         // a per chunk
#define GRID 512        // 32 b x 8 zc x 2 strips
#define NBLK_B 16       // blocks per batch
#define EPSTR 260       // padded row stride (words) for sEPh

// ---------------- device scratch ----------------
__device__ __align__(16) float g_x0[BB*TT*HID];
__device__ __align__(16) float g_x1[BB*TT*HID];
__device__ __align__(16) __half g_wgh[3*512*768];     // f16 glu weights, [layer][o][k*256+ic]
__device__ __align__(16) float g_WhT[HID*AA];
__device__ __align__(16) __half g_fcWh[VV*(HID+CE)];  // f16 fc weights row-major
__device__ __align__(16) __half g_Wh[AA*32];          // plain f16 W_cov, taps 25..31 = 0
__device__ __align__(16) unsigned g_EPh[BB*NZ*2*8192]; // f16x2 EP, [slab][(a&31)*256 + px/2]
__device__ __align__(16) float g_QB[BB*TT*AA];        // q + b_h + b_cov
__device__ __align__(16) float g_epart[2*NZ*BB*HW];   // double-buffered partial e
__device__ __align__(16) float g_alpha[BB*TT*HW];
__device__ __align__(16) float g_ctxall[BB*TT*CE];

// per-batch barrier state (128B padded)
__device__ unsigned g_barC[BB*32];
__device__ unsigned g_barG[BB*32];

__device__ __forceinline__ float sigmoid_fast(float x) {
    return __fdividef(1.f, 1.f + __expf(-x));
}

// ---- packed helpers (sm_103a) ----
typedef unsigned long long u64;
__device__ __forceinline__ unsigned pk_h2(float lo, float hi) {
    unsigned d;
    asm("cvt.rn.f16x2.f32 %0, %1, %2;" : "=r"(d) : "f"(hi), "f"(lo));
    return d;
}
__device__ __forceinline__ unsigned tanh2_hw(unsigned s) {
    unsigned d; asm("tanh.approx.f16x2 %0, %1;" : "=r"(d) : "r"(s)); return d;
}
__device__ __forceinline__ unsigned hfma2(unsigned a, unsigned b, unsigned c) {
    unsigned d;
    asm("fma.rn.f16x2 %0, %1, %2, %3;" : "=r"(d) : "r"(a), "r"(b), "r"(c));
    return d;
}
__device__ __forceinline__ unsigned hadd2(unsigned a, unsigned b) {
    unsigned d;
    asm("add.rn.f16x2 %0, %1, %2;" : "=r"(d) : "r"(a), "r"(b));
    return d;
}
__device__ __forceinline__ void h2f2(unsigned h, float& lo, float& hi) {
    asm("{.reg .b16 l, hh; mov.b32 {l, hh}, %2; cvt.f32.f16 %0, l; cvt.f32.f16 %1, hh;}"
        : "=f"(lo), "=f"(hi) : "r"(h));
}
__device__ __forceinline__ void mma16816(float& c0, float& c1, float& c2, float& c3,
                                         unsigned a0, unsigned a1, unsigned a2, unsigned a3,
                                         unsigned b0, unsigned b1) {
    asm("mma.sync.aligned.m16n8k16.row.col.f32.f16.f16.f32 "
        "{%0,%1,%2,%3}, {%4,%5,%6,%7}, {%8,%9}, {%0,%1,%2,%3};"
        : "+f"(c0), "+f"(c1), "+f"(c2), "+f"(c3)
        : "r"(a0), "r"(a1), "r"(a2), "r"(a3), "r"(b0), "r"(b1));
}

// ---------------- prep ----------------
__global__ void __launch_bounds__(256) prep_kernel(const int* __restrict__ tgt,
                            const float* __restrict__ embed,
                            const float* __restrict__ w1,
                            const float* __restrict__ w2,
                            const float* __restrict__ w3,
                            const float* __restrict__ W_h,
                            const float* __restrict__ fc_W,
                            const float* __restrict__ W_cov) {
    int idx = blockIdx.x * 256 + threadIdx.x;
    if (idx < BB*TT*HID) {
        int bt = idx >> 8;
        g_x0[idx] = embed[tgt[bt]*HID + (idx & 255)];
    }
    if (idx < 3*512*768) {
        int layer = idx / (512*768);
        int rem = idx % (512*768);
        int o = rem / 768, kk = rem % 768;
        int k = kk >> 8, ic = kk & 255;
        const float* w = (layer == 0) ? w1 : (layer == 1) ? w2 : w3;
        g_wgh[idx] = __float2half(w[o*768 + ic*3 + k]);
    }
    if (idx < AA*HID) {
        int a = idx >> 8, h = idx & 255;
        g_WhT[h*AA + a] = W_h[idx];
    }
    if (idx < VV*(HID+CE)) {
        g_fcWh[idx] = __float2half(fc_W[idx]);
    }
    if (idx < AA*32) {
        int a = idx >> 5, k = idx & 31;
        g_Wh[idx] = __float2half((k < 25) ? W_cov[a*25 + k] : 0.f);
    }
}

// ---------------- causal GLU layer via HMMA (shared X tile across 3 taps) ----------------
// block: (b, o-tile: 32 a-channels + 32 gates, t-half of 48). 8 warps.
__global__ void __launch_bounds__(256) glu_kernel(int src_sel, int layer,
                                                  const float* __restrict__ bias) {
    const float* xin  = src_sel ? g_x1 : g_x0;
    float*       xout = src_sel ? g_x0 : g_x1;
    const unsigned* wW = (const unsigned*)g_wgh + layer*(512*768/2);

    int b  = blockIdx.x;
    int o0 = blockIdx.y * 32;
    int t0 = blockIdx.z * 48;
    __shared__ unsigned sW3[3][64][9];  // [tap][local row][kpair]
    __shared__ unsigned sX[50][9];      // [t0-2 + row][kpair]
    __shared__ float    sY[64][51];     // pre-GLU y
    int tid = threadIdx.x, lane = tid & 31, warp = tid >> 5;
    int ln4 = lane & 3, lnr = lane >> 2;
    int mt = warp >> 1;               // 0..3 (rows mt*16..+15; 0,1 = a; 2,3 = gate)
    int nbase = (warp & 1) * 3;       // 3 n-tiles of 8 t per warp
    int rL = mt*16 + lnr, rH = rL + 8;

    float acc[3][4];
#pragma unroll
    for (int nt = 0; nt < 3; nt++)
#pragma unroll
        for (int i = 0; i < 4; i++) acc[nt][i] = 0.f;

    for (int is = 0; is < 16; is++) {
        __syncthreads();
        // W tiles for all 3 taps: 1536 words
#pragma unroll
        for (int rep = 0; rep < 6; rep++) {
            int w = tid + rep*256;
            int k = w >> 9, r = (w >> 3) & 63, jp = w & 7;
            int wr = (r < 32) ? (o0 + r) : (256 + o0 + r - 32);
            sW3[k][r][jp] = wW[wr*384 + k*128 + is*8 + jp];
        }
        // X tile: 50 t-rows, shared by all taps: 400 words
        for (int idx = tid; idx < 400; idx += 256) {
            int tl = idx >> 3, jp = idx & 7;
            int tg = t0 + tl - 2;
            unsigned v = 0u;
            if (tg >= 0 && tg < TT) {
                float2 f = *(const float2*)&xin[(b*TT + tg)*HID + is*16 + jp*2];
                v = pk_h2(f.x, f.y);
            }
            sX[tl][jp] = v;
        }
        __syncthreads();

#pragma unroll
        for (int k = 0; k < 3; k++) {
            unsigned a0 = sW3[k][rL][ln4],     a1 = sW3[k][rH][ln4];
            unsigned a2 = sW3[k][rL][ln4 + 4], a3 = sW3[k][rH][ln4 + 4];
#pragma unroll
            for (int nt = 0; nt < 3; nt++) {
                int tr = (nbase + nt)*8 + lnr + k;
                unsigned b0 = sX[tr][ln4], b1 = sX[tr][ln4 + 4];
                mma16816(acc[nt][0], acc[nt][1], acc[nt][2], acc[nt][3],
                         a0, a1, a2, a3, b0, b1);
            }
        }
    }

    // stage pre-GLU y
#pragma unroll
    for (int nt = 0; nt < 3; nt++) {
        int tc = (nbase + nt)*8 + ln4*2;
        sY[rL][tc]     = acc[nt][0];
        sY[rL][tc + 1] = acc[nt][1];
        sY[rH][tc]     = acc[nt][2];
        sY[rH][tc + 1] = acc[nt][3];
    }
    __syncthreads();
    for (int idx = tid; idx < 32*48; idx += 256) {
        int r = idx & 31, tl = idx >> 5;
        float av = sY[r][tl]      + bias[o0 + r];
        float gv = sY[r + 32][tl] + bias[256 + o0 + r];
        xout[(b*TT + t0 + tl)*HID + o0 + r] = av * sigmoid_fast(gv);
    }
}

// ---------------- enc_proj: HMMA  EP[a,px] = W_enc @ enc_feat + b_enc -> f16 ----------------
__global__ void __launch_bounds__(256) encproj_kernel(const float* __restrict__ enc_feat,
                                                      const float* __restrict__ W_enc,
                                                      const float* __restrict__ b_enc) {
    int b = blockIdx.x, a0 = blockIdx.y*64, p0 = blockIdx.z*64;
    __shared__ unsigned sWh[64][9];
    __shared__ unsigned sFt[64][9];
    int tid = threadIdx.x, lane = tid & 31, warp = tid >> 5;
    int ln4 = lane & 3, lnr = lane >> 2;
    int m  = warp >> 1;
    int nb = (warp & 1) * 4;

    float acc[4][4];
#pragma unroll
    for (int nt = 0; nt < 4; nt++)
#pragma unroll
        for (int i = 0; i < 4; i++) acc[nt][i] = 0.f;

    for (int ks = 0; ks < 25; ks++) {
        int c0 = ks*16;
        __syncthreads();
#pragma unroll
        for (int rep = 0; rep < 2; rep++) {
            int w = tid + rep*256;
            int a = w >> 3, kp = w & 7;
            float2 wv = *(const float2*)&W_enc[(a0 + a)*CE + c0 + kp*2];
            sWh[a][kp] = pk_h2(wv.x, wv.y);
        }
#pragma unroll
        for (int rep = 0; rep < 2; rep++) {
            int w = tid + rep*256;
            int px = w & 63, kp = w >> 6;
            float f0 = enc_feat[((size_t)b*CE + c0 + kp*2    )*HW + p0 + px];
            float f1 = enc_feat[((size_t)b*CE + c0 + kp*2 + 1)*HW + p0 + px];
            sFt[px][kp] = pk_h2(f0, f1);
        }
        __syncthreads();

        int rL = m*16 + lnr, rH = rL + 8;
        unsigned af0 = sWh[rL][ln4],     af1 = sWh[rH][ln4];
        unsigned af2 = sWh[rL][ln4 + 4], af3 = sWh[rH][ln4 + 4];
#pragma unroll
        for (int nt = 0; nt < 4; nt++) {
            int pxr = (nb + nt)*8 + lnr;
            unsigned b0 = sFt[pxr][ln4], b1 = sFt[pxr][ln4 + 4];
            mma16816(acc[nt][0], acc[nt][1], acc[nt][2], acc[nt][3],
                     af0, af1, af2, af3, b0, b1);
        }
    }

    int aL = a0 + m*16 + lnr, aH = aL + 8;
    float beL = b_enc[aL], beH = b_enc[aH];
    int slab_p = p0 >> 9;
#pragma unroll
    for (int nt = 0; nt < 4; nt++) {
        int pxc = p0 + (nb + nt)*8 + ln4*2;
        int wofs = ((pxc & 511) >> 1);
        {
            int slab = (b*NZ + (aL >> 5))*2 + slab_p;
            g_EPh[slab*8192 + (aL & 31)*256 + wofs] = pk_h2(acc[nt][0] + beL, acc[nt][1] + beL);
        }
        {
            int slab = (b*NZ + (aH >> 5))*2 + slab_p;
            g_EPh[slab*8192 + (aH & 31)*256 + wofs] = pk_h2(acc[nt][2] + beH, acc[nt][3] + beH);
        }
    }
}

// ---------------- q precompute ----------------
__global__ void __launch_bounds__(256) qgemm_kernel(const float* __restrict__ b_h,
                                                    const float* __restrict__ b_cov) {
    int m0 = blockIdx.x * 64;
    int n0 = blockIdx.y * 64;
    __shared__ float Hs[16][66];
    __shared__ float Ws[16][64];
    int tid = threadIdx.x;
    int tm = (tid & 15)*4, tn = (tid >> 4)*4;
    float acc[4][4];
#pragma unroll
    for (int r = 0; r < 4; r++)
#pragma unroll
        for (int c = 0; c < 4; c++) acc[r][c] = 0.f;

    for (int k0 = 0; k0 < HID; k0 += 16) {
        __syncthreads();
        for (int idx = tid; idx < 1024; idx += 256) {
            int kk = idx & 15, m = idx >> 4;
            Hs[kk][m] = g_x1[(m0 + m)*HID + k0 + kk];
        }
        for (int idx = tid; idx < 1024; idx += 256) {
            int i = idx & 63, kk = idx >> 6;
            Ws[kk][i] = g_WhT[(k0 + kk)*AA + n0 + i];
        }
        __syncthreads();
#pragma unroll
        for (int kk = 0; kk < 16; kk++) {
            float hv[4], wv[4];
#pragma unroll
            for (int r = 0; r < 4; r++) hv[r] = Hs[kk][tm + r];
#pragma unroll
            for (int c = 0; c < 4; c++) wv[c] = Ws[kk][tn + c];
#pragma unroll
            for (int r = 0; r < 4; r++)
#pragma unroll
                for (int c = 0; c < 4; c++)
                    acc[r][c] = fmaf(hv[r], wv[c], acc[r][c]);
        }
    }
#pragma unroll
    for (int r = 0; r < 4; r++)
#pragma unroll
        for (int c = 0; c < 4; c++) {
            int n = n0 + tn + c;
            g_QB[(m0 + tm + r)*AA + n] = acc[r][c] + b_h[n] + b_cov[n];
        }
}

// ---------------- persistent scan: HMMA conv, f16x2 tanh, per-batch barrier ----------------
__global__ void __launch_bounds__(128, 4) scan_kernel(const float* __restrict__ v_attn) {
    int bid   = blockIdx.x;
    int b     = bid >> 4;
    int zc    = (bid >> 1) & 7;
    int strip = bid & 1;
    int a0    = zc * ACH;
    int r0    = strip * 8;

    __shared__ __align__(16) unsigned sEPh[32*EPSTR];
    __shared__ float    sCov[12][68];
    __shared__ float    sE[HW];
    __shared__ unsigned sQh[ACH];
    __shared__ float    reds[4];

    int tid = threadIdx.x, lane = tid & 31, warp = tid >> 5;
    int ln4 = lane & 3, lnr = lane >> 2;
    int wpx = warp * 128;

    {
        const uint4* src = (const uint4*)&g_EPh[((b*NZ + zc)*2 + strip)*8192];
        for (int i = tid; i < 2048; i += 128) {
            int a = i >> 6, w = (i & 63) * 4;
            *(uint4*)&sEPh[a*EPSTR + w] = src[i];
        }
    }
    for (int i = tid; i < 12*68; i += 128) ((float*)sCov)[i] = 0.f;

    unsigned af[2][2][4];
#pragma unroll
    for (int mt = 0; mt < 2; mt++)
#pragma unroll
        for (int kt = 0; kt < 2; kt++) {
            int rL = a0 + mt*16 + lnr, rH = rL + 8;
            int kc = kt*16 + ln4*2;
            af[mt][kt][0] = *(const unsigned*)&g_Wh[rL*32 + kc];
            af[mt][kt][1] = *(const unsigned*)&g_Wh[rH*32 + kc];
            af[mt][kt][2] = *(const unsigned*)&g_Wh[rL*32 + kc + 8];
            af[mt][kt][3] = *(const unsigned*)&g_Wh[rH*32 + kc + 8];
        }
    unsigned vreg[4];
#pragma unroll
    for (int m = 0; m < 4; m++) {
        float v = v_attn[a0 + lnr + m*8];
        vreg[m] = pk_h2(v, v);
    }
    int goff[8]; bool gval[8];
#pragma unroll
    for (int kt = 0; kt < 2; kt++)
#pragma unroll
        for (int pos = 0; pos < 4; pos++) {
            int j = kt*4 + pos;
            int k = kt*16 + ln4*2 + (pos & 1) + ((pos & 2) ? 8 : 0);
            gval[j] = (k < 25);
            goff[j] = ((k/5)*68 + (k%5));
        }

    for (int t = 0; t < TT; t++) {
        int ping = t & 1;
        if (tid < ACH) {
            float q = g_QB[(b*TT + t)*AA + a0 + tid];
            sQh[tid] = pk_h2(q, q);
        }
        __syncthreads();

        unsigned qreg[4];
#pragma unroll
        for (int m = 0; m < 4; m++) qreg[m] = sQh[lnr + m*8];

#pragma unroll 2
        for (int nt = 0; nt < 16; nt++) {
            int n0 = wpx + nt*8;
            int px = n0 + lnr;
            int py = px >> 6, pxx = px & 63;
            const float* cb = &sCov[py][pxx];
            float gv[8];
#pragma unroll
            for (int j = 0; j < 8; j++)
                gv[j] = gval[j] ? cb[goff[j]] : 0.f;
            unsigned b00 = pk_h2(gv[0], gv[1]), b01 = pk_h2(gv[2], gv[3]);
            unsigned b10 = pk_h2(gv[4], gv[5]), b11 = pk_h2(gv[6], gv[7]);
            int epc = (n0 >> 1) + ln4;

            unsigned eacc = 0u;
#pragma unroll
            for (int mt = 0; mt < 2; mt++) {
                float c0 = 0.f, c1 = 0.f, c2 = 0.f, c3 = 0.f;
                mma16816(c0, c1, c2, c3,
                         af[mt][0][0], af[mt][0][1], af[mt][0][2], af[mt][0][3], b00, b01);
                mma16816(c0, c1, c2, c3,
                         af[mt][1][0], af[mt][1][1], af[mt][1][2], af[mt][1][3], b10, b11);
                int rowL = mt*16 + lnr, rowH = rowL + 8;
                unsigned sL = pk_h2(c0, c1);
                sL = hadd2(sL, sEPh[rowL*EPSTR + epc]);
                sL = hadd2(sL, qreg[mt*2]);
                eacc = hfma2(tanh2_hw(sL), vreg[mt*2], eacc);
                unsigned sH = pk_h2(c2, c3);
                sH = hadd2(sH, sEPh[rowH*EPSTR + epc]);
                sH = hadd2(sH, qreg[mt*2 + 1]);
                eacc = hfma2(tanh2_hw(sH), vreg[mt*2 + 1], eacc);
            }
            eacc = hadd2(eacc, __shfl_xor_sync(~0u, eacc, 4));
            eacc = hadd2(eacc, __shfl_xor_sync(~0u, eacc, 8));
            eacc = hadd2(eacc, __shfl_xor_sync(~0u, eacc, 16));
            if (lane < 4) {
                float lo, hi;
                h2f2(eacc, lo, hi);
                int gp = strip*512 + n0 + lane*2;
                *(float2*)&g_epart[(size_t)ping*(NZ*BB*HW) + (zc*BB + b)*HW + gp] =
                    make_float2(lo, hi);
            }
        }

        // ---- per-batch barrier (16 arrivals) ----
        __threadfence();
        __syncthreads();
        if (tid == 0) {
            volatile unsigned* gp = &g_barG[b*32];
            unsigned gen = *gp;
            unsigned arrived = atomicAdd(&g_barC[b*32], 1u);
            if (arrived == NBLK_B - 1) {
                g_barC[b*32] = 0;
                __threadfence();
                *gp = gen + 1;
            } else {
                int spins = 0;
                while (*gp == gen) { __nanosleep(64); if (++spins > (1 << 23)) break; }
            }
            __threadfence();
        }
        __syncthreads();

        // ---- phase2: softmax (no max pass; |e|<=4) + cov + alpha ----
        float e8[8];
        {
            float4 s0v = make_float4(0.f,0.f,0.f,0.f);
            float4 s1v = make_float4(0.f,0.f,0.f,0.f);
            const float* base = g_epart + (size_t)ping*(NZ*BB*HW) + b*HW + tid*8;
#pragma unroll
            for (int z = 0; z < NZ; z++) {
                const float4* p4 = (const float4*)(base + (size_t)z*BB*HW);
                float4 q0 = __ldcg(p4);
                float4 q1 = __ldcg(p4 + 1);
                s0v.x += q0.x; s0v.y += q0.y; s0v.z += q0.z; s0v.w += q0.w;
                s1v.x += q1.x; s1v.y += q1.y; s1v.z += q1.z; s1v.w += q1.w;
            }
            e8[0]=s0v.x; e8[1]=s0v.y; e8[2]=s0v.z; e8[3]=s0v.w;
            e8[4]=s1v.x; e8[5]=s1v.y; e8[6]=s1v.z; e8[7]=s1v.w;
        }
        float ex8[8], sl = 0.f;
#pragma unroll
        for (int j = 0; j < 8; j++) { ex8[j] = __expf(e8[j]); sl += ex8[j]; }
        ((float4*)sE)[tid*2]     = make_float4(ex8[0], ex8[1], ex8[2], ex8[3]);
        ((float4*)sE)[tid*2 + 1] = make_float4(ex8[4], ex8[5], ex8[6], ex8[7]);
#pragma unroll
        for (int o = 16; o; o >>= 1) sl += __shfl_xor_sync(~0u, sl, o);
        if (lane == 0) reds[warp] = sl;
        __syncthreads();
        float s = (reds[0] + reds[1]) + (reds[2] + reds[3]);
        float inv = __fdividef(1.f, s);

        for (int h = tid; h < 12*64; h += 128) {
            int hr = h >> 6, cc = h & 63;
            int imrow = r0 - 2 + hr;
            if ((unsigned)imrow < HH_)
                sCov[hr][cc + 2] += sE[imrow*WW_ + cc] * inv;
        }
        if (zc == 0 && strip == 0) {
            float4* ap = (float4*)(g_alpha + ((size_t)b*TT + t)*HW) + tid*2;
            ap[0] = make_float4(ex8[0]*inv, ex8[1]*inv, ex8[2]*inv, ex8[3]*inv);
            ap[1] = make_float4(ex8[4]*inv, ex8[5]*inv, ex8[6]*inv, ex8[7]*inv);
        }
        __syncthreads();
    }
}

// ---------------- ctx GEMM via HMMA: ctx[t,c] = alpha[t,:] @ enc_feat[c,:]^T ----------------
// block: (b, t-tile 32, c-tile 64). 8 warps: mt = warp>>2 (2x16 t-rows), 2 n-tiles each.
__global__ void __launch_bounds__(256) ctxgemm_kernel(const float* __restrict__ enc_feat) {
    int b  = blockIdx.x;
    int t0 = blockIdx.y * 32;
    int c0 = blockIdx.z * 64;
    __shared__ unsigned sA[32][9];   // [t-local][px-pair]
    __shared__ unsigned sB[64][9];   // [c-local][px-pair]
    int tid = threadIdx.x, lane = tid & 31, warp = tid >> 5;
    int ln4 = lane & 3, lnr = lane >> 2;
    int mt = warp >> 2;              // 0..1
    int nb = (warp & 3) * 2;         // 2 n-tiles of 8 c

    float acc[2][4];
#pragma unroll
    for (int nt = 0; nt < 2; nt++)
#pragma unroll
        for (int i = 0; i < 4; i++) acc[nt][i] = 0.f;

    for (int ks = 0; ks < 64; ks++) {
        int k0 = ks*16;
        __syncthreads();
        // alpha tile: 256 words
        {
            int tl = tid >> 3, jp = tid & 7;
            float2 av = *(const float2*)&g_alpha[((size_t)b*TT + t0 + tl)*HW + k0 + jp*2];
            sA[tl][jp] = pk_h2(av.x, av.y);
        }
        // enc tile: 512 words
#pragma unroll
        for (int rep = 0; rep < 2; rep++) {
            int w = tid + rep*256;
            int cl = w >> 3, jp = w & 7;
            int cc = c0 + cl;
            unsigned v = 0u;
            if (cc < CE) {
                float2 f = *(const float2*)&enc_feat[((size_t)b*CE + cc)*HW + k0 + jp*2];
                v = pk_h2(f.x, f.y);
            }
            sB[cl][jp] = v;
        }
        __syncthreads();

        int rL = mt*16 + lnr, rH = rL + 8;
        unsigned a0 = sA[rL][ln4],     a1 = sA[rH][ln4];
        unsigned a2 = sA[rL][ln4 + 4], a3 = sA[rH][ln4 + 4];
#pragma unroll
        for (int nt = 0; nt < 2; nt++) {
            int cr = (nb + nt)*8 + lnr;
            unsigned b0 = sB[cr][ln4], b1 = sB[cr][ln4 + 4];
            mma16816(acc[nt][0], acc[nt][1], acc[nt][2], acc[nt][3],
                     a0, a1, a2, a3, b0, b1);
        }
    }

    int tL = t0 + mt*16 + lnr, tH = tL + 8;
#pragma unroll
    for (int nt = 0; nt < 2; nt++) {
        int cc = c0 + (nb + nt)*8 + ln4*2;
        if (cc + 1 < CE) {
            *(float2*)&g_ctxall[((size_t)b*TT + tL)*CE + cc] = make_float2(acc[nt][0], acc[nt][1]);
            *(float2*)&g_ctxall[((size_t)b*TT + tH)*CE + cc] = make_float2(acc[nt][2], acc[nt][3]);
        }
    }
}

// ---------------- final fc via HMMA: out[m,v] = [hidd|ctx][m,:] @ fc_W[v,:]^T + fc_b ----------------
// block: (m-tile 64, v-tile 64). 8 warps, encproj geometry.
__global__ void __launch_bounds__(256) fc_kernel(const float* __restrict__ fc_b,
                                                 float* __restrict__ out) {
    int m0 = blockIdx.x * 64;
    int v0 = blockIdx.y * 64;
    __shared__ unsigned sW[64][9];   // [v-local][kpair]
    __shared__ unsigned sI[64][9];   // [m-local][kpair]
    __shared__ float    sY[64][65];  // [v-local][m-local]
    int tid = threadIdx.x, lane = tid & 31, warp = tid >> 5;
    int ln4 = lane & 3, lnr = lane >> 2;
    int mt = warp >> 1;              // v-row tile 0..3
    int nb = (warp & 1) * 4;         // 4 n-tiles of 8 m

    float acc[4][4];
#pragma unroll
    for (int nt = 0; nt < 4; nt++)
#pragma unroll
        for (int i = 0; i < 4; i++) acc[nt][i] = 0.f;

    for (int ks = 0; ks < 41; ks++) {
        int k0 = ks*16;
        __syncthreads();
#pragma unroll
        for (int rep = 0; rep < 2; rep++) {
            int w = tid + rep*256;
            int r = w >> 3, jp = w & 7;
            sW[r][jp] = *(const unsigned*)&g_fcWh[(v0 + r)*(HID+CE) + k0 + jp*2];
        }
#pragma unroll
        for (int rep = 0; rep < 2; rep++) {
            int w = tid + rep*256;
            int r = w >> 3, jp = w & 7;
            float2 f;
            if (k0 < HID) f = *(const float2*)&g_x1[(m0 + r)*HID + k0 + jp*2];
            else          f = *(const float2*)&g_ctxall[(size_t)(m0 + r)*CE + (k0 - HID) + jp*2];
            sI[r][jp] = pk_h2(f.x, f.y);
        }
        __syncthreads();

        int rL = mt*16 + lnr, rH = rL + 8;
        unsigned a0 = sW[rL][ln4],     a1 = sW[rH][ln4];
        unsigned a2 = sW[rL][ln4 + 4], a3 = sW[rH][ln4 + 4];
#pragma unroll
        for (int nt = 0; nt < 4; nt++) {
            int mr = (nb + nt)*8 + lnr;
            unsigned b0 = sI[mr][ln4], b1 = sI[mr][ln4 + 4];
            mma16816(acc[nt][0], acc[nt][1], acc[nt][2], acc[nt][3],
                     a0, a1, a2, a3, b0, b1);
        }
    }

    // stage and coalesced store
    {
        int rL = mt*16 + lnr, rH = rL + 8;
#pragma unroll
        for (int nt = 0; nt < 4; nt++) {
            int mc = (nb + nt)*8 + ln4*2;
            sY[rL][mc]     = acc[nt][0];
            sY[rL][mc + 1] = acc[nt][1];
            sY[rH][mc]     = acc[nt][2];
            sY[rH][mc + 1] = acc[nt][3];
        }
    }
    __syncthreads();
    for (int idx = tid; idx < 64*64; idx += 256) {
        int v = idx & 63, m = idx >> 6;
        out[(m0 + m)*VV + v0 + v] = sY[v][m] + fc_b[v0 + v];
    }
}

// ---------------- launch ----------------
extern "C" void kernel_launch(void* const* d_in, const int* in_sizes, int n_in,
                              void* d_out, int out_size) {
    const float* enc_feat = (const float*)d_in[0];
    const int*   tgt      = (const int*)  d_in[1];
    const float* embed    = (const float*)d_in[2];
    const float* w1       = (const float*)d_in[3];
    const float* b1       = (const float*)d_in[4];
    const float* w2       = (const float*)d_in[5];
    const float* b2       = (const float*)d_in[6];
    const float* w3       = (const float*)d_in[7];
    const float* b3       = (const float*)d_in[8];
    const float* W_enc    = (const float*)d_in[9];
    const float* b_enc    = (const float*)d_in[10];
    const float* W_h      = (const float*)d_in[11];
    const float* b_h      = (const float*)d_in[12];
    const float* W_cov    = (const float*)d_in[13];
    const float* b_cov    = (const float*)d_in[14];
    const float* v_attn   = (const float*)d_in[15];
    const float* fc_W     = (const float*)d_in[16];
    const float* fc_b     = (const float*)d_in[17];
    float* out = (float*)d_out;

    prep_kernel<<<4608, 256>>>(tgt, embed, w1, w2, w3, W_h, fc_W, W_cov);

    dim3 gglu(BB, 8, 2);
    glu_kernel<<<gglu, 256>>>(0, 0, b1);   // g_x0 -> g_x1
    glu_kernel<<<gglu, 256>>>(1, 1, b2);   // g_x1 -> g_x0
    glu_kernel<<<gglu, 256>>>(0, 2, b3);   // g_x0 -> g_x1 (= hidd)

    encproj_kernel<<<dim3(BB, 4, 16), 256>>>(enc_feat, W_enc, b_enc);
    qgemm_kernel<<<dim3(48, 4), 256>>>(b_h, b_cov);

    scan_kernel<<<GRID, 128>>>(v_attn);

    ctxgemm_kernel<<<dim3(BB, 3, 7), 256>>>(enc_feat);
    fc_kernel<<<dim3(48, 4), 256>>>(fc_b, out);
}

// round 15
// speedup vs baseline: 3.1160x; 1.1732x over previous
#include <cuda_runtime.h>
#include <cuda_bf16.h>
#include <cuda_fp16.h>

#define BB   32
#define TT   96
#define HID  256
#define CE   400
#define VV   256
#define HH_  16
#define WW_  64
#define AA   256
#define HW   1024
#define NZ   8          // a-chunks
#define ACH  32         // a per chunk
#define SGRID 256       // scan grid: 32 b x 8 zc
#define NBLK_B 8        // blocks per batch
#define EP2STR 516      // padded row stride (words) for sEP (full image)

// dynamic smem layout (bytes)
#define SM_EP   0
#define SM_COV  66048               // 32*516*4
#define SM_E    (66048 + 5440)      // +20*68*4
#define SM_Q    (SM_E + 4096)
#define SM_RED  (SM_Q + 256)        // 32 floats (raw q) + 32 words (packed q)
#define SM_TOT  (SM_RED + 32)

// ---------------- device scratch ----------------
__device__ __align__(16) float g_x0[BB*TT*HID];
__device__ __align__(16) float g_x1[BB*TT*HID];
__device__ __align__(16) __half g_wgh[3*512*768];     // f16 glu weights, [layer][o][k*256+ic]
__device__ __align__(16) float g_WhT[HID*AA];
__device__ __align__(16) __half g_fcWh[VV*(HID+CE)];  // f16 fc weights row-major
__device__ __align__(16) __half g_Wh[AA*32];          // plain f16 W_cov, taps 25..31 = 0
__device__ __align__(16) unsigned g_EPh[BB*NZ*2*8192]; // f16x2 EP, [slab][(a&31)*256 + px/2]
__device__ __align__(16) float g_QB[BB*TT*AA];        // q + b_h + b_cov
__device__ __align__(16) float g_epart[2*NZ*BB*HW];   // double-buffered partial e
__device__ __align__(16) float g_alpha[BB*TT*HW];
__device__ __align__(16) float g_ctxall[BB*TT*CE];

// per-batch barrier state (128B padded)
__device__ unsigned g_barC[BB*32];
__device__ unsigned g_barG[BB*32];

__device__ __forceinline__ float sigmoid_fast(float x) {
    return __fdividef(1.f, 1.f + __expf(-x));
}

// ---- packed helpers (sm_103a) ----
typedef unsigned long long u64;
__device__ __forceinline__ unsigned pk_h2(float lo, float hi) {
    unsigned d;
    asm("cvt.rn.f16x2.f32 %0, %1, %2;" : "=r"(d) : "f"(hi), "f"(lo));
    return d;
}
__device__ __forceinline__ unsigned tanh2_hw(unsigned s) {
    unsigned d; asm("tanh.approx.f16x2 %0, %1;" : "=r"(d) : "r"(s)); return d;
}
__device__ __forceinline__ unsigned hfma2(unsigned a, unsigned b, unsigned c) {
    unsigned d;
    asm("fma.rn.f16x2 %0, %1, %2, %3;" : "=r"(d) : "r"(a), "r"(b), "r"(c));
    return d;
}
__device__ __forceinline__ unsigned hadd2(unsigned a, unsigned b) {
    unsigned d;
    asm("add.rn.f16x2 %0, %1, %2;" : "=r"(d) : "r"(a), "r"(b));
    return d;
}
__device__ __forceinline__ void h2f2(unsigned h, float& lo, float& hi) {
    asm("{.reg .b16 l, hh; mov.b32 {l, hh}, %2; cvt.f32.f16 %0, l; cvt.f32.f16 %1, hh;}"
        : "=f"(lo), "=f"(hi) : "r"(h));
}
__device__ __forceinline__ void mma16816(float& c0, float& c1, float& c2, float& c3,
                                         unsigned a0, unsigned a1, unsigned a2, unsigned a3,
                                         unsigned b0, unsigned b1) {
    asm("mma.sync.aligned.m16n8k16.row.col.f32.f16.f16.f32 "
        "{%0,%1,%2,%3}, {%4,%5,%6,%7}, {%8,%9}, {%0,%1,%2,%3};"
        : "+f"(c0), "+f"(c1), "+f"(c2), "+f"(c3)
        : "r"(a0), "r"(a1), "r"(a2), "r"(a3), "r"(b0), "r"(b1));
}

// ---------------- prep ----------------
__global__ void __launch_bounds__(256) prep_kernel(const int* __restrict__ tgt,
                            const float* __restrict__ embed,
                            const float* __restrict__ w1,
                            const float* __restrict__ w2,
                            const float* __restrict__ w3,
                            const float* __restrict__ W_h,
                            const float* __restrict__ fc_W,
                            const float* __restrict__ W_cov) {
    int idx = blockIdx.x * 256 + threadIdx.x;
    if (idx < BB*TT*HID) {
        int bt = idx >> 8;
        g_x0[idx] = embed[tgt[bt]*HID + (idx & 255)];
    }
    if (idx < 3*512*768) {
        int layer = idx / (512*768);
        int rem = idx % (512*768);
        int o = rem / 768, kk = rem % 768;
        int k = kk >> 8, ic = kk & 255;
        const float* w = (layer == 0) ? w1 : (layer == 1) ? w2 : w3;
        g_wgh[idx] = __float2half(w[o*768 + ic*3 + k]);
    }
    if (idx < AA*HID) {
        int a = idx >> 8, h = idx & 255;
        g_WhT[h*AA + a] = W_h[idx];
    }
    if (idx < VV*(HID+CE)) {
        g_fcWh[idx] = __float2half(fc_W[idx]);
    }
    if (idx < AA*32) {
        int a = idx >> 5, k = idx & 31;
        g_Wh[idx] = __float2half((k < 25) ? W_cov[a*25 + k] : 0.f);
    }
}

// ---------------- causal GLU layer via HMMA (shared X tile across 3 taps) ----------------
__global__ void __launch_bounds__(256) glu_kernel(int src_sel, int layer,
                                                  const float* __restrict__ bias) {
    const float* xin  = src_sel ? g_x1 : g_x0;
    float*       xout = src_sel ? g_x0 : g_x1;
    const unsigned* wW = (const unsigned*)g_wgh + layer*(512*768/2);

    int b  = blockIdx.x;
    int o0 = blockIdx.y * 32;
    int t0 = blockIdx.z * 48;
    __shared__ unsigned sW3[3][64][9];
    __shared__ unsigned sX[50][9];
    __shared__ float    sY[64][51];
    int tid = threadIdx.x, lane = tid & 31, warp = tid >> 5;
    int ln4 = lane & 3, lnr = lane >> 2;
    int mt = warp >> 1;
    int nbase = (warp & 1) * 3;
    int rL = mt*16 + lnr, rH = rL + 8;

    float acc[3][4];
#pragma unroll
    for (int nt = 0; nt < 3; nt++)
#pragma unroll
        for (int i = 0; i < 4; i++) acc[nt][i] = 0.f;

    for (int is = 0; is < 16; is++) {
        __syncthreads();
#pragma unroll
        for (int rep = 0; rep < 6; rep++) {
            int w = tid + rep*256;
            int k = w >> 9, r = (w >> 3) & 63, jp = w & 7;
            int wr = (r < 32) ? (o0 + r) : (256 + o0 + r - 32);
            sW3[k][r][jp] = wW[wr*384 + k*128 + is*8 + jp];
        }
        for (int idx = tid; idx < 400; idx += 256) {
            int tl = idx >> 3, jp = idx & 7;
            int tg = t0 + tl - 2;
            unsigned v = 0u;
            if (tg >= 0 && tg < TT) {
                float2 f = *(const float2*)&xin[(b*TT + tg)*HID + is*16 + jp*2];
                v = pk_h2(f.x, f.y);
            }
            sX[tl][jp] = v;
        }
        __syncthreads();

#pragma unroll
        for (int k = 0; k < 3; k++) {
            unsigned a0 = sW3[k][rL][ln4],     a1 = sW3[k][rH][ln4];
            unsigned a2 = sW3[k][rL][ln4 + 4], a3 = sW3[k][rH][ln4 + 4];
#pragma unroll
            for (int nt = 0; nt < 3; nt++) {
                int tr = (nbase + nt)*8 + lnr + k;
                unsigned b0 = sX[tr][ln4], b1 = sX[tr][ln4 + 4];
                mma16816(acc[nt][0], acc[nt][1], acc[nt][2], acc[nt][3],
                         a0, a1, a2, a3, b0, b1);
            }
        }
    }

#pragma unroll
    for (int nt = 0; nt < 3; nt++) {
        int tc = (nbase + nt)*8 + ln4*2;
        sY[rL][tc]     = acc[nt][0];
        sY[rL][tc + 1] = acc[nt][1];
        sY[rH][tc]     = acc[nt][2];
        sY[rH][tc + 1] = acc[nt][3];
    }
    __syncthreads();
    for (int idx = tid; idx < 32*48; idx += 256) {
        int r = idx & 31, tl = idx >> 5;
        float av = sY[r][tl]      + bias[o0 + r];
        float gv = sY[r + 32][tl] + bias[256 + o0 + r];
        xout[(b*TT + t0 + tl)*HID + o0 + r] = av * sigmoid_fast(gv);
    }
}

// ---------------- enc_proj: HMMA  EP[a,px] = W_enc @ enc_feat + b_enc -> f16 ----------------
__global__ void __launch_bounds__(256) encproj_kernel(const float* __restrict__ enc_feat,
                                                      const float* __restrict__ W_enc,
                                                      const float* __restrict__ b_enc) {
    int b = blockIdx.x, a0 = blockIdx.y*64, p0 = blockIdx.z*64;
    __shared__ unsigned sWh[64][9];
    __shared__ unsigned sFt[64][9];
    int tid = threadIdx.x, lane = tid & 31, warp = tid >> 5;
    int ln4 = lane & 3, lnr = lane >> 2;
    int m  = warp >> 1;
    int nb = (warp & 1) * 4;

    float acc[4][4];
#pragma unroll
    for (int nt = 0; nt < 4; nt++)
#pragma unroll
        for (int i = 0; i < 4; i++) acc[nt][i] = 0.f;

    for (int ks = 0; ks < 25; ks++) {
        int c0 = ks*16;
        __syncthreads();
#pragma unroll
        for (int rep = 0; rep < 2; rep++) {
            int w = tid + rep*256;
            int a = w >> 3, kp = w & 7;
            float2 wv = *(const float2*)&W_enc[(a0 + a)*CE + c0 + kp*2];
            sWh[a][kp] = pk_h2(wv.x, wv.y);
        }
#pragma unroll
        for (int rep = 0; rep < 2; rep++) {
            int w = tid + rep*256;
            int px = w & 63, kp = w >> 6;
            float f0 = enc_feat[((size_t)b*CE + c0 + kp*2    )*HW + p0 + px];
            float f1 = enc_feat[((size_t)b*CE + c0 + kp*2 + 1)*HW + p0 + px];
            sFt[px][kp] = pk_h2(f0, f1);
        }
        __syncthreads();

        int rL = m*16 + lnr, rH = rL + 8;
        unsigned af0 = sWh[rL][ln4],     af1 = sWh[rH][ln4];
        unsigned af2 = sWh[rL][ln4 + 4], af3 = sWh[rH][ln4 + 4];
#pragma unroll
        for (int nt = 0; nt < 4; nt++) {
            int pxr = (nb + nt)*8 + lnr;
            unsigned b0 = sFt[pxr][ln4], b1 = sFt[pxr][ln4 + 4];
            mma16816(acc[nt][0], acc[nt][1], acc[nt][2], acc[nt][3],
                     af0, af1, af2, af3, b0, b1);
        }
    }

    int aL = a0 + m*16 + lnr, aH = aL + 8;
    float beL = b_enc[aL], beH = b_enc[aH];
    int slab_p = p0 >> 9;
#pragma unroll
    for (int nt = 0; nt < 4; nt++) {
        int pxc = p0 + (nb + nt)*8 + ln4*2;
        int wofs = ((pxc & 511) >> 1);
        {
            int slab = (b*NZ + (aL >> 5))*2 + slab_p;
            g_EPh[slab*8192 + (aL & 31)*256 + wofs] = pk_h2(acc[nt][0] + beL, acc[nt][1] + beL);
        }
        {
            int slab = (b*NZ + (aH >> 5))*2 + slab_p;
            g_EPh[slab*8192 + (aH & 31)*256 + wofs] = pk_h2(acc[nt][2] + beH, acc[nt][3] + beH);
        }
    }
}

// ---------------- q precompute ----------------
__global__ void __launch_bounds__(256) qgemm_kernel(const float* __restrict__ b_h,
                                                    const float* __restrict__ b_cov) {
    int m0 = blockIdx.x * 64;
    int n0 = blockIdx.y * 64;
    __shared__ float Hs[16][66];
    __shared__ float Ws[16][64];
    int tid = threadIdx.x;
    int tm = (tid & 15)*4, tn = (tid >> 4)*4;
    float acc[4][4];
#pragma unroll
    for (int r = 0; r < 4; r++)
#pragma unroll
        for (int c = 0; c < 4; c++) acc[r][c] = 0.f;

    for (int k0 = 0; k0 < HID; k0 += 16) {
        __syncthreads();
        for (int idx = tid; idx < 1024; idx += 256) {
            int kk = idx & 15, m = idx >> 4;
            Hs[kk][m] = g_x1[(m0 + m)*HID + k0 + kk];
        }
        for (int idx = tid; idx < 1024; idx += 256) {
            int i = idx & 63, kk = idx >> 6;
            Ws[kk][i] = g_WhT[(k0 + kk)*AA + n0 + i];
        }
        __syncthreads();
#pragma unroll
        for (int kk = 0; kk < 16; kk++) {
            float hv[4], wv[4];
#pragma unroll
            for (int r = 0; r < 4; r++) hv[r] = Hs[kk][tm + r];
#pragma unroll
            for (int c = 0; c < 4; c++) wv[c] = Ws[kk][tn + c];
#pragma unroll
            for (int r = 0; r < 4; r++)
#pragma unroll
                for (int c = 0; c < 4; c++)
                    acc[r][c] = fmaf(hv[r], wv[c], acc[r][c]);
        }
    }
#pragma unroll
    for (int r = 0; r < 4; r++)
#pragma unroll
        for (int c = 0; c < 4; c++) {
            int n = n0 + tn + c;
            g_QB[(m0 + tm + r)*AA + n] = acc[r][c] + b_h[n] + b_cov[n];
        }
}

// ---------------- persistent scan: 8 blocks/batch, full image, dynamic smem ----------------
// bid = b*8 + zc. 256 threads; warp w handles px [w*128, w*128+128).
extern __shared__ __align__(16) char s_dyn[];
__global__ void __launch_bounds__(256, 2) scan_kernel(const float* __restrict__ v_attn) {
    int bid = blockIdx.x;
    int b   = bid >> 3;
    int zc  = bid & 7;
    int a0  = zc * ACH;

    unsigned* sEP  = (unsigned*)(s_dyn + SM_EP);    // [32][EP2STR]
    float (*sCov)[68] = (float (*)[68])(s_dyn + SM_COV);  // rows -2..17
    float*    sE   = (float*)(s_dyn + SM_E);
    float*    sQf  = (float*)(s_dyn + SM_Q);        // raw q values (32)
    unsigned* sQh  = (unsigned*)(s_dyn + SM_Q) + 32; // packed (q,q) (32)
    float*    reds = (float*)(s_dyn + SM_RED);

    int tid = threadIdx.x, lane = tid & 31, warp = tid >> 5;
    int ln4 = lane & 3, lnr = lane >> 2;
    int wpx = warp * 128;

    // one-time EP load: 16384 words (64KB) remapped to EP2STR rows
    {
        const uint4* src0 = (const uint4*)&g_EPh[((b*NZ + zc)*2 + 0)*8192];
        const uint4* src1 = (const uint4*)&g_EPh[((b*NZ + zc)*2 + 1)*8192];
        for (int i = tid; i < 4096; i += 256) {
            int word = i*4;
            int a = word >> 9, px2 = word & 511;
            int strip = px2 >> 8, wofs = px2 & 255;
            uint4 v = (strip == 0) ? src0[(a*256 + wofs) >> 2] : src1[(a*256 + wofs) >> 2];
            *(uint4*)&sEP[a*EP2STR + px2] = v;
        }
    }
    for (int i = tid; i < 20*68; i += 256) ((float*)sCov)[i] = 0.f;

    // A-fragments (W_cov) constant over t
    unsigned af[2][2][4];
#pragma unroll
    for (int mt = 0; mt < 2; mt++)
#pragma unroll
        for (int kt = 0; kt < 2; kt++) {
            int rL = a0 + mt*16 + lnr, rH = rL + 8;
            int kc = kt*16 + ln4*2;
            af[mt][kt][0] = *(const unsigned*)&g_Wh[rL*32 + kc];
            af[mt][kt][1] = *(const unsigned*)&g_Wh[rH*32 + kc];
            af[mt][kt][2] = *(const unsigned*)&g_Wh[rL*32 + kc + 8];
            af[mt][kt][3] = *(const unsigned*)&g_Wh[rH*32 + kc + 8];
        }
    unsigned vreg[4];
#pragma unroll
    for (int m = 0; m < 4; m++) {
        float v = v_attn[a0 + lnr + m*8];
        vreg[m] = pk_h2(v, v);
    }
    int goff[8]; bool gval[8];
#pragma unroll
    for (int kt = 0; kt < 2; kt++)
#pragma unroll
        for (int pos = 0; pos < 4; pos++) {
            int j = kt*4 + pos;
            int k = kt*16 + ln4*2 + (pos & 1) + ((pos & 2) ? 8 : 0);
            gval[j] = (k < 25);
            goff[j] = ((k/5)*68 + (k%5));
        }

    if (tid < ACH) sQf[tid] = g_QB[(b*TT + 0)*AA + a0 + tid];

    for (int t = 0; t < TT; t++) {
        int ping = t & 1;
        if (tid < ACH) {
            float q = sQf[tid];
            sQh[tid] = pk_h2(q, q);
        }
        __syncthreads();   // q packed + cov from previous phase2 visible

        unsigned qreg[4];
#pragma unroll
        for (int m = 0; m < 4; m++) qreg[m] = sQh[lnr + m*8];

        // ---- energy: 16 n-tiles of 8 px per warp ----
#pragma unroll 2
        for (int nt = 0; nt < 16; nt++) {
            int n0 = wpx + nt*8;
            int px = n0 + lnr;
            int py = px >> 6, pxx = px & 63;
            const float* cb = &sCov[py][pxx];
            float gv[8];
#pragma unroll
            for (int j = 0; j < 8; j++)
                gv[j] = gval[j] ? cb[goff[j]] : 0.f;
            unsigned b00 = pk_h2(gv[0], gv[1]), b01 = pk_h2(gv[2], gv[3]);
            unsigned b10 = pk_h2(gv[4], gv[5]), b11 = pk_h2(gv[6], gv[7]);
            int epc = (n0 >> 1) + ln4;

            unsigned eacc = 0u;
#pragma unroll
            for (int mt = 0; mt < 2; mt++) {
                float c0 = 0.f, c1 = 0.f, c2 = 0.f, c3 = 0.f;
                mma16816(c0, c1, c2, c3,
                         af[mt][0][0], af[mt][0][1], af[mt][0][2], af[mt][0][3], b00, b01);
                mma16816(c0, c1, c2, c3,
                         af[mt][1][0], af[mt][1][1], af[mt][1][2], af[mt][1][3], b10, b11);
                int rowL = mt*16 + lnr, rowH = rowL + 8;
                unsigned sL = pk_h2(c0, c1);
                sL = hadd2(sL, sEP[rowL*EP2STR + epc]);
                sL = hadd2(sL, qreg[mt*2]);
                eacc = hfma2(tanh2_hw(sL), vreg[mt*2], eacc);
                unsigned sH = pk_h2(c2, c3);
                sH = hadd2(sH, sEP[rowH*EP2STR + epc]);
                sH = hadd2(sH, qreg[mt*2 + 1]);
                eacc = hfma2(tanh2_hw(sH), vreg[mt*2 + 1], eacc);
            }
            eacc = hadd2(eacc, __shfl_xor_sync(~0u, eacc, 4));
            eacc = hadd2(eacc, __shfl_xor_sync(~0u, eacc, 8));
            eacc = hadd2(eacc, __shfl_xor_sync(~0u, eacc, 16));
            if (lane < 4) {
                float lo, hi;
                h2f2(eacc, lo, hi);
                *(float2*)&g_epart[(size_t)ping*(NZ*BB*HW) + (zc*BB + b)*HW + n0 + lane*2] =
                    make_float2(lo, hi);
            }
        }
        // prefetch next q (raw) while waiting
        if (tid < ACH && t + 1 < TT) sQf[tid] = g_QB[(b*TT + t + 1)*AA + a0 + tid];

        // ---- per-batch barrier (8 arrivals) ----
        __threadfence();
        __syncthreads();
        if (tid == 0) {
            volatile unsigned* gp = &g_barG[b*32];
            unsigned gen = *gp;
            unsigned arrived = atomicAdd(&g_barC[b*32], 1u);
            if (arrived == NBLK_B - 1) {
                g_barC[b*32] = 0;
                __threadfence();
                *gp = gen + 1;
            } else {
                int spins = 0;
                while (*gp == gen) { __nanosleep(32); if (++spins > (1 << 23)) break; }
            }
            __threadfence();
        }
        __syncthreads();

        // ---- phase2 (redundant per block): softmax (no max; |e|<=4) + cov + alpha ----
        float e4x = 0.f, e4y = 0.f, e4z = 0.f, e4w = 0.f;
        {
            const float* base = g_epart + (size_t)ping*(NZ*BB*HW) + b*HW + tid*4;
#pragma unroll
            for (int z = 0; z < NZ; z++) {
                float4 q0 = __ldcg((const float4*)(base + (size_t)z*BB*HW));
                e4x += q0.x; e4y += q0.y; e4z += q0.z; e4w += q0.w;
            }
        }
        float4 ex;
        ex.x = __expf(e4x); ex.y = __expf(e4y); ex.z = __expf(e4z); ex.w = __expf(e4w);
        ((float4*)sE)[tid] = ex;
        float sl = ex.x + ex.y + ex.z + ex.w;
#pragma unroll
        for (int o = 16; o; o >>= 1) sl += __shfl_xor_sync(~0u, sl, o);
        if (lane == 0) reds[warp] = sl;
        __syncthreads();
        float s = ((reds[0] + reds[1]) + (reds[2] + reds[3]))
                + ((reds[4] + reds[5]) + (reds[6] + reds[7]));
        float inv = __fdividef(1.f, s);

        // cov image update: image row r -> sCov[r+2], col c -> +2
        for (int h = tid; h < 1024; h += 256) {
            int r = h >> 6, cc = h & 63;
            sCov[r + 2][cc + 2] += sE[h] * inv;
        }
        if (zc == 0) {
            float4* ap = (float4*)(g_alpha + ((size_t)b*TT + t)*HW) + tid;
            float4 av;
            av.x = ex.x*inv; av.y = ex.y*inv; av.z = ex.z*inv; av.w = ex.w*inv;
            ap[0] = av;
        }
        __syncthreads();
    }
}

// ---------------- ctx GEMM via HMMA ----------------
__global__ void __launch_bounds__(256) ctxgemm_kernel(const float* __restrict__ enc_feat) {
    int b  = blockIdx.x;
    int t0 = blockIdx.y * 32;
    int c0 = blockIdx.z * 64;
    __shared__ unsigned sA[32][9];
    __shared__ unsigned sB[64][9];
    int tid = threadIdx.x, lane = tid & 31, warp = tid >> 5;
    int ln4 = lane & 3, lnr = lane >> 2;
    int mt = warp >> 2;
    int nb = (warp & 3) * 2;

    float acc[2][4];
#pragma unroll
    for (int nt = 0; nt < 2; nt++)
#pragma unroll
        for (int i = 0; i < 4; i++) acc[nt][i] = 0.f;

    for (int ks = 0; ks < 64; ks++) {
        int k0 = ks*16;
        __syncthreads();
        {
            int tl = tid >> 3, jp = tid & 7;
            float2 av = *(const float2*)&g_alpha[((size_t)b*TT + t0 + tl)*HW + k0 + jp*2];
            sA[tl][jp] = pk_h2(av.x, av.y);
        }
#pragma unroll
        for (int rep = 0; rep < 2; rep++) {
            int w = tid + rep*256;
            int cl = w >> 3, jp = w & 7;
            int cc = c0 + cl;
            unsigned v = 0u;
            if (cc < CE) {
                float2 f = *(const float2*)&enc_feat[((size_t)b*CE + cc)*HW + k0 + jp*2];
                v = pk_h2(f.x, f.y);
            }
            sB[cl][jp] = v;
        }
        __syncthreads();

        int rL = mt*16 + lnr, rH = rL + 8;
        unsigned a0 = sA[rL][ln4],     a1 = sA[rH][ln4];
        unsigned a2 = sA[rL][ln4 + 4], a3 = sA[rH][ln4 + 4];
#pragma unroll
        for (int nt = 0; nt < 2; nt++) {
            int cr = (nb + nt)*8 + lnr;
            unsigned b0 = sB[cr][ln4], b1 = sB[cr][ln4 + 4];
            mma16816(acc[nt][0], acc[nt][1], acc[nt][2], acc[nt][3],
                     a0, a1, a2, a3, b0, b1);
        }
    }

    int tL = t0 + mt*16 + lnr, tH = tL + 8;
#pragma unroll
    for (int nt = 0; nt < 2; nt++) {
        int cc = c0 + (nb + nt)*8 + ln4*2;
        if (cc + 1 < CE) {
            *(float2*)&g_ctxall[((size_t)b*TT + tL)*CE + cc] = make_float2(acc[nt][0], acc[nt][1]);
            *(float2*)&g_ctxall[((size_t)b*TT + tH)*CE + cc] = make_float2(acc[nt][2], acc[nt][3]);
        }
    }
}

// ---------------- final fc via HMMA ----------------
__global__ void __launch_bounds__(256) fc_kernel(const float* __restrict__ fc_b,
                                                 float* __restrict__ out) {
    int m0 = blockIdx.x * 64;
    int v0 = blockIdx.y * 64;
    __shared__ unsigned sW[64][9];
    __shared__ unsigned sI[64][9];
    __shared__ float    sY[64][65];
    int tid = threadIdx.x, lane = tid & 31, warp = tid >> 5;
    int ln4 = lane & 3, lnr = lane >> 2;
    int mt = warp >> 1;
    int nb = (warp & 1) * 4;

    float acc[4][4];
#pragma unroll
    for (int nt = 0; nt < 4; nt++)
#pragma unroll
        for (int i = 0; i < 4; i++) acc[nt][i] = 0.f;

    for (int ks = 0; ks < 41; ks++) {
        int k0 = ks*16;
        __syncthreads();
#pragma unroll
        for (int rep = 0; rep < 2; rep++) {
            int w = tid + rep*256;
            int r = w >> 3, jp = w & 7;
            sW[r][jp] = *(const unsigned*)&g_fcWh[(v0 + r)*(HID+CE) + k0 + jp*2];
        }
#pragma unroll
        for (int rep = 0; rep < 2; rep++) {
            int w = tid + rep*256;
            int r = w >> 3, jp = w & 7;
            float2 f;
            if (k0 < HID) f = *(const float2*)&g_x1[(m0 + r)*HID + k0 + jp*2];
            else          f = *(const float2*)&g_ctxall[(size_t)(m0 + r)*CE + (k0 - HID) + jp*2];
            sI[r][jp] = pk_h2(f.x, f.y);
        }
        __syncthreads();

        int rL = mt*16 + lnr, rH = rL + 8;
        unsigned a0 = sW[rL][ln4],     a1 = sW[rH][ln4];
        unsigned a2 = sW[rL][ln4 + 4], a3 = sW[rH][ln4 + 4];
#pragma unroll
        for (int nt = 0; nt < 4; nt++) {
            int mr = (nb + nt)*8 + lnr;
            unsigned b0 = sI[mr][ln4], b1 = sI[mr][ln4 + 4];
            mma16816(acc[nt][0], acc[nt][1], acc[nt][2], acc[nt][3],
                     a0, a1, a2, a3, b0, b1);
        }
    }

    {
        int rL = mt*16 + lnr, rH = rL + 8;
#pragma unroll
        for (int nt = 0; nt < 4; nt++) {
            int mc = (nb + nt)*8 + ln4*2;
            sY[rL][mc]     = acc[nt][0];
            sY[rL][mc + 1] = acc[nt][1];
            sY[rH][mc]     = acc[nt][2];
            sY[rH][mc + 1] = acc[nt][3];
        }
    }
    __syncthreads();
    for (int idx = tid; idx < 64*64; idx += 256) {
        int v = idx & 63, m = idx >> 6;
        out[(m0 + m)*VV + v0 + v] = sY[v][m] + fc_b[v0 + v];
    }
}

// ---------------- launch ----------------
extern "C" void kernel_launch(void* const* d_in, const int* in_sizes, int n_in,
                              void* d_out, int out_size) {
    const float* enc_feat = (const float*)d_in[0];
    const int*   tgt      = (const int*)  d_in[1];
    const float* embed    = (const float*)d_in[2];
    const float* w1       = (const float*)d_in[3];
    const float* b1       = (const float*)d_in[4];
    const float* w2       = (const float*)d_in[5];
    const float* b2       = (const float*)d_in[6];
    const float* w3       = (const float*)d_in[7];
    const float* b3       = (const float*)d_in[8];
    const float* W_enc    = (const float*)d_in[9];
    const float* b_enc    = (const float*)d_in[10];
    const float* W_h      = (const float*)d_in[11];
    const float* b_h      = (const float*)d_in[12];
    const float* W_cov    = (const float*)d_in[13];
    const float* b_cov    = (const float*)d_in[14];
    const float* v_attn   = (const float*)d_in[15];
    const float* fc_W     = (const float*)d_in[16];
    const float* fc_b     = (const float*)d_in[17];
    float* out = (float*)d_out;

    cudaFuncSetAttribute(scan_kernel, cudaFuncAttributeMaxDynamicSharedMemorySize, SM_TOT);

    prep_kernel<<<4608, 256>>>(tgt, embed, w1, w2, w3, W_h, fc_W, W_cov);

    dim3 gglu(BB, 8, 2);
    glu_kernel<<<gglu, 256>>>(0, 0, b1);   // g_x0 -> g_x1
    glu_kernel<<<gglu, 256>>>(1, 1, b2);   // g_x1 -> g_x0
    glu_kernel<<<gglu, 256>>>(0, 2, b3);   // g_x0 -> g_x1 (= hidd)

    encproj_kernel<<<dim3(BB, 4, 16), 256>>>(enc_feat, W_enc, b_enc);
    qgemm_kernel<<<dim3(48, 4), 256>>>(b_h, b_cov);

    scan_kernel<<<SGRID, 256, SM_TOT>>>(v_attn);

    ctxgemm_kernel<<<dim3(BB, 3, 7), 256>>>(enc_feat);
    fc_kernel<<<dim3(48, 4), 256>>>(fc_b, out);
}

// round 16
// speedup vs baseline: 3.1869x; 1.0228x over previous
#include <cuda_runtime.h>
#include <cuda_bf16.h>
#include <cuda_fp16.h>

#define BB   32
#define TT   96
#define HID  256
#define CE   400
#define VV   256
#define HH_  16
#define WW_  64
#define AA   256
#define HW   1024
#define NZ   4          // a-chunks (scan)
#define ACH  64         // a per scan block
#define SGRID 128       // scan grid: 32 b x 4 zc
#define NBLK_B 4        // blocks per batch
#define EP2STR 516      // padded row stride (words) for sEP (full image)

// dynamic smem layout (bytes)
#define SM_EP   0
#define SM_COV  132096              // 64*516*4
#define SM_E    (SM_COV + 5440)     // 20*68*4
#define SM_Q    (SM_E + 4096)
#define SM_RED  (SM_Q + 512)        // 64 floats (raw q) + 64 words (packed q)
#define SM_TOT  (SM_RED + 32)

// ---------------- device scratch ----------------
__device__ __align__(16) float g_x0[BB*TT*HID];
__device__ __align__(16) float g_x1[BB*TT*HID];
__device__ __align__(16) __half g_wgh[3*512*768];     // f16 glu weights, [layer][o][k*256+ic]
__device__ __align__(16) float g_WhT[HID*AA];
__device__ __align__(16) __half g_fcWh[VV*(HID+CE)];  // f16 fc weights row-major
__device__ __align__(16) __half g_Wh[AA*32];          // plain f16 W_cov, taps 25..31 = 0
__device__ __align__(16) unsigned g_EPh[BB*8*2*8192]; // f16x2 EP, [slab32][(a&31)*256 + px/2]
__device__ __align__(16) float g_QB[BB*TT*AA];        // q + b_h + b_cov
__device__ __align__(16) float g_epart[2*NZ*BB*HW];   // double-buffered partial e
__device__ __align__(16) float g_alpha[BB*TT*HW];
__device__ __align__(16) float g_ctxall[BB*TT*CE];

// per-batch barrier state (128B padded)
__device__ unsigned g_barC[BB*32];
__device__ unsigned g_barG[BB*32];

__device__ __forceinline__ float sigmoid_fast(float x) {
    return __fdividef(1.f, 1.f + __expf(-x));
}

// ---- packed helpers (sm_103a) ----
typedef unsigned long long u64;
__device__ __forceinline__ unsigned pk_h2(float lo, float hi) {
    unsigned d;
    asm("cvt.rn.f16x2.f32 %0, %1, %2;" : "=r"(d) : "f"(hi), "f"(lo));
    return d;
}
__device__ __forceinline__ unsigned tanh2_hw(unsigned s) {
    unsigned d; asm("tanh.approx.f16x2 %0, %1;" : "=r"(d) : "r"(s)); return d;
}
__device__ __forceinline__ unsigned hfma2(unsigned a, unsigned b, unsigned c) {
    unsigned d;
    asm("fma.rn.f16x2 %0, %1, %2, %3;" : "=r"(d) : "r"(a), "r"(b), "r"(c));
    return d;
}
__device__ __forceinline__ unsigned hadd2(unsigned a, unsigned b) {
    unsigned d;
    asm("add.rn.f16x2 %0, %1, %2;" : "=r"(d) : "r"(a), "r"(b));
    return d;
}
__device__ __forceinline__ void h2f2(unsigned h, float& lo, float& hi) {
    asm("{.reg .b16 l, hh; mov.b32 {l, hh}, %2; cvt.f32.f16 %0, l; cvt.f32.f16 %1, hh;}"
        : "=f"(lo), "=f"(hi) : "r"(h));
}
__device__ __forceinline__ void mma16816(float& c0, float& c1, float& c2, float& c3,
                                         unsigned a0, unsigned a1, unsigned a2, unsigned a3,
                                         unsigned b0, unsigned b1) {
    asm("mma.sync.aligned.m16n8k16.row.col.f32.f16.f16.f32 "
        "{%0,%1,%2,%3}, {%4,%5,%6,%7}, {%8,%9}, {%0,%1,%2,%3};"
        : "+f"(c0), "+f"(c1), "+f"(c2), "+f"(c3)
        : "r"(a0), "r"(a1), "r"(a2), "r"(a3), "r"(b0), "r"(b1));
}

// ---------------- prep ----------------
__global__ void __launch_bounds__(256) prep_kernel(const int* __restrict__ tgt,
                            const float* __restrict__ embed,
                            const float* __restrict__ w1,
                            const float* __restrict__ w2,
                            const float* __restrict__ w3,
                            const float* __restrict__ W_h,
                            const float* __restrict__ fc_W,
                            const float* __restrict__ W_cov) {
    int idx = blockIdx.x * 256 + threadIdx.x;
    if (idx < BB*TT*HID) {
        int bt = idx >> 8;
        g_x0[idx] = embed[tgt[bt]*HID + (idx & 255)];
    }
    if (idx < 3*512*768) {
        int layer = idx / (512*768);
        int rem = idx % (512*768);
        int o = rem / 768, kk = rem % 768;
        int k = kk >> 8, ic = kk & 255;
        const float* w = (layer == 0) ? w1 : (layer == 1) ? w2 : w3;
        g_wgh[idx] = __float2half(w[o*768 + ic*3 + k]);
    }
    if (idx < AA*HID) {
        int a = idx >> 8, h = idx & 255;
        g_WhT[h*AA + a] = W_h[idx];
    }
    if (idx < VV*(HID+CE)) {
        g_fcWh[idx] = __float2half(fc_W[idx]);
    }
    if (idx < AA*32) {
        int a = idx >> 5, k = idx & 31;
        g_Wh[idx] = __float2half((k < 25) ? W_cov[a*25 + k] : 0.f);
    }
}

// ---------------- causal GLU layer via HMMA (shared X tile across 3 taps) ----------------
__global__ void __launch_bounds__(256) glu_kernel(int src_sel, int layer,
                                                  const float* __restrict__ bias) {
    const float* xin  = src_sel ? g_x1 : g_x0;
    float*       xout = src_sel ? g_x0 : g_x1;
    const unsigned* wW = (const unsigned*)g_wgh + layer*(512*768/2);

    int b  = blockIdx.x;
    int o0 = blockIdx.y * 32;
    int t0 = blockIdx.z * 48;
    __shared__ unsigned sW3[3][64][9];
    __shared__ unsigned sX[50][9];
    __shared__ float    sY[64][51];
    int tid = threadIdx.x, lane = tid & 31, warp = tid >> 5;
    int ln4 = lane & 3, lnr = lane >> 2;
    int mt = warp >> 1;
    int nbase = (warp & 1) * 3;
    int rL = mt*16 + lnr, rH = rL + 8;

    float acc[3][4];
#pragma unroll
    for (int nt = 0; nt < 3; nt++)
#pragma unroll
        for (int i = 0; i < 4; i++) acc[nt][i] = 0.f;

    for (int is = 0; is < 16; is++) {
        __syncthreads();
#pragma unroll
        for (int rep = 0; rep < 6; rep++) {
            int w = tid + rep*256;
            int k = w >> 9, r = (w >> 3) & 63, jp = w & 7;
            int wr = (r < 32) ? (o0 + r) : (256 + o0 + r - 32);
            sW3[k][r][jp] = wW[wr*384 + k*128 + is*8 + jp];
        }
        for (int idx = tid; idx < 400; idx += 256) {
            int tl = idx >> 3, jp = idx & 7;
            int tg = t0 + tl - 2;
            unsigned v = 0u;
            if (tg >= 0 && tg < TT) {
                float2 f = *(const float2*)&xin[(b*TT + tg)*HID + is*16 + jp*2];
                v = pk_h2(f.x, f.y);
            }
            sX[tl][jp] = v;
        }
        __syncthreads();

#pragma unroll
        for (int k = 0; k < 3; k++) {
            unsigned a0 = sW3[k][rL][ln4],     a1 = sW3[k][rH][ln4];
            unsigned a2 = sW3[k][rL][ln4 + 4], a3 = sW3[k][rH][ln4 + 4];
#pragma unroll
            for (int nt = 0; nt < 3; nt++) {
                int tr = (nbase + nt)*8 + lnr + k;
                unsigned b0 = sX[tr][ln4], b1 = sX[tr][ln4 + 4];
                mma16816(acc[nt][0], acc[nt][1], acc[nt][2], acc[nt][3],
                         a0, a1, a2, a3, b0, b1);
            }
        }
    }

#pragma unroll
    for (int nt = 0; nt < 3; nt++) {
        int tc = (nbase + nt)*8 + ln4*2;
        sY[rL][tc]     = acc[nt][0];
        sY[rL][tc + 1] = acc[nt][1];
        sY[rH][tc]     = acc[nt][2];
        sY[rH][tc + 1] = acc[nt][3];
    }
    __syncthreads();
    for (int idx = tid; idx < 32*48; idx += 256) {
        int r = idx & 31, tl = idx >> 5;
        float av = sY[r][tl]      + bias[o0 + r];
        float gv = sY[r + 32][tl] + bias[256 + o0 + r];
        xout[(b*TT + t0 + tl)*HID + o0 + r] = av * sigmoid_fast(gv);
    }
}

// ---------------- enc_proj: HMMA  EP[a,px] = W_enc @ enc_feat + b_enc -> f16 ----------------
__global__ void __launch_bounds__(256) encproj_kernel(const float* __restrict__ enc_feat,
                                                      const float* __restrict__ W_enc,
                                                      const float* __restrict__ b_enc) {
    int b = blockIdx.x, a0 = blockIdx.y*64, p0 = blockIdx.z*64;
    __shared__ unsigned sWh[64][9];
    __shared__ unsigned sFt[64][9];
    int tid = threadIdx.x, lane = tid & 31, warp = tid >> 5;
    int ln4 = lane & 3, lnr = lane >> 2;
    int m  = warp >> 1;
    int nb = (warp & 1) * 4;

    float acc[4][4];
#pragma unroll
    for (int nt = 0; nt < 4; nt++)
#pragma unroll
        for (int i = 0; i < 4; i++) acc[nt][i] = 0.f;

    for (int ks = 0; ks < 25; ks++) {
        int c0 = ks*16;
        __syncthreads();
#pragma unroll
        for (int rep = 0; rep < 2; rep++) {
            int w = tid + rep*256;
            int a = w >> 3, kp = w & 7;
            float2 wv = *(const float2*)&W_enc[(a0 + a)*CE + c0 + kp*2];
            sWh[a][kp] = pk_h2(wv.x, wv.y);
        }
#pragma unroll
        for (int rep = 0; rep < 2; rep++) {
            int w = tid + rep*256;
            int px = w & 63, kp = w >> 6;
            float f0 = enc_feat[((size_t)b*CE + c0 + kp*2    )*HW + p0 + px];
            float f1 = enc_feat[((size_t)b*CE + c0 + kp*2 + 1)*HW + p0 + px];
            sFt[px][kp] = pk_h2(f0, f1);
        }
        __syncthreads();

        int rL = m*16 + lnr, rH = rL + 8;
        unsigned af0 = sWh[rL][ln4],     af1 = sWh[rH][ln4];
        unsigned af2 = sWh[rL][ln4 + 4], af3 = sWh[rH][ln4 + 4];
#pragma unroll
        for (int nt = 0; nt < 4; nt++) {
            int pxr = (nb + nt)*8 + lnr;
            unsigned b0 = sFt[pxr][ln4], b1 = sFt[pxr][ln4 + 4];
            mma16816(acc[nt][0], acc[nt][1], acc[nt][2], acc[nt][3],
                     af0, af1, af2, af3, b0, b1);
        }
    }

    int aL = a0 + m*16 + lnr, aH = aL + 8;
    float beL = b_enc[aL], beH = b_enc[aH];
    int slab_p = p0 >> 9;
#pragma unroll
    for (int nt = 0; nt < 4; nt++) {
        int pxc = p0 + (nb + nt)*8 + ln4*2;
        int wofs = ((pxc & 511) >> 1);
        {
            int slab = (b*8 + (aL >> 5))*2 + slab_p;
            g_EPh[slab*8192 + (aL & 31)*256 + wofs] = pk_h2(acc[nt][0] + beL, acc[nt][1] + beL);
        }
        {
            int slab = (b*8 + (aH >> 5))*2 + slab_p;
            g_EPh[slab*8192 + (aH & 31)*256 + wofs] = pk_h2(acc[nt][2] + beH, acc[nt][3] + beH);
        }
    }
}

// ---------------- q precompute ----------------
__global__ void __launch_bounds__(256) qgemm_kernel(const float* __restrict__ b_h,
                                                    const float* __restrict__ b_cov) {
    int m0 = blockIdx.x * 64;
    int n0 = blockIdx.y * 64;
    __shared__ float Hs[16][66];
    __shared__ float Ws[16][64];
    int tid = threadIdx.x;
    int tm = (tid & 15)*4, tn = (tid >> 4)*4;
    float acc[4][4];
#pragma unroll
    for (int r = 0; r < 4; r++)
#pragma unroll
        for (int c = 0; c < 4; c++) acc[r][c] = 0.f;

    for (int k0 = 0; k0 < HID; k0 += 16) {
        __syncthreads();
        for (int idx = tid; idx < 1024; idx += 256) {
            int kk = idx & 15, m = idx >> 4;
            Hs[kk][m] = g_x1[(m0 + m)*HID + k0 + kk];
        }
        for (int idx = tid; idx < 1024; idx += 256) {
            int i = idx & 63, kk = idx >> 6;
            Ws[kk][i] = g_WhT[(k0 + kk)*AA + n0 + i];
        }
        __syncthreads();
#pragma unroll
        for (int kk = 0; kk < 16; kk++) {
            float hv[4], wv[4];
#pragma unroll
            for (int r = 0; r < 4; r++) hv[r] = Hs[kk][tm + r];
#pragma unroll
            for (int c = 0; c < 4; c++) wv[c] = Ws[kk][tn + c];
#pragma unroll
            for (int r = 0; r < 4; r++)
#pragma unroll
                for (int c = 0; c < 4; c++)
                    acc[r][c] = fmaf(hv[r], wv[c], acc[r][c]);
        }
    }
#pragma unroll
    for (int r = 0; r < 4; r++)
#pragma unroll
        for (int c = 0; c < 4; c++) {
            int n = n0 + tn + c;
            g_QB[(m0 + tm + r)*AA + n] = acc[r][c] + b_h[n] + b_cov[n];
        }
}

// ---------------- persistent scan: 4 blocks/batch (64 a each), 1 block/SM, dynamic smem ----------------
// bid = b*4 + zc. 256 threads; warp w handles px [w*128, w*128+128).
extern __shared__ __align__(16) char s_dyn[];
__global__ void __launch_bounds__(256, 1) scan_kernel(const float* __restrict__ v_attn) {
    int bid = blockIdx.x;
    int b   = bid >> 2;
    int zc  = bid & 3;
    int a0  = zc * ACH;

    unsigned* sEP  = (unsigned*)(s_dyn + SM_EP);    // [64][EP2STR]
    float (*sCov)[68] = (float (*)[68])(s_dyn + SM_COV);  // rows -2..17
    float*    sE   = (float*)(s_dyn + SM_E);
    float*    sQf  = (float*)(s_dyn + SM_Q);         // raw q values (64)
    unsigned* sQh  = (unsigned*)(s_dyn + SM_Q) + 64; // packed (q,q) (64)
    float*    reds = (float*)(s_dyn + SM_RED);

    int tid = threadIdx.x, lane = tid & 31, warp = tid >> 5;
    int ln4 = lane & 3, lnr = lane >> 2;
    int wpx = warp * 128;

    // one-time EP load: 32768 words (128KB) remapped to EP2STR rows
    for (int i = tid; i < 8192; i += 256) {
        int word = i*4;
        int a = word >> 9, px2 = word & 511;        // a: 0..63 local
        int strip = px2 >> 8, wofs = px2 & 255;
        int slab = (b*8 + zc*2 + (a >> 5))*2 + strip;
        uint4 v = *(const uint4*)&g_EPh[slab*8192 + (a & 31)*256 + wofs];
        *(uint4*)&sEP[a*EP2STR + px2] = v;
    }
    for (int i = tid; i < 20*68; i += 256) ((float*)sCov)[i] = 0.f;

    // A-fragments (W_cov) constant over t: 4 m-tiles of 16 rows
    unsigned af[4][2][4];
#pragma unroll
    for (int mt = 0; mt < 4; mt++)
#pragma unroll
        for (int kt = 0; kt < 2; kt++) {
            int rL = a0 + mt*16 + lnr, rH = rL + 8;
            int kc = kt*16 + ln4*2;
            af[mt][kt][0] = *(const unsigned*)&g_Wh[rL*32 + kc];
            af[mt][kt][1] = *(const unsigned*)&g_Wh[rH*32 + kc];
            af[mt][kt][2] = *(const unsigned*)&g_Wh[rL*32 + kc + 8];
            af[mt][kt][3] = *(const unsigned*)&g_Wh[rH*32 + kc + 8];
        }
    unsigned vreg[8];
#pragma unroll
    for (int m = 0; m < 8; m++) {
        float v = v_attn[a0 + lnr + m*8];
        vreg[m] = pk_h2(v, v);
    }
    int goff[8]; bool gval[8];
#pragma unroll
    for (int kt = 0; kt < 2; kt++)
#pragma unroll
        for (int pos = 0; pos < 4; pos++) {
            int j = kt*4 + pos;
            int k = kt*16 + ln4*2 + (pos & 1) + ((pos & 2) ? 8 : 0);
            gval[j] = (k < 25);
            goff[j] = ((k/5)*68 + (k%5));
        }

    if (tid < ACH) sQf[tid] = g_QB[(b*TT + 0)*AA + a0 + tid];

    for (int t = 0; t < TT; t++) {
        int ping = t & 1;
        if (tid < ACH) {
            float q = sQf[tid];
            sQh[tid] = pk_h2(q, q);
        }
        __syncthreads();   // q packed + cov from previous phase2 visible

        unsigned qreg[8];
#pragma unroll
        for (int m = 0; m < 8; m++) qreg[m] = sQh[lnr + m*8];

        // ---- energy: 16 n-tiles of 8 px per warp, 64 a-rows ----
#pragma unroll 2
        for (int nt = 0; nt < 16; nt++) {
            int n0 = wpx + nt*8;
            int px = n0 + lnr;
            int py = px >> 6, pxx = px & 63;
            const float* cb = &sCov[py][pxx];
            float gv[8];
#pragma unroll
            for (int j = 0; j < 8; j++)
                gv[j] = gval[j] ? cb[goff[j]] : 0.f;
            unsigned b00 = pk_h2(gv[0], gv[1]), b01 = pk_h2(gv[2], gv[3]);
            unsigned b10 = pk_h2(gv[4], gv[5]), b11 = pk_h2(gv[6], gv[7]);
            int epc = (n0 >> 1) + ln4;

            unsigned eacc = 0u;
#pragma unroll
            for (int mt = 0; mt < 4; mt++) {
                float c0 = 0.f, c1 = 0.f, c2 = 0.f, c3 = 0.f;
                mma16816(c0, c1, c2, c3,
                         af[mt][0][0], af[mt][0][1], af[mt][0][2], af[mt][0][3], b00, b01);
                mma16816(c0, c1, c2, c3,
                         af[mt][1][0], af[mt][1][1], af[mt][1][2], af[mt][1][3], b10, b11);
                int rowL = mt*16 + lnr, rowH = rowL + 8;
                unsigned sL = pk_h2(c0, c1);
                sL = hadd2(sL, sEP[rowL*EP2STR + epc]);
                sL = hadd2(sL, qreg[mt*2]);
                eacc = hfma2(tanh2_hw(sL), vreg[mt*2], eacc);
                unsigned sH = pk_h2(c2, c3);
                sH = hadd2(sH, sEP[rowH*EP2STR + epc]);
                sH = hadd2(sH, qreg[mt*2 + 1]);
                eacc = hfma2(tanh2_hw(sH), vreg[mt*2 + 1], eacc);
            }
            eacc = hadd2(eacc, __shfl_xor_sync(~0u, eacc, 4));
            eacc = hadd2(eacc, __shfl_xor_sync(~0u, eacc, 8));
            eacc = hadd2(eacc, __shfl_xor_sync(~0u, eacc, 16));
            if (lane < 4) {
                float lo, hi;
                h2f2(eacc, lo, hi);
                *(float2*)&g_epart[(size_t)ping*(NZ*BB*HW) + (zc*BB + b)*HW + n0 + lane*2] =
                    make_float2(lo, hi);
            }
        }
        // prefetch next q (raw) while waiting
        if (tid < ACH && t + 1 < TT) sQf[tid] = g_QB[(b*TT + t + 1)*AA + a0 + tid];

        // ---- per-batch barrier (4 arrivals) ----
        __threadfence();
        __syncthreads();
        if (tid == 0) {
            volatile unsigned* gp = &g_barG[b*32];
            unsigned gen = *gp;
            unsigned arrived = atomicAdd(&g_barC[b*32], 1u);
            if (arrived == NBLK_B - 1) {
                g_barC[b*32] = 0;
                __threadfence();
                *gp = gen + 1;
            } else {
                int spins = 0;
                while (*gp == gen) { __nanosleep(32); if (++spins > (1 << 23)) break; }
            }
            __threadfence();
        }
        __syncthreads();

        // ---- phase2 (redundant per block): softmax (no max; |e|<=4) + cov + alpha ----
        float e4x = 0.f, e4y = 0.f, e4z = 0.f, e4w = 0.f;
        {
            const float* base = g_epart + (size_t)ping*(NZ*BB*HW) + b*HW + tid*4;
#pragma unroll
            for (int z = 0; z < NZ; z++) {
                float4 q0 = __ldcg((const float4*)(base + (size_t)z*BB*HW));
                e4x += q0.x; e4y += q0.y; e4z += q0.z; e4w += q0.w;
            }
        }
        float4 ex;
        ex.x = __expf(e4x); ex.y = __expf(e4y); ex.z = __expf(e4z); ex.w = __expf(e4w);
        ((float4*)sE)[tid] = ex;
        float sl = ex.x + ex.y + ex.z + ex.w;
#pragma unroll
        for (int o = 16; o; o >>= 1) sl += __shfl_xor_sync(~0u, sl, o);
        if (lane == 0) reds[warp] = sl;
        __syncthreads();
        float s = ((reds[0] + reds[1]) + (reds[2] + reds[3]))
                + ((reds[4] + reds[5]) + (reds[6] + reds[7]));
        float inv = __fdividef(1.f, s);

        // cov image update: image row r -> sCov[r+2], col c -> +2
        for (int h = tid; h < 1024; h += 256) {
            int r = h >> 6, cc = h & 63;
            sCov[r + 2][cc + 2] += sE[h] * inv;
        }
        if (zc == 0) {
            float4* ap = (float4*)(g_alpha + ((size_t)b*TT + t)*HW) + tid;
            float4 av;
            av.x = ex.x*inv; av.y = ex.y*inv; av.z = ex.z*inv; av.w = ex.w*inv;
            ap[0] = av;
        }
        __syncthreads();
    }
}

// ---------------- ctx GEMM via HMMA ----------------
__global__ void __launch_bounds__(256) ctxgemm_kernel(const float* __restrict__ enc_feat) {
    int b  = blockIdx.x;
    int t0 = blockIdx.y * 32;
    int c0 = blockIdx.z * 64;
    __shared__ unsigned sA[32][9];
    __shared__ unsigned sB[64][9];
    int tid = threadIdx.x, lane = tid & 31, warp = tid >> 5;
    int ln4 = lane & 3, lnr = lane >> 2;
    int mt = warp >> 2;
    int nb = (warp & 3) * 2;

    float acc[2][4];
#pragma unroll
    for (int nt = 0; nt < 2; nt++)
#pragma unroll
        for (int i = 0; i < 4; i++) acc[nt][i] = 0.f;

    for (int ks = 0; ks < 64; ks++) {
        int k0 = ks*16;
        __syncthreads();
        {
            int tl = tid >> 3, jp = tid & 7;
            float2 av = *(const float2*)&g_alpha[((size_t)b*TT + t0 + tl)*HW + k0 + jp*2];
            sA[tl][jp] = pk_h2(av.x, av.y);
        }
#pragma unroll
        for (int rep = 0; rep < 2; rep++) {
            int w = tid + rep*256;
            int cl = w >> 3, jp = w & 7;
            int cc = c0 + cl;
            unsigned v = 0u;
            if (cc < CE) {
                float2 f = *(const float2*)&enc_feat[((size_t)b*CE + cc)*HW + k0 + jp*2];
                v = pk_h2(f.x, f.y);
            }
            sB[cl][jp] = v;
        }
        __syncthreads();

        int rL = mt*16 + lnr, rH = rL + 8;
        unsigned a0 = sA[rL][ln4],     a1 = sA[rH][ln4];
        unsigned a2 = sA[rL][ln4 + 4], a3 = sA[rH][ln4 + 4];
#pragma unroll
        for (int nt = 0; nt < 2; nt++) {
            int cr = (nb + nt)*8 + lnr;
            unsigned b0 = sB[cr][ln4], b1 = sB[cr][ln4 + 4];
            mma16816(acc[nt][0], acc[nt][1], acc[nt][2], acc[nt][3],
                     a0, a1, a2, a3, b0, b1);
        }
    }

    int tL = t0 + mt*16 + lnr, tH = tL + 8;
#pragma unroll
    for (int nt = 0; nt < 2; nt++) {
        int cc = c0 + (nb + nt)*8 + ln4*2;
        if (cc + 1 < CE) {
            *(float2*)&g_ctxall[((size_t)b*TT + tL)*CE + cc] = make_float2(acc[nt][0], acc[nt][1]);
            *(float2*)&g_ctxall[((size_t)b*TT + tH)*CE + cc] = make_float2(acc[nt][2], acc[nt][3]);
        }
    }
}

// ---------------- final fc via HMMA ----------------
__global__ void __launch_bounds__(256) fc_kernel(const float* __restrict__ fc_b,
                                                 float* __restrict__ out) {
    int m0 = blockIdx.x * 64;
    int v0 = blockIdx.y * 64;
    __shared__ unsigned sW[64][9];
    __shared__ unsigned sI[64][9];
    __shared__ float    sY[64][65];
    int tid = threadIdx.x, lane = tid & 31, warp = tid >> 5;
    int ln4 = lane & 3, lnr = lane >> 2;
    int mt = warp >> 1;
    int nb = (warp & 1) * 4;

    float acc[4][4];
#pragma unroll
    for (int nt = 0; nt < 4; nt++)
#pragma unroll
        for (int i = 0; i < 4; i++) acc[nt][i] = 0.f;

    for (int ks = 0; ks < 41; ks++) {
        int k0 = ks*16;
        __syncthreads();
#pragma unroll
        for (int rep = 0; rep < 2; rep++) {
            int w = tid + rep*256;
            int r = w >> 3, jp = w & 7;
            sW[r][jp] = *(const unsigned*)&g_fcWh[(v0 + r)*(HID+CE) + k0 + jp*2];
        }
#pragma unroll
        for (int rep = 0; rep < 2; rep++) {
            int w = tid + rep*256;
            int r = w >> 3, jp = w & 7;
            float2 f;
            if (k0 < HID) f = *(const float2*)&g_x1[(m0 + r)*HID + k0 + jp*2];
            else          f = *(const float2*)&g_ctxall[(size_t)(m0 + r)*CE + (k0 - HID) + jp*2];
            sI[r][jp] = pk_h2(f.x, f.y);
        }
        __syncthreads();

        int rL = mt*16 + lnr, rH = rL + 8;
        unsigned a0 = sW[rL][ln4],     a1 = sW[rH][ln4];
        unsigned a2 = sW[rL][ln4 + 4], a3 = sW[rH][ln4 + 4];
#pragma unroll
        for (int nt = 0; nt < 4; nt++) {
            int mr = (nb + nt)*8 + lnr;
            unsigned b0 = sI[mr][ln4], b1 = sI[mr][ln4 + 4];
            mma16816(acc[nt][0], acc[nt][1], acc[nt][2], acc[nt][3],
                     a0, a1, a2, a3, b0, b1);
        }
    }

    {
        int rL = mt*16 + lnr, rH = rL + 8;
#pragma unroll
        for (int nt = 0; nt < 4; nt++) {
            int mc = (nb + nt)*8 + ln4*2;
            sY[rL][mc]     = acc[nt][0];
            sY[rL][mc + 1] = acc[nt][1];
            sY[rH][mc]     = acc[nt][2];
            sY[rH][mc + 1] = acc[nt][3];
        }
    }
    __syncthreads();
    for (int idx = tid; idx < 64*64; idx += 256) {
        int v = idx & 63, m = idx >> 6;
        out[(m0 + m)*VV + v0 + v] = sY[v][m] + fc_b[v0 + v];
    }
}

// ---------------- launch ----------------
extern "C" void kernel_launch(void* const* d_in, const int* in_sizes, int n_in,
                              void* d_out, int out_size) {
    const float* enc_feat = (const float*)d_in[0];
    const int*   tgt      = (const int*)  d_in[1];
    const float* embed    = (const float*)d_in[2];
    const float* w1       = (const float*)d_in[3];
    const float* b1       = (const float*)d_in[4];
    const float* w2       = (const float*)d_in[5];
    const float* b2       = (const float*)d_in[6];
    const float* w3       = (const float*)d_in[7];
    const float* b3       = (const float*)d_in[8];
    const float* W_enc    = (const float*)d_in[9];
    const float* b_enc    = (const float*)d_in[10];
    const float* W_h      = (const float*)d_in[11];
    const float* b_h      = (const float*)d_in[12];
    const float* W_cov    = (const float*)d_in[13];
    const float* b_cov    = (const float*)d_in[14];
    const float* v_attn   = (const float*)d_in[15];
    const float* fc_W     = (const float*)d_in[16];
    const float* fc_b     = (const float*)d_in[17];
    float* out = (float*)d_out;

    cudaFuncSetAttribute(scan_kernel, cudaFuncAttributeMaxDynamicSharedMemorySize, SM_TOT);

    prep_kernel<<<4608, 256>>>(tgt, embed, w1, w2, w3, W_h, fc_W, W_cov);

    dim3 gglu(BB, 8, 2);
    glu_kernel<<<gglu, 256>>>(0, 0, b1);   // g_x0 -> g_x1
    glu_kernel<<<gglu, 256>>>(1, 1, b2);   // g_x1 -> g_x0
    glu_kernel<<<gglu, 256>>>(0, 2, b3);   // g_x0 -> g_x1 (= hidd)

    encproj_kernel<<<dim3(BB, 4, 16), 256>>>(enc_feat, W_enc, b_enc);
    qgemm_kernel<<<dim3(48, 4), 256>>>(b_h, b_cov);

    scan_kernel<<<SGRID, 256, SM_TOT>>>(v_attn);

    ctxgemm_kernel<<<dim3(BB, 3, 7), 256>>>(enc_feat);
    fc_kernel<<<dim3(48, 4), 256>>>(fc_b, out);
}